// round 3
// baseline (speedup 1.0000x reference)
#include <cuda_runtime.h>
#include <cuda_bf16.h>
#include <math.h>

// Problem constants
#define Bsz 8
#define Tlen 1024
#define IN_DIM 32
#define HID 512
#define DI 1024
#define DS 16
#define DTR 32
#define Fdim 96
#define MT (Bsz * Tlen)   // 8192 rows

// ---------------- scratch (device globals; no runtime allocation) ----------------
__device__ float g_h[MT * HID];        // 16 MB
__device__ float g_hn[MT * HID];       // 16 MB
__device__ float g_xz[MT * 2 * DI];    // 64 MB
__device__ float g_xssm[MT * DI];      // 32 MB
__device__ float g_dbl[MT * 64];       // 2 MB
__device__ float g_delta[MT * DI];     // 32 MB
__device__ float g_y[MT * DI];         // 32 MB
__device__ float g_xs[MT * IN_DIM];    // 1 MB

// ---------------- input channel scaling ----------------
__global__ void scale_x_kernel(const float* __restrict__ x, float* __restrict__ xs) {
    int idx = blockIdx.x * blockDim.x + threadIdx.x;   // over MT*IN_DIM
    int i = idx & 31;
    float v = x[idx];
    if (i < 4) {
        float c = (i == 0) ? 0.3f : (i == 1) ? 0.5f : (i == 2) ? 0.9f : 1.0f;
        v *= c;
    }
    xs[idx] = v;
}

// ---------------- generic tiled SGEMM: C[m,n] = sum_k A[m,k]*B[n,k] ----------------
// A: [M, lda], Bw: [N, ldb] (both K-contiguous), C: [M, ldc]
// MODE 0: C = acc (+bias); MODE 1: C = softplus(acc + bias); MODE 2: C += acc
#define BM 64
#define BN 64
#define BKK 16

template<int MODE>
__global__ void __launch_bounds__(256) gemm_tn_kernel(
    const float* __restrict__ A, int lda,
    const float* __restrict__ Bw, int ldb,
    const float* __restrict__ bias,
    float* __restrict__ C, int ldc,
    int M, int N, int K)
{
    __shared__ float As[BKK][BM + 4];
    __shared__ float Bs[BKK][BN + 4];

    int tid = threadIdx.x;
    int bm = blockIdx.y * BM;
    int bn = blockIdx.x * BN;

    int lrow = tid >> 2;          // 0..63
    int lk   = (tid & 3) * 4;     // 0,4,8,12

    int tr = (tid >> 4) * 4;      // output row offset in tile
    int tc = (tid & 15) * 4;      // output col offset in tile

    float acc[4][4];
#pragma unroll
    for (int i = 0; i < 4; i++)
#pragma unroll
        for (int j = 0; j < 4; j++) acc[i][j] = 0.f;

    const float* Aptr = A + (size_t)(bm + lrow) * lda + lk;
    const float* Bptr = Bw + (size_t)(bn + lrow) * ldb + lk;

    for (int k0 = 0; k0 < K; k0 += BKK) {
        float4 av = *(const float4*)Aptr;
        float4 bv = *(const float4*)Bptr;
        Aptr += BKK;
        Bptr += BKK;
        As[lk + 0][lrow] = av.x; As[lk + 1][lrow] = av.y;
        As[lk + 2][lrow] = av.z; As[lk + 3][lrow] = av.w;
        Bs[lk + 0][lrow] = bv.x; Bs[lk + 1][lrow] = bv.y;
        Bs[lk + 2][lrow] = bv.z; Bs[lk + 3][lrow] = bv.w;
        __syncthreads();
#pragma unroll
        for (int k = 0; k < BKK; ++k) {
            float4 a4 = *(const float4*)&As[k][tr];
            float4 b4 = *(const float4*)&Bs[k][tc];
            float ar[4] = {a4.x, a4.y, a4.z, a4.w};
            float br[4] = {b4.x, b4.y, b4.z, b4.w};
#pragma unroll
            for (int i = 0; i < 4; ++i)
#pragma unroll
                for (int j = 0; j < 4; ++j)
                    acc[i][j] = fmaf(ar[i], br[j], acc[i][j]);
        }
        __syncthreads();
    }

#pragma unroll
    for (int i = 0; i < 4; ++i) {
        float* Cp = C + (size_t)(bm + tr + i) * ldc + (bn + tc);
        float vals[4];
#pragma unroll
        for (int j = 0; j < 4; ++j) {
            float v = acc[i][j];
            if (MODE == 0 || MODE == 1) {
                if (bias) v += bias[bn + tc + j];
            }
            if (MODE == 1) {
                // numerically stable softplus: max(v,0) + log1p(exp(-|v|))
                v = fmaxf(v, 0.f) + log1pf(expf(-fabsf(v)));
            }
            vals[j] = v;
        }
        if (MODE == 2) {
            float4 old = *(const float4*)Cp;
            vals[0] += old.x; vals[1] += old.y; vals[2] += old.z; vals[3] += old.w;
        }
        float4 r; r.x = vals[0]; r.y = vals[1]; r.z = vals[2]; r.w = vals[3];
        *(float4*)Cp = r;
    }
}

// ---------------- rmsnorm: out = h * rsqrt(mean(h^2)+eps) * w ----------------
__global__ void __launch_bounds__(128) rmsnorm_kernel(
    const float* __restrict__ h, const float* __restrict__ w, float* __restrict__ out)
{
    int row = blockIdx.x;
    const float* hr = h + (size_t)row * HID;
    float v[4];
    float ss = 0.f;
#pragma unroll
    for (int i = 0; i < 4; i++) {
        v[i] = hr[threadIdx.x + i * 128];
        ss += v[i] * v[i];
    }
#pragma unroll
    for (int o = 16; o; o >>= 1) ss += __shfl_xor_sync(0xffffffffu, ss, o);
    __shared__ float red[4];
    if ((threadIdx.x & 31) == 0) red[threadIdx.x >> 5] = ss;
    __syncthreads();
    float tot = red[0] + red[1] + red[2] + red[3];
    float sc = rsqrtf(tot * (1.f / (float)HID) + 1e-5f);
#pragma unroll
    for (int i = 0; i < 4; i++) {
        int c = threadIdx.x + i * 128;
        out[(size_t)row * HID + c] = v[i] * sc * w[c];
    }
}

// ---------------- depthwise causal conv (K=4) + bias + silu ----------------
// x_in = xz[:, 0:DI];  xssm[bt, d] = silu(sum_k x_in[b, t-3+k, d]*w[d,k] + cb[d])
__global__ void conv_silu_kernel(const float* __restrict__ xz,
                                 const float* __restrict__ cw,
                                 const float* __restrict__ cb,
                                 float* __restrict__ xssm)
{
    int idx = blockIdx.x * blockDim.x + threadIdx.x;   // over MT*DI
    int d = idx & (DI - 1);
    int bt = idx >> 10;
    int t = bt & (Tlen - 1);
    float w0 = cw[d * 4 + 0], w1 = cw[d * 4 + 1], w2 = cw[d * 4 + 2], w3 = cw[d * 4 + 3];
    const float* col = xz + (size_t)bt * (2 * DI) + d;
    float acc = cb[d] + w3 * col[0];
    if (t >= 1) acc += w2 * col[-(2 * DI)];
    if (t >= 2) acc += w1 * col[-(4 * DI)];
    if (t >= 3) acc += w0 * col[-(6 * DI)];
    float sig = 1.f / (1.f + __expf(-acc));
    xssm[(size_t)bt * DI + d] = acc * sig;
}

// ---------------- selective scan ----------------
// One group of 16 lanes per (b,d); lane s owns state s. 256 threads = 16 groups/block.
__global__ void __launch_bounds__(256) scan_kernel(
    const float* __restrict__ delta,  // [MT, DI]
    const float* __restrict__ xssm,   // [MT, DI]
    const float* __restrict__ dbl,    // [MT, 64]  cols 32:48 = B, 48:64 = C
    const float* __restrict__ xz,     // [MT, 2*DI] (z in second half)
    const float* __restrict__ A_log,  // [DI, DS]
    const float* __restrict__ Dp,     // [DI]
    float* __restrict__ y)            // [MT, DI]
{
    int tid = threadIdx.x;
    int s = tid & 15;
    int g = blockIdx.x * 16 + (tid >> 4);   // b*DI + d
    int b = g >> 10;
    int d = g & (DI - 1);

    float A = -expf(A_log[d * DS + s]);
    float Dd = Dp[d];
    float h = 0.f;

    const float* dptr = delta + (size_t)b * Tlen * DI + d;
    const float* xptr = xssm + (size_t)b * Tlen * DI + d;
    const float* bcp  = dbl + (size_t)b * Tlen * 64;
    const float* zptr = xz + (size_t)b * Tlen * (2 * DI) + DI + d;
    float* yptr = y + (size_t)b * Tlen * DI + d;

    for (int t = 0; t < Tlen; t++) {
        float dt = __ldg(dptr);
        float xv = __ldg(xptr);
        float Bv = __ldg(bcp + 32 + s);
        float Cv = __ldg(bcp + 48 + s);
        float dA = __expf(dt * A);
        h = fmaf(h, dA, dt * xv * Bv);
        float yv = h * Cv;
        yv += __shfl_xor_sync(0xffffffffu, yv, 8, 32);
        yv += __shfl_xor_sync(0xffffffffu, yv, 4, 32);
        yv += __shfl_xor_sync(0xffffffffu, yv, 2, 32);
        yv += __shfl_xor_sync(0xffffffffu, yv, 1, 32);
        if (s == 0) {
            float z = __ldg(zptr);
            float sz = z / (1.f + __expf(-z));
            *yptr = (yv + xv * Dd) * sz;
        }
        dptr += DI; xptr += DI; bcp += 64; zptr += 2 * DI; yptr += DI;
    }
}

// ---------------- final FC on last token ----------------
__global__ void fc_kernel(const float* __restrict__ h, const float* __restrict__ fc_w,
                          const float* __restrict__ fc_b, float* __restrict__ out)
{
    int idx = blockIdx.x * blockDim.x + threadIdx.x;
    if (idx >= Bsz * Fdim) return;
    int b = idx / Fdim, f = idx % Fdim;
    const float* hr = h + ((size_t)b * Tlen + (Tlen - 1)) * HID;
    const float* wr = fc_w + (size_t)f * HID;
    float acc = fc_b[f];
    for (int k = 0; k < HID; k += 4) {
        float4 hv = *(const float4*)(hr + k);
        float4 wv = *(const float4*)(wr + k);
        acc += hv.x * wv.x + hv.y * wv.y + hv.z * wv.z + hv.w * wv.w;
    }
    out[idx] = acc;
}

// ---------------- launcher ----------------
extern "C" void kernel_launch(void* const* d_in, const int* in_sizes, int n_in,
                              void* d_out, int out_size)
{
    const float* x        = (const float*)d_in[0];
    const float* ip_w     = (const float*)d_in[1];
    const float* ip_b     = (const float*)d_in[2];
    const float* norm_w   = (const float*)d_in[3];
    const float* inp_w    = (const float*)d_in[4];
    const float* conv_w   = (const float*)d_in[5];
    const float* conv_b   = (const float*)d_in[6];
    const float* xproj_w  = (const float*)d_in[7];
    const float* dtproj_w = (const float*)d_in[8];
    const float* dtproj_b = (const float*)d_in[9];
    const float* A_log    = (const float*)d_in[10];
    const float* Dvec     = (const float*)d_in[11];
    const float* outp_w   = (const float*)d_in[12];
    const float* fc_w     = (const float*)d_in[13];
    const float* fc_b     = (const float*)d_in[14];

    float *h, *hn, *xz, *xssm, *dbl, *delta, *y, *xs;
    cudaGetSymbolAddress((void**)&h, g_h);
    cudaGetSymbolAddress((void**)&hn, g_hn);
    cudaGetSymbolAddress((void**)&xz, g_xz);
    cudaGetSymbolAddress((void**)&xssm, g_xssm);
    cudaGetSymbolAddress((void**)&dbl, g_dbl);
    cudaGetSymbolAddress((void**)&delta, g_delta);
    cudaGetSymbolAddress((void**)&y, g_y);
    cudaGetSymbolAddress((void**)&xs, g_xs);

    // x scaled
    scale_x_kernel<<<(MT * IN_DIM) / 256, 256>>>(x, xs);

    // h = xs @ ip_w^T + ip_b   (M=8192, N=512, K=32)
    gemm_tn_kernel<0><<<dim3(HID / BN, MT / BM), 256>>>(
        xs, IN_DIM, ip_w, IN_DIM, ip_b, h, HID, MT, HID, IN_DIM);

    for (int l = 0; l < 2; l++) {
        const float* nw  = norm_w + l * HID;
        const float* iw  = inp_w + (size_t)l * 2 * DI * HID;
        const float* cw  = conv_w + (size_t)l * DI * 4;
        const float* cb  = conv_b + (size_t)l * DI;
        const float* xpw = xproj_w + (size_t)l * 64 * DI;
        const float* dpw = dtproj_w + (size_t)l * DI * DTR;
        const float* dpb = dtproj_b + (size_t)l * DI;
        const float* Al  = A_log + (size_t)l * DI * DS;
        const float* Dl  = Dvec + (size_t)l * DI;
        const float* ow  = outp_w + (size_t)l * HID * DI;

        // hn = rmsnorm(h) * nw
        rmsnorm_kernel<<<MT, 128>>>(h, nw, hn);

        // xz = hn @ inp_w^T   (M=8192, N=2048, K=512)
        gemm_tn_kernel<0><<<dim3((2 * DI) / BN, MT / BM), 256>>>(
            hn, HID, iw, HID, nullptr, xz, 2 * DI, MT, 2 * DI, HID);

        // depthwise conv + silu -> xssm
        conv_silu_kernel<<<(MT * DI) / 256, 256>>>(xz, cw, cb, xssm);

        // dbl = xssm @ xproj_w^T   (M=8192, N=64, K=1024)
        gemm_tn_kernel<0><<<dim3(64 / BN, MT / BM), 256>>>(
            xssm, DI, xpw, DI, nullptr, dbl, 64, MT, 64, DI);

        // delta = softplus(dt_raw @ dtproj_w^T + dtproj_b)  (M=8192, N=1024, K=32; lda=64)
        gemm_tn_kernel<1><<<dim3(DI / BN, MT / BM), 256>>>(
            dbl, 64, dpw, DTR, dpb, delta, DI, MT, DI, DTR);

        // selective scan (+ x*D, * silu(z)) -> y
        scan_kernel<<<(Bsz * DI) / 16, 256>>>(delta, xssm, dbl, xz, Al, Dl, y);

        // h += y @ outp_w^T   (M=8192, N=512, K=1024)
        gemm_tn_kernel<2><<<dim3(HID / BN, MT / BM), 256>>>(
            y, DI, ow, DI, nullptr, h, HID, MT, HID, DI);
    }

    // out = h[:, -1, :] @ fc_w^T + fc_b
    fc_kernel<<<3, 256>>>(h, fc_w, fc_b, (float*)d_out);
}

// round 5
// speedup vs baseline: 1.3696x; 1.3696x over previous
#include <cuda_runtime.h>
#include <cuda_bf16.h>
#include <math.h>
#include <stdint.h>

// Problem constants
#define Bsz 8
#define Tlen 1024
#define IN_DIM 32
#define HID 512
#define DI 1024
#define DS 16
#define DTR 32
#define Fdim 96
#define MT (Bsz * Tlen)   // 8192 rows

// ---------------- scratch (device globals; no runtime allocation) ----------------
__device__ float g_h[MT * HID];        // 16 MB
__device__ float g_hn[MT * HID];       // 16 MB
__device__ float g_xz[MT * 2 * DI];    // 64 MB
__device__ float g_xssm[MT * DI];      // 32 MB
__device__ float g_dbl[MT * 64];       // 2 MB
__device__ float g_delta[MT * DI];     // 32 MB
__device__ float g_y[MT * DI];         // 32 MB
__device__ float g_xs[MT * IN_DIM];    // 1 MB
__device__ float g_wi[2 * DI * HID];   // 4 MB  (tf32-rounded inp_w for one layer)
__device__ float g_wo[HID * DI];       // 2 MB  (tf32-rounded outp_w for one layer)

// ---------------- tf32 round-to-nearest helper ----------------
__device__ __forceinline__ float tf32r(float x) {
    uint32_t u;
    asm("cvt.rna.tf32.f32 %0, %1;" : "=r"(u) : "f"(x));
    return __uint_as_float(u);
}

__global__ void round_tf32_kernel(const float* __restrict__ in, float* __restrict__ out, int n) {
    int i = blockIdx.x * blockDim.x + threadIdx.x;
    if (i < n) out[i] = tf32r(in[i]);
}

// ================= mma.sync tf32 GEMM: C[m,n] = sum_k A[m,k]*B[n,k] =================
// CTA tile 128x128x32, 256 threads = 8 warps (2m x 4n), warp tile 64x32.
// Double-buffered cp.async. RES=0: C = acc ; RES=1: C += acc.

#define APAD 36                        // floats per smem row (32 + 4): conflict-free frag gather
#define TILE_FLTS (128 * APAD)         // 4608 floats per operand tile
#define STAGE_FLTS (2 * TILE_FLTS)     // A + B
#define SMEM_BYTES (2 * STAGE_FLTS * 4)  // 2 stages = 73728 B

__device__ __forceinline__ uint32_t smem_u32(const void* p) {
    uint32_t a;
    asm("{ .reg .u64 t; cvta.to.shared.u64 t, %1; cvt.u32.u64 %0, t; }" : "=r"(a) : "l"(p));
    return a;
}

__device__ __forceinline__ void cpa16(uint32_t saddr, const void* gaddr) {
    asm volatile("cp.async.cg.shared.global [%0], [%1], 16;" :: "r"(saddr), "l"(gaddr));
}

// load 128-row x 32-float tile into padded smem rows
__device__ __forceinline__ void load_tileP(const float* __restrict__ g, int ld,
                                           int row0, int k0, float* s, int tid) {
#pragma unroll
    for (int i = 0; i < 4; i++) {
        int flat = i * 256 + tid;
        int r = flat >> 3;
        int seg = flat & 7;
        const float* gp = g + (size_t)(row0 + r) * ld + k0 + seg * 4;
        cpa16(smem_u32(s + r * APAD + seg * 4), gp);
    }
}

__device__ __forceinline__ void mma8(float* d, const uint32_t* a, const uint32_t* b) {
    asm volatile(
        "mma.sync.aligned.m16n8k8.row.col.f32.tf32.tf32.f32 "
        "{%0,%1,%2,%3}, {%4,%5,%6,%7}, {%8,%9}, {%0,%1,%2,%3};"
        : "+f"(d[0]), "+f"(d[1]), "+f"(d[2]), "+f"(d[3])
        : "r"(a[0]), "r"(a[1]), "r"(a[2]), "r"(a[3]), "r"(b[0]), "r"(b[1]));
}

template<int RES>
__global__ void __launch_bounds__(256)
gemm_mma_kernel(const float* __restrict__ A, int lda,
                const float* __restrict__ B, int ldb,
                float* __restrict__ C, int ldc, int K)
{
    extern __shared__ float sm[];
    int tid = threadIdx.x;
    int wid = tid >> 5, lane = tid & 31;
    int g = lane >> 2, t = lane & 3;
    int warp_m = wid >> 2;   // 0..1 -> 64 rows
    int warp_n = wid & 3;    // 0..3 -> 32 cols
    int bm = blockIdx.y * 128;
    int bn = blockIdx.x * 128;

    float acc[4][4][4];
#pragma unroll
    for (int mt = 0; mt < 4; mt++)
#pragma unroll
        for (int nt = 0; nt < 4; nt++)
#pragma unroll
            for (int q = 0; q < 4; q++) acc[mt][nt][q] = 0.f;

    int nk = K >> 5;

    // prologue: chunk 0 -> stage 0
    load_tileP(A, lda, bm, 0, sm, tid);
    load_tileP(B, ldb, bn, 0, sm + TILE_FLTS, tid);
    asm volatile("cp.async.commit_group;" ::: "memory");

    for (int kc = 0; kc < nk; kc++) {
        int buf = kc & 1;
        if (kc + 1 < nk) {
            int nb = (kc + 1) & 1;
            load_tileP(A, lda, bm, (kc + 1) * 32, sm + nb * STAGE_FLTS, tid);
            load_tileP(B, ldb, bn, (kc + 1) * 32, sm + nb * STAGE_FLTS + TILE_FLTS, tid);
            asm volatile("cp.async.commit_group;" ::: "memory");
            asm volatile("cp.async.wait_group 1;" ::: "memory");
        } else {
            asm volatile("cp.async.wait_group 0;" ::: "memory");
        }
        __syncthreads();

        const float* sA = sm + buf * STAGE_FLTS;
        const float* sB = sA + TILE_FLTS;

#pragma unroll
        for (int kk = 0; kk < 32; kk += 8) {
            uint32_t afr[4][4];
#pragma unroll
            for (int mt = 0; mt < 4; mt++) {
                int r0 = warp_m * 64 + mt * 16;
                afr[mt][0] = __float_as_uint(sA[(r0 + g) * APAD + kk + t]);
                afr[mt][1] = __float_as_uint(sA[(r0 + 8 + g) * APAD + kk + t]);
                afr[mt][2] = __float_as_uint(sA[(r0 + g) * APAD + kk + t + 4]);
                afr[mt][3] = __float_as_uint(sA[(r0 + 8 + g) * APAD + kk + t + 4]);
            }
            uint32_t bfr[4][2];
#pragma unroll
            for (int nt = 0; nt < 4; nt++) {
                int n0 = warp_n * 32 + nt * 8;
                bfr[nt][0] = __float_as_uint(sB[(n0 + g) * APAD + kk + t]);
                bfr[nt][1] = __float_as_uint(sB[(n0 + g) * APAD + kk + t + 4]);
            }
#pragma unroll
            for (int mt = 0; mt < 4; mt++)
#pragma unroll
                for (int nt = 0; nt < 4; nt++)
                    mma8(acc[mt][nt], afr[mt], bfr[nt]);
        }
        __syncthreads();
    }

    // epilogue
#pragma unroll
    for (int mt = 0; mt < 4; mt++) {
        int row = bm + warp_m * 64 + mt * 16 + g;
#pragma unroll
        for (int nt = 0; nt < 4; nt++) {
            int col = bn + warp_n * 32 + nt * 8 + t * 2;
            float* c0 = C + (size_t)row * ldc + col;
            float* c1 = C + (size_t)(row + 8) * ldc + col;
            float2 v0 = make_float2(acc[mt][nt][0], acc[mt][nt][1]);
            float2 v1 = make_float2(acc[mt][nt][2], acc[mt][nt][3]);
            if (RES) {
                float2 o0 = *(const float2*)c0;
                float2 o1 = *(const float2*)c1;
                v0.x += o0.x; v0.y += o0.y;
                v1.x += o1.x; v1.y += o1.y;
            }
            *(float2*)c0 = v0;
            *(float2*)c1 = v1;
        }
    }
}

// ---------------- input channel scaling ----------------
__global__ void scale_x_kernel(const float* __restrict__ x, float* __restrict__ xs) {
    int idx = blockIdx.x * blockDim.x + threadIdx.x;   // over MT*IN_DIM
    int i = idx & 31;
    float v = x[idx];
    if (i < 4) {
        float c = (i == 0) ? 0.3f : (i == 1) ? 0.5f : (i == 2) ? 0.9f : 1.0f;
        v *= c;
    }
    xs[idx] = v;
}

// ---------------- generic tiled SGEMM (small GEMMs only) ----------------
#define BM 64
#define BN 64
#define BKK 16

template<int MODE>
__global__ void __launch_bounds__(256) gemm_tn_kernel(
    const float* __restrict__ A, int lda,
    const float* __restrict__ Bw, int ldb,
    const float* __restrict__ bias,
    float* __restrict__ C, int ldc,
    int M, int N, int K)
{
    __shared__ float As[BKK][BM + 4];
    __shared__ float Bs[BKK][BN + 4];

    int tid = threadIdx.x;
    int bm = blockIdx.y * BM;
    int bn = blockIdx.x * BN;

    int lrow = tid >> 2;
    int lk   = (tid & 3) * 4;
    int tr = (tid >> 4) * 4;
    int tc = (tid & 15) * 4;

    float acc[4][4];
#pragma unroll
    for (int i = 0; i < 4; i++)
#pragma unroll
        for (int j = 0; j < 4; j++) acc[i][j] = 0.f;

    const float* Aptr = A + (size_t)(bm + lrow) * lda + lk;
    const float* Bptr = Bw + (size_t)(bn + lrow) * ldb + lk;

    for (int k0 = 0; k0 < K; k0 += BKK) {
        float4 av = *(const float4*)Aptr;
        float4 bv = *(const float4*)Bptr;
        Aptr += BKK;
        Bptr += BKK;
        As[lk + 0][lrow] = av.x; As[lk + 1][lrow] = av.y;
        As[lk + 2][lrow] = av.z; As[lk + 3][lrow] = av.w;
        Bs[lk + 0][lrow] = bv.x; Bs[lk + 1][lrow] = bv.y;
        Bs[lk + 2][lrow] = bv.z; Bs[lk + 3][lrow] = bv.w;
        __syncthreads();
#pragma unroll
        for (int k = 0; k < BKK; ++k) {
            float4 a4 = *(const float4*)&As[k][tr];
            float4 b4 = *(const float4*)&Bs[k][tc];
            float ar[4] = {a4.x, a4.y, a4.z, a4.w};
            float br[4] = {b4.x, b4.y, b4.z, b4.w};
#pragma unroll
            for (int i = 0; i < 4; ++i)
#pragma unroll
                for (int j = 0; j < 4; ++j)
                    acc[i][j] = fmaf(ar[i], br[j], acc[i][j]);
        }
        __syncthreads();
    }

#pragma unroll
    for (int i = 0; i < 4; ++i) {
        float* Cp = C + (size_t)(bm + tr + i) * ldc + (bn + tc);
        float vals[4];
#pragma unroll
        for (int j = 0; j < 4; ++j) {
            float v = acc[i][j];
            if (MODE == 0 || MODE == 1) {
                if (bias) v += bias[bn + tc + j];
            }
            if (MODE == 1) {
                v = fmaxf(v, 0.f) + log1pf(expf(-fabsf(v)));
            }
            vals[j] = v;
        }
        float4 r; r.x = vals[0]; r.y = vals[1]; r.z = vals[2]; r.w = vals[3];
        *(float4*)Cp = r;
    }
}

// ---------------- rmsnorm (+ tf32 round for MMA consumption) ----------------
__global__ void __launch_bounds__(128) rmsnorm_kernel(
    const float* __restrict__ h, const float* __restrict__ w, float* __restrict__ out)
{
    int row = blockIdx.x;
    const float* hr = h + (size_t)row * HID;
    float v[4];
    float ss = 0.f;
#pragma unroll
    for (int i = 0; i < 4; i++) {
        v[i] = hr[threadIdx.x + i * 128];
        ss += v[i] * v[i];
    }
#pragma unroll
    for (int o = 16; o; o >>= 1) ss += __shfl_xor_sync(0xffffffffu, ss, o);
    __shared__ float red[4];
    if ((threadIdx.x & 31) == 0) red[threadIdx.x >> 5] = ss;
    __syncthreads();
    float tot = red[0] + red[1] + red[2] + red[3];
    float sc = rsqrtf(tot * (1.f / (float)HID) + 1e-5f);
#pragma unroll
    for (int i = 0; i < 4; i++) {
        int c = threadIdx.x + i * 128;
        out[(size_t)row * HID + c] = tf32r(v[i] * sc * w[c]);
    }
}

// ---------------- depthwise causal conv (K=4) + bias + silu ----------------
__global__ void conv_silu_kernel(const float* __restrict__ xz,
                                 const float* __restrict__ cw,
                                 const float* __restrict__ cb,
                                 float* __restrict__ xssm)
{
    int idx = blockIdx.x * blockDim.x + threadIdx.x;   // over MT*DI
    int d = idx & (DI - 1);
    int bt = idx >> 10;
    int t = bt & (Tlen - 1);
    float w0 = cw[d * 4 + 0], w1 = cw[d * 4 + 1], w2 = cw[d * 4 + 2], w3 = cw[d * 4 + 3];
    const float* col = xz + (size_t)bt * (2 * DI) + d;
    float acc = cb[d] + w3 * col[0];
    if (t >= 1) acc += w2 * col[-(2 * DI)];
    if (t >= 2) acc += w1 * col[-(4 * DI)];
    if (t >= 3) acc += w0 * col[-(6 * DI)];
    float sig = 1.f / (1.f + __expf(-acc));
    xssm[(size_t)bt * DI + d] = acc * sig;
}

// ---------------- selective scan (y rounded to tf32 for outp MMA) ----------------
__global__ void __launch_bounds__(256) scan_kernel(
    const float* __restrict__ delta,
    const float* __restrict__ xssm,
    const float* __restrict__ dbl,
    const float* __restrict__ xz,
    const float* __restrict__ A_log,
    const float* __restrict__ Dp,
    float* __restrict__ y)
{
    int tid = threadIdx.x;
    int s = tid & 15;
    int g = blockIdx.x * 16 + (tid >> 4);   // b*DI + d
    int b = g >> 10;
    int d = g & (DI - 1);

    float A = -expf(A_log[d * DS + s]);
    float Dd = Dp[d];
    float h = 0.f;

    const float* dptr = delta + (size_t)b * Tlen * DI + d;
    const float* xptr = xssm + (size_t)b * Tlen * DI + d;
    const float* bcp  = dbl + (size_t)b * Tlen * 64;
    const float* zptr = xz + (size_t)b * Tlen * (2 * DI) + DI + d;
    float* yptr = y + (size_t)b * Tlen * DI + d;

    for (int t = 0; t < Tlen; t++) {
        float dt = __ldg(dptr);
        float xv = __ldg(xptr);
        float Bv = __ldg(bcp + 32 + s);
        float Cv = __ldg(bcp + 48 + s);
        float dA = __expf(dt * A);
        h = fmaf(h, dA, dt * xv * Bv);
        float yv = h * Cv;
        yv += __shfl_xor_sync(0xffffffffu, yv, 8, 32);
        yv += __shfl_xor_sync(0xffffffffu, yv, 4, 32);
        yv += __shfl_xor_sync(0xffffffffu, yv, 2, 32);
        yv += __shfl_xor_sync(0xffffffffu, yv, 1, 32);
        if (s == 0) {
            float z = __ldg(zptr);
            float sz = z / (1.f + __expf(-z));
            *yptr = tf32r((yv + xv * Dd) * sz);
        }
        dptr += DI; xptr += DI; bcp += 64; zptr += 2 * DI; yptr += DI;
    }
}

// ---------------- final FC on last token ----------------
__global__ void fc_kernel(const float* __restrict__ h, const float* __restrict__ fc_w,
                          const float* __restrict__ fc_b, float* __restrict__ out)
{
    int idx = blockIdx.x * blockDim.x + threadIdx.x;
    if (idx >= Bsz * Fdim) return;
    int b = idx / Fdim, f = idx % Fdim;
    const float* hr = h + ((size_t)b * Tlen + (Tlen - 1)) * HID;
    const float* wr = fc_w + (size_t)f * HID;
    float acc = fc_b[f];
    for (int k = 0; k < HID; k += 4) {
        float4 hv = *(const float4*)(hr + k);
        float4 wv = *(const float4*)(wr + k);
        acc += hv.x * wv.x + hv.y * wv.y + hv.z * wv.z + hv.w * wv.w;
    }
    out[idx] = acc;
}

// ---------------- launcher ----------------
extern "C" void kernel_launch(void* const* d_in, const int* in_sizes, int n_in,
                              void* d_out, int out_size)
{
    const float* x        = (const float*)d_in[0];
    const float* ip_w     = (const float*)d_in[1];
    const float* ip_b     = (const float*)d_in[2];
    const float* norm_w   = (const float*)d_in[3];
    const float* inp_w    = (const float*)d_in[4];
    const float* conv_w   = (const float*)d_in[5];
    const float* conv_b   = (const float*)d_in[6];
    const float* xproj_w  = (const float*)d_in[7];
    const float* dtproj_w = (const float*)d_in[8];
    const float* dtproj_b = (const float*)d_in[9];
    const float* A_log    = (const float*)d_in[10];
    const float* Dvec     = (const float*)d_in[11];
    const float* outp_w   = (const float*)d_in[12];
    const float* fc_w     = (const float*)d_in[13];
    const float* fc_b     = (const float*)d_in[14];

    float *h, *hn, *xz, *xssm, *dbl, *delta, *y, *xs, *wi, *wo;
    cudaGetSymbolAddress((void**)&h, g_h);
    cudaGetSymbolAddress((void**)&hn, g_hn);
    cudaGetSymbolAddress((void**)&xz, g_xz);
    cudaGetSymbolAddress((void**)&xssm, g_xssm);
    cudaGetSymbolAddress((void**)&dbl, g_dbl);
    cudaGetSymbolAddress((void**)&delta, g_delta);
    cudaGetSymbolAddress((void**)&y, g_y);
    cudaGetSymbolAddress((void**)&xs, g_xs);
    cudaGetSymbolAddress((void**)&wi, g_wi);
    cudaGetSymbolAddress((void**)&wo, g_wo);

    static int attr_done = 0;
    if (!attr_done) {
        cudaFuncSetAttribute(gemm_mma_kernel<0>, cudaFuncAttributeMaxDynamicSharedMemorySize, SMEM_BYTES);
        cudaFuncSetAttribute(gemm_mma_kernel<1>, cudaFuncAttributeMaxDynamicSharedMemorySize, SMEM_BYTES);
        attr_done = 1;
    }

    // x scaled
    scale_x_kernel<<<(MT * IN_DIM) / 256, 256>>>(x, xs);

    // h = xs @ ip_w^T + ip_b   (M=8192, N=512, K=32) — small, stays FFMA
    gemm_tn_kernel<0><<<dim3(HID / BN, MT / BM), 256>>>(
        xs, IN_DIM, ip_w, IN_DIM, ip_b, h, HID, MT, HID, IN_DIM);

    for (int l = 0; l < 2; l++) {
        const float* nw  = norm_w + l * HID;
        const float* iw  = inp_w + (size_t)l * 2 * DI * HID;
        const float* cw  = conv_w + (size_t)l * DI * 4;
        const float* cb  = conv_b + (size_t)l * DI;
        const float* xpw = xproj_w + (size_t)l * 64 * DI;
        const float* dpw = dtproj_w + (size_t)l * DI * DTR;
        const float* dpb = dtproj_b + (size_t)l * DI;
        const float* Al  = A_log + (size_t)l * DI * DS;
        const float* Dl  = Dvec + (size_t)l * DI;
        const float* ow  = outp_w + (size_t)l * HID * DI;

        // hn = rmsnorm(h) * nw  (tf32-rounded)
        rmsnorm_kernel<<<MT, 128>>>(h, nw, hn);

        // round inp_w to tf32
        round_tf32_kernel<<<(2 * DI * HID) / 256, 256>>>(iw, wi, 2 * DI * HID);

        // xz = hn @ inp_w^T   (M=8192, N=2048, K=512) — tensor cores (mma.sync tf32)
        gemm_mma_kernel<0><<<dim3((2 * DI) / 128, MT / 128), 256, SMEM_BYTES>>>(
            hn, HID, wi, HID, xz, 2 * DI, HID);

        // depthwise conv + silu -> xssm
        conv_silu_kernel<<<(MT * DI) / 256, 256>>>(xz, cw, cb, xssm);

        // dbl = xssm @ xproj_w^T   (M=8192, N=64, K=1024)
        gemm_tn_kernel<0><<<dim3(64 / BN, MT / BM), 256>>>(
            xssm, DI, xpw, DI, nullptr, dbl, 64, MT, 64, DI);

        // delta = softplus(dt_raw @ dtproj_w^T + dtproj_b)
        gemm_tn_kernel<1><<<dim3(DI / BN, MT / BM), 256>>>(
            dbl, 64, dpw, DTR, dpb, delta, DI, MT, DI, DTR);

        // selective scan (+ x*D, * silu(z)) -> y  (tf32-rounded)
        scan_kernel<<<(Bsz * DI) / 16, 256>>>(delta, xssm, dbl, xz, Al, Dl, y);

        // round outp_w to tf32
        round_tf32_kernel<<<(HID * DI) / 256, 256>>>(ow, wo, HID * DI);

        // h += y @ outp_w^T   (M=8192, N=512, K=1024) — tensor cores, residual add
        gemm_mma_kernel<1><<<dim3(HID / 128, MT / 128), 256, SMEM_BYTES>>>(
            y, DI, wo, DI, h, HID, DI);
    }

    // out = h[:, -1, :] @ fc_w^T + fc_b
    fc_kernel<<<3, 256>>>(h, fc_w, fc_b, (float*)d_out);
}

// round 6
// speedup vs baseline: 2.8676x; 2.0938x over previous
#include <cuda_runtime.h>
#include <cuda_bf16.h>
#include <math.h>
#include <stdint.h>

// Problem constants
#define Bsz 8
#define Tlen 1024
#define IN_DIM 32
#define HID 512
#define DI 1024
#define DS 16
#define DTR 32
#define Fdim 96
#define MT (Bsz * Tlen)   // 8192 rows

// ---------------- scratch (device globals; no runtime allocation) ----------------
__device__ float g_h[MT * HID];        // 16 MB
__device__ float g_hn[MT * HID];       // 16 MB
__device__ float g_xz[MT * 2 * DI];    // 64 MB
__device__ float g_xssm[MT * DI];      // 32 MB
__device__ float g_dbl[MT * 64];       // 2 MB
__device__ float g_delta[MT * DI];     // 32 MB
__device__ float g_y[MT * DI];         // 32 MB
__device__ float g_xs[MT * IN_DIM];    // 1 MB
__device__ float g_wi[2 * DI * HID];   // 4 MB  (tf32-rounded inp_w for one layer)
__device__ float g_wo[HID * DI];       // 2 MB  (tf32-rounded outp_w for one layer)

// ---------------- tf32 round-to-nearest helper ----------------
__device__ __forceinline__ float tf32r(float x) {
    uint32_t u;
    asm("cvt.rna.tf32.f32 %0, %1;" : "=r"(u) : "f"(x));
    return __uint_as_float(u);
}

__global__ void round_tf32_kernel(const float* __restrict__ in, float* __restrict__ out, int n) {
    int i = blockIdx.x * blockDim.x + threadIdx.x;
    if (i < n) out[i] = tf32r(in[i]);
}

__device__ __forceinline__ uint32_t smem_u32(const void* p) {
    uint32_t a;
    asm("{ .reg .u64 t; cvta.to.shared.u64 t, %1; cvt.u32.u64 %0, t; }" : "=r"(a) : "l"(p));
    return a;
}

__device__ __forceinline__ void cpa16(uint32_t saddr, const void* gaddr) {
    asm volatile("cp.async.cg.shared.global [%0], [%1], 16;" :: "r"(saddr), "l"(gaddr));
}

// ================= mma.sync tf32 GEMM: C[m,n] = sum_k A[m,k]*B[n,k] =================
// CTA tile 128x128x32, 256 threads = 8 warps (2m x 4n), warp tile 64x32.
// Double-buffered cp.async. RES=0: C = acc ; RES=1: C += acc.

#define APAD 36
#define TILE_FLTS (128 * APAD)
#define STAGE_FLTS (2 * TILE_FLTS)
#define SMEM_BYTES (2 * STAGE_FLTS * 4)

// load 128-row x 32-float tile into padded smem rows
__device__ __forceinline__ void load_tileP(const float* __restrict__ g, int ld,
                                           int row0, int k0, float* s, int tid) {
#pragma unroll
    for (int i = 0; i < 4; i++) {
        int flat = i * 256 + tid;
        int r = flat >> 3;
        int seg = flat & 7;
        const float* gp = g + (size_t)(row0 + r) * ld + k0 + seg * 4;
        cpa16(smem_u32(s + r * APAD + seg * 4), gp);
    }
}

__device__ __forceinline__ void mma8(float* d, const uint32_t* a, const uint32_t* b) {
    asm volatile(
        "mma.sync.aligned.m16n8k8.row.col.f32.tf32.tf32.f32 "
        "{%0,%1,%2,%3}, {%4,%5,%6,%7}, {%8,%9}, {%0,%1,%2,%3};"
        : "+f"(d[0]), "+f"(d[1]), "+f"(d[2]), "+f"(d[3])
        : "r"(a[0]), "r"(a[1]), "r"(a[2]), "r"(a[3]), "r"(b[0]), "r"(b[1]));
}

template<int RES>
__global__ void __launch_bounds__(256)
gemm_mma_kernel(const float* __restrict__ A, int lda,
                const float* __restrict__ B, int ldb,
                float* __restrict__ C, int ldc, int K)
{
    extern __shared__ float sm[];
    int tid = threadIdx.x;
    int wid = tid >> 5, lane = tid & 31;
    int g = lane >> 2, t = lane & 3;
    int warp_m = wid >> 2;
    int warp_n = wid & 3;
    int bm = blockIdx.y * 128;
    int bn = blockIdx.x * 128;

    float acc[4][4][4];
#pragma unroll
    for (int mt = 0; mt < 4; mt++)
#pragma unroll
        for (int nt = 0; nt < 4; nt++)
#pragma unroll
            for (int q = 0; q < 4; q++) acc[mt][nt][q] = 0.f;

    int nk = K >> 5;

    load_tileP(A, lda, bm, 0, sm, tid);
    load_tileP(B, ldb, bn, 0, sm + TILE_FLTS, tid);
    asm volatile("cp.async.commit_group;" ::: "memory");

    for (int kc = 0; kc < nk; kc++) {
        int buf = kc & 1;
        if (kc + 1 < nk) {
            int nb = (kc + 1) & 1;
            load_tileP(A, lda, bm, (kc + 1) * 32, sm + nb * STAGE_FLTS, tid);
            load_tileP(B, ldb, bn, (kc + 1) * 32, sm + nb * STAGE_FLTS + TILE_FLTS, tid);
            asm volatile("cp.async.commit_group;" ::: "memory");
            asm volatile("cp.async.wait_group 1;" ::: "memory");
        } else {
            asm volatile("cp.async.wait_group 0;" ::: "memory");
        }
        __syncthreads();

        const float* sA = sm + buf * STAGE_FLTS;
        const float* sB = sA + TILE_FLTS;

#pragma unroll
        for (int kk = 0; kk < 32; kk += 8) {
            uint32_t afr[4][4];
#pragma unroll
            for (int mt = 0; mt < 4; mt++) {
                int r0 = warp_m * 64 + mt * 16;
                afr[mt][0] = __float_as_uint(sA[(r0 + g) * APAD + kk + t]);
                afr[mt][1] = __float_as_uint(sA[(r0 + 8 + g) * APAD + kk + t]);
                afr[mt][2] = __float_as_uint(sA[(r0 + g) * APAD + kk + t + 4]);
                afr[mt][3] = __float_as_uint(sA[(r0 + 8 + g) * APAD + kk + t + 4]);
            }
            uint32_t bfr[4][2];
#pragma unroll
            for (int nt = 0; nt < 4; nt++) {
                int n0 = warp_n * 32 + nt * 8;
                bfr[nt][0] = __float_as_uint(sB[(n0 + g) * APAD + kk + t]);
                bfr[nt][1] = __float_as_uint(sB[(n0 + g) * APAD + kk + t + 4]);
            }
#pragma unroll
            for (int mt = 0; mt < 4; mt++)
#pragma unroll
                for (int nt = 0; nt < 4; nt++)
                    mma8(acc[mt][nt], afr[mt], bfr[nt]);
        }
        __syncthreads();
    }

#pragma unroll
    for (int mt = 0; mt < 4; mt++) {
        int row = bm + warp_m * 64 + mt * 16 + g;
#pragma unroll
        for (int nt = 0; nt < 4; nt++) {
            int col = bn + warp_n * 32 + nt * 8 + t * 2;
            float* c0 = C + (size_t)row * ldc + col;
            float* c1 = C + (size_t)(row + 8) * ldc + col;
            float2 v0 = make_float2(acc[mt][nt][0], acc[mt][nt][1]);
            float2 v1 = make_float2(acc[mt][nt][2], acc[mt][nt][3]);
            if (RES) {
                float2 o0 = *(const float2*)c0;
                float2 o1 = *(const float2*)c1;
                v0.x += o0.x; v0.y += o0.y;
                v1.x += o1.x; v1.y += o1.y;
            }
            *(float2*)c0 = v0;
            *(float2*)c1 = v1;
        }
    }
}

// ---------------- input channel scaling ----------------
__global__ void scale_x_kernel(const float* __restrict__ x, float* __restrict__ xs) {
    int idx = blockIdx.x * blockDim.x + threadIdx.x;
    int i = idx & 31;
    float v = x[idx];
    if (i < 4) {
        float c = (i == 0) ? 0.3f : (i == 1) ? 0.5f : (i == 2) ? 0.9f : 1.0f;
        v *= c;
    }
    xs[idx] = v;
}

// ---------------- generic tiled SGEMM (small GEMMs only) ----------------
#define BM 64
#define BN 64
#define BKK 16

template<int MODE>
__global__ void __launch_bounds__(256) gemm_tn_kernel(
    const float* __restrict__ A, int lda,
    const float* __restrict__ Bw, int ldb,
    const float* __restrict__ bias,
    float* __restrict__ C, int ldc,
    int M, int N, int K)
{
    __shared__ float As[BKK][BM + 4];
    __shared__ float Bs[BKK][BN + 4];

    int tid = threadIdx.x;
    int bm = blockIdx.y * BM;
    int bn = blockIdx.x * BN;

    int lrow = tid >> 2;
    int lk   = (tid & 3) * 4;
    int tr = (tid >> 4) * 4;
    int tc = (tid & 15) * 4;

    float acc[4][4];
#pragma unroll
    for (int i = 0; i < 4; i++)
#pragma unroll
        for (int j = 0; j < 4; j++) acc[i][j] = 0.f;

    const float* Aptr = A + (size_t)(bm + lrow) * lda + lk;
    const float* Bptr = Bw + (size_t)(bn + lrow) * ldb + lk;

    for (int k0 = 0; k0 < K; k0 += BKK) {
        float4 av = *(const float4*)Aptr;
        float4 bv = *(const float4*)Bptr;
        Aptr += BKK;
        Bptr += BKK;
        As[lk + 0][lrow] = av.x; As[lk + 1][lrow] = av.y;
        As[lk + 2][lrow] = av.z; As[lk + 3][lrow] = av.w;
        Bs[lk + 0][lrow] = bv.x; Bs[lk + 1][lrow] = bv.y;
        Bs[lk + 2][lrow] = bv.z; Bs[lk + 3][lrow] = bv.w;
        __syncthreads();
#pragma unroll
        for (int k = 0; k < BKK; ++k) {
            float4 a4 = *(const float4*)&As[k][tr];
            float4 b4 = *(const float4*)&Bs[k][tc];
            float ar[4] = {a4.x, a4.y, a4.z, a4.w};
            float br[4] = {b4.x, b4.y, b4.z, b4.w};
#pragma unroll
            for (int i = 0; i < 4; ++i)
#pragma unroll
                for (int j = 0; j < 4; ++j)
                    acc[i][j] = fmaf(ar[i], br[j], acc[i][j]);
        }
        __syncthreads();
    }

#pragma unroll
    for (int i = 0; i < 4; ++i) {
        float* Cp = C + (size_t)(bm + tr + i) * ldc + (bn + tc);
        float vals[4];
#pragma unroll
        for (int j = 0; j < 4; ++j) {
            float v = acc[i][j];
            if (MODE == 0 || MODE == 1) {
                if (bias) v += bias[bn + tc + j];
            }
            if (MODE == 1) {
                v = fmaxf(v, 0.f) + log1pf(expf(-fabsf(v)));
            }
            vals[j] = v;
        }
        float4 r; r.x = vals[0]; r.y = vals[1]; r.z = vals[2]; r.w = vals[3];
        *(float4*)Cp = r;
    }
}

// ---------------- rmsnorm (+ tf32 round for MMA consumption) ----------------
__global__ void __launch_bounds__(128) rmsnorm_kernel(
    const float* __restrict__ h, const float* __restrict__ w, float* __restrict__ out)
{
    int row = blockIdx.x;
    const float* hr = h + (size_t)row * HID;
    float v[4];
    float ss = 0.f;
#pragma unroll
    for (int i = 0; i < 4; i++) {
        v[i] = hr[threadIdx.x + i * 128];
        ss += v[i] * v[i];
    }
#pragma unroll
    for (int o = 16; o; o >>= 1) ss += __shfl_xor_sync(0xffffffffu, ss, o);
    __shared__ float red[4];
    if ((threadIdx.x & 31) == 0) red[threadIdx.x >> 5] = ss;
    __syncthreads();
    float tot = red[0] + red[1] + red[2] + red[3];
    float sc = rsqrtf(tot * (1.f / (float)HID) + 1e-5f);
#pragma unroll
    for (int i = 0; i < 4; i++) {
        int c = threadIdx.x + i * 128;
        out[(size_t)row * HID + c] = tf32r(v[i] * sc * w[c]);
    }
}

// ---------------- depthwise causal conv (K=4) + bias + silu ----------------
__global__ void conv_silu_kernel(const float* __restrict__ xz,
                                 const float* __restrict__ cw,
                                 const float* __restrict__ cb,
                                 float* __restrict__ xssm)
{
    int idx = blockIdx.x * blockDim.x + threadIdx.x;
    int d = idx & (DI - 1);
    int bt = idx >> 10;
    int t = bt & (Tlen - 1);
    float w0 = cw[d * 4 + 0], w1 = cw[d * 4 + 1], w2 = cw[d * 4 + 2], w3 = cw[d * 4 + 3];
    const float* col = xz + (size_t)bt * (2 * DI) + d;
    float acc = cb[d] + w3 * col[0];
    if (t >= 1) acc += w2 * col[-(2 * DI)];
    if (t >= 2) acc += w1 * col[-(4 * DI)];
    if (t >= 3) acc += w0 * col[-(6 * DI)];
    float sig = 1.f / (1.f + __expf(-acc));
    xssm[(size_t)bt * DI + d] = acc * sig;
}

// ================= chunked smem-staged selective scan =================
// Block = 256 threads = 16 groups x 16 lanes; block handles (b, 16 consecutive d).
// T processed in chunks of SCH=64, double-buffered cp.async prefetch.
#define SCH 64
#define NCH (Tlen / SCH)   // 16

__global__ void __launch_bounds__(256) scan2_kernel(
    const float* __restrict__ delta,  // [MT, DI]
    const float* __restrict__ xssm,   // [MT, DI]
    const float* __restrict__ dbl,    // [MT, 64]  cols 32:48 = B, 48:64 = C
    const float* __restrict__ xz,     // [MT, 2*DI] (z in second half)
    const float* __restrict__ A_log,  // [DI, DS]
    const float* __restrict__ Dp,     // [DI]
    float* __restrict__ y)            // [MT, DI]
{
    __shared__ float sd[2][SCH][16];
    __shared__ float sx[2][SCH][16];
    __shared__ float sz[2][SCH][16];
    __shared__ float sbc[2][SCH][32];
    __shared__ float sy[SCH][16];

    int tid = threadIdx.x;
    int b   = blockIdx.x >> 6;          // 0..7
    int dt0 = (blockIdx.x & 63) << 4;   // d tile base

    int s   = tid & 15;
    int grp = tid >> 4;                 // 0..15
    int d   = dt0 + grp;

    float A  = -expf(A_log[d * DS + s]);
    float Dd = Dp[d];
    float hst = 0.f;

    int lrow = tid >> 2;          // 0..63
    int lq   = (tid & 3) * 4;     // 0,4,8,12
    size_t base_row = (size_t)b * Tlen;

    // prefetch chunk 0 -> buf 0
    {
        size_t ro = (base_row + lrow);
        cpa16(smem_u32(&sd[0][lrow][lq]), delta + ro * DI + dt0 + lq);
        cpa16(smem_u32(&sx[0][lrow][lq]), xssm + ro * DI + dt0 + lq);
        cpa16(smem_u32(&sz[0][lrow][lq]), xz + ro * (2 * DI) + DI + dt0 + lq);
#pragma unroll
        for (int i = 0; i < 2; i++) {
            int idx = i * 256 + tid;
            int r = idx >> 3, qq = (idx & 7) * 4;
            cpa16(smem_u32(&sbc[0][r][qq]), dbl + (base_row + r) * 64 + 32 + qq);
        }
        asm volatile("cp.async.commit_group;" ::: "memory");
    }

    for (int c = 0; c < NCH; c++) {
        int buf = c & 1;
        if (c + 1 < NCH) {
            int nb = 1 - buf;
            size_t ro = (base_row + (c + 1) * SCH + lrow);
            cpa16(smem_u32(&sd[nb][lrow][lq]), delta + ro * DI + dt0 + lq);
            cpa16(smem_u32(&sx[nb][lrow][lq]), xssm + ro * DI + dt0 + lq);
            cpa16(smem_u32(&sz[nb][lrow][lq]), xz + ro * (2 * DI) + DI + dt0 + lq);
#pragma unroll
            for (int i = 0; i < 2; i++) {
                int idx = i * 256 + tid;
                int r = idx >> 3, qq = (idx & 7) * 4;
                cpa16(smem_u32(&sbc[nb][r][qq]),
                      dbl + (base_row + (c + 1) * SCH + r) * 64 + 32 + qq);
            }
            asm volatile("cp.async.commit_group;" ::: "memory");
            asm volatile("cp.async.wait_group 1;" ::: "memory");
        } else {
            asm volatile("cp.async.wait_group 0;" ::: "memory");
        }
        __syncthreads();

#pragma unroll 4
        for (int tt = 0; tt < SCH; tt++) {
            float dtv = sd[buf][tt][grp];
            float xv  = sx[buf][tt][grp];
            float Bv  = sbc[buf][tt][s];
            float Cv  = sbc[buf][tt][16 + s];
            float dA = __expf(dtv * A);
            hst = fmaf(hst, dA, dtv * xv * Bv);
            float yv = hst * Cv;
            yv += __shfl_xor_sync(0xffffffffu, yv, 8, 32);
            yv += __shfl_xor_sync(0xffffffffu, yv, 4, 32);
            yv += __shfl_xor_sync(0xffffffffu, yv, 2, 32);
            yv += __shfl_xor_sync(0xffffffffu, yv, 1, 32);
            if (s == 0) {
                float zv = sz[buf][tt][grp];
                float szl = zv / (1.f + __expf(-zv));
                sy[tt][grp] = tf32r((yv + xv * Dd) * szl);
            }
        }
        __syncthreads();

        // coalesced store of y chunk
        {
            size_t ro = (base_row + c * SCH + lrow);
            float4 v = *(const float4*)&sy[lrow][lq];
            *(float4*)(y + ro * DI + dt0 + lq) = v;
        }
        // next iteration's top __syncthreads orders sy reuse
    }
}

// ---------------- final FC on last token ----------------
__global__ void fc_kernel(const float* __restrict__ h, const float* __restrict__ fc_w,
                          const float* __restrict__ fc_b, float* __restrict__ out)
{
    int idx = blockIdx.x * blockDim.x + threadIdx.x;
    if (idx >= Bsz * Fdim) return;
    int b = idx / Fdim, f = idx % Fdim;
    const float* hr = h + ((size_t)b * Tlen + (Tlen - 1)) * HID;
    const float* wr = fc_w + (size_t)f * HID;
    float acc = fc_b[f];
    for (int k = 0; k < HID; k += 4) {
        float4 hv = *(const float4*)(hr + k);
        float4 wv = *(const float4*)(wr + k);
        acc += hv.x * wv.x + hv.y * wv.y + hv.z * wv.z + hv.w * wv.w;
    }
    out[idx] = acc;
}

// ---------------- launcher ----------------
extern "C" void kernel_launch(void* const* d_in, const int* in_sizes, int n_in,
                              void* d_out, int out_size)
{
    const float* x        = (const float*)d_in[0];
    const float* ip_w     = (const float*)d_in[1];
    const float* ip_b     = (const float*)d_in[2];
    const float* norm_w   = (const float*)d_in[3];
    const float* inp_w    = (const float*)d_in[4];
    const float* conv_w   = (const float*)d_in[5];
    const float* conv_b   = (const float*)d_in[6];
    const float* xproj_w  = (const float*)d_in[7];
    const float* dtproj_w = (const float*)d_in[8];
    const float* dtproj_b = (const float*)d_in[9];
    const float* A_log    = (const float*)d_in[10];
    const float* Dvec     = (const float*)d_in[11];
    const float* outp_w   = (const float*)d_in[12];
    const float* fc_w     = (const float*)d_in[13];
    const float* fc_b     = (const float*)d_in[14];

    float *h, *hn, *xz, *xssm, *dbl, *delta, *y, *xs, *wi, *wo;
    cudaGetSymbolAddress((void**)&h, g_h);
    cudaGetSymbolAddress((void**)&hn, g_hn);
    cudaGetSymbolAddress((void**)&xz, g_xz);
    cudaGetSymbolAddress((void**)&xssm, g_xssm);
    cudaGetSymbolAddress((void**)&dbl, g_dbl);
    cudaGetSymbolAddress((void**)&delta, g_delta);
    cudaGetSymbolAddress((void**)&y, g_y);
    cudaGetSymbolAddress((void**)&xs, g_xs);
    cudaGetSymbolAddress((void**)&wi, g_wi);
    cudaGetSymbolAddress((void**)&wo, g_wo);

    static int attr_done = 0;
    if (!attr_done) {
        cudaFuncSetAttribute(gemm_mma_kernel<0>, cudaFuncAttributeMaxDynamicSharedMemorySize, SMEM_BYTES);
        cudaFuncSetAttribute(gemm_mma_kernel<1>, cudaFuncAttributeMaxDynamicSharedMemorySize, SMEM_BYTES);
        attr_done = 1;
    }

    // x scaled
    scale_x_kernel<<<(MT * IN_DIM) / 256, 256>>>(x, xs);

    // h = xs @ ip_w^T + ip_b   (M=8192, N=512, K=32)
    gemm_tn_kernel<0><<<dim3(HID / BN, MT / BM), 256>>>(
        xs, IN_DIM, ip_w, IN_DIM, ip_b, h, HID, MT, HID, IN_DIM);

    for (int l = 0; l < 2; l++) {
        const float* nw  = norm_w + l * HID;
        const float* iw  = inp_w + (size_t)l * 2 * DI * HID;
        const float* cw  = conv_w + (size_t)l * DI * 4;
        const float* cb  = conv_b + (size_t)l * DI;
        const float* xpw = xproj_w + (size_t)l * 64 * DI;
        const float* dpw = dtproj_w + (size_t)l * DI * DTR;
        const float* dpb = dtproj_b + (size_t)l * DI;
        const float* Al  = A_log + (size_t)l * DI * DS;
        const float* Dl  = Dvec + (size_t)l * DI;
        const float* ow  = outp_w + (size_t)l * HID * DI;

        // hn = rmsnorm(h) * nw  (tf32-rounded)
        rmsnorm_kernel<<<MT, 128>>>(h, nw, hn);

        // round inp_w to tf32
        round_tf32_kernel<<<(2 * DI * HID) / 256, 256>>>(iw, wi, 2 * DI * HID);

        // xz = hn @ inp_w^T   (M=8192, N=2048, K=512) — mma.sync tf32
        gemm_mma_kernel<0><<<dim3((2 * DI) / 128, MT / 128), 256, SMEM_BYTES>>>(
            hn, HID, wi, HID, xz, 2 * DI, HID);

        // depthwise conv + silu -> xssm
        conv_silu_kernel<<<(MT * DI) / 256, 256>>>(xz, cw, cb, xssm);

        // dbl = xssm @ xproj_w^T   (M=8192, N=64, K=1024)
        gemm_tn_kernel<0><<<dim3(64 / BN, MT / BM), 256>>>(
            xssm, DI, xpw, DI, nullptr, dbl, 64, MT, 64, DI);

        // delta = softplus(dt_raw @ dtproj_w^T + dtproj_b)
        gemm_tn_kernel<1><<<dim3(DI / BN, MT / BM), 256>>>(
            dbl, 64, dpw, DTR, dpb, delta, DI, MT, DI, DTR);

        // chunked selective scan (+ x*D, * silu(z)) -> y  (tf32-rounded)
        scan2_kernel<<<Bsz * (DI / 16), 256>>>(delta, xssm, dbl, xz, Al, Dl, y);

        // round outp_w to tf32
        round_tf32_kernel<<<(HID * DI) / 256, 256>>>(ow, wo, HID * DI);

        // h += y @ outp_w^T   (M=8192, N=512, K=1024) — mma.sync tf32, residual add
        gemm_mma_kernel<1><<<dim3(HID / 128, MT / 128), 256, SMEM_BYTES>>>(
            y, DI, wo, DI, h, HID, DI);
    }

    // out = h[:, -1, :] @ fc_w^T + fc_b
    fc_kernel<<<3, 256>>>(h, fc_w, fc_b, (float*)d_out);
}

// round 7
// speedup vs baseline: 2.9141x; 1.0162x over previous
#include <cuda_runtime.h>
#include <cuda_bf16.h>
#include <math.h>
#include <stdint.h>

// Problem constants
#define Bsz 8
#define Tlen 1024
#define IN_DIM 32
#define HID 512
#define DI 1024
#define DS 16
#define DTR 32
#define Fdim 96
#define MT (Bsz * Tlen)   // 8192 rows

// ---------------- scratch (device globals; no runtime allocation) ----------------
__device__ float g_h[MT * HID];        // 16 MB
__device__ float g_hn[MT * HID];       // 16 MB
__device__ float g_xz[MT * 2 * DI];    // 64 MB
__device__ float g_xssm[MT * DI];      // 32 MB
__device__ float g_dbl[MT * 64];       // 2 MB
__device__ float g_delta[MT * DI];     // 32 MB
__device__ float g_y[MT * DI];         // 32 MB
__device__ float g_xs[MT * IN_DIM];    // 1 MB
__device__ float g_wi[2 * 2 * DI * HID]; // 8 MB  (tf32-rounded inp_w, both layers)
__device__ float g_wo[2 * HID * DI];     // 4 MB  (tf32-rounded outp_w, both layers)

// ---------------- tf32 round-to-nearest helper ----------------
__device__ __forceinline__ float tf32r(float x) {
    uint32_t u;
    asm("cvt.rna.tf32.f32 %0, %1;" : "=r"(u) : "f"(x));
    return __uint_as_float(u);
}

__global__ void round_tf32_kernel(const float* __restrict__ in, float* __restrict__ out, int n) {
    int i = blockIdx.x * blockDim.x + threadIdx.x;
    if (i < n) out[i] = tf32r(in[i]);
}

__device__ __forceinline__ uint32_t smem_u32(const void* p) {
    uint32_t a;
    asm("{ .reg .u64 t; cvta.to.shared.u64 t, %1; cvt.u32.u64 %0, t; }" : "=r"(a) : "l"(p));
    return a;
}

__device__ __forceinline__ void cpa16(uint32_t saddr, const void* gaddr) {
    asm volatile("cp.async.cg.shared.global [%0], [%1], 16;" :: "r"(saddr), "l"(gaddr));
}

// ================= mma.sync tf32 GEMM: C[m,n] = sum_k A[m,k]*B[n,k] =================
// CTA tile 128x128x32, 256 threads = 8 warps (2m x 4n), warp tile 64x32.
// 3-stage cp.async pipeline. RES=0: C = acc ; RES=1: C += acc.

#define APAD 36
#define TILE_FLTS (128 * APAD)
#define STAGE_FLTS (2 * TILE_FLTS)
#define NSTAGE 3
#define SMEM_BYTES (NSTAGE * STAGE_FLTS * 4)   // 110592 B

// load 128-row x 32-float tile into padded smem rows
__device__ __forceinline__ void load_tileP(const float* __restrict__ g, int ld,
                                           int row0, int k0, float* s, int tid) {
#pragma unroll
    for (int i = 0; i < 4; i++) {
        int flat = i * 256 + tid;
        int r = flat >> 3;
        int seg = flat & 7;
        const float* gp = g + (size_t)(row0 + r) * ld + k0 + seg * 4;
        cpa16(smem_u32(s + r * APAD + seg * 4), gp);
    }
}

__device__ __forceinline__ void mma8(float* d, const uint32_t* a, const uint32_t* b) {
    asm volatile(
        "mma.sync.aligned.m16n8k8.row.col.f32.tf32.tf32.f32 "
        "{%0,%1,%2,%3}, {%4,%5,%6,%7}, {%8,%9}, {%0,%1,%2,%3};"
        : "+f"(d[0]), "+f"(d[1]), "+f"(d[2]), "+f"(d[3])
        : "r"(a[0]), "r"(a[1]), "r"(a[2]), "r"(a[3]), "r"(b[0]), "r"(b[1]));
}

template<int RES>
__global__ void __launch_bounds__(256)
gemm_mma_kernel(const float* __restrict__ A, int lda,
                const float* __restrict__ B, int ldb,
                float* __restrict__ C, int ldc, int K)
{
    extern __shared__ float sm[];
    int tid = threadIdx.x;
    int wid = tid >> 5, lane = tid & 31;
    int g = lane >> 2, t = lane & 3;
    int warp_m = wid >> 2;
    int warp_n = wid & 3;
    int bm = blockIdx.y * 128;
    int bn = blockIdx.x * 128;

    float acc[4][4][4];
#pragma unroll
    for (int mt = 0; mt < 4; mt++)
#pragma unroll
        for (int nt = 0; nt < 4; nt++)
#pragma unroll
            for (int q = 0; q < 4; q++) acc[mt][nt][q] = 0.f;

    int nk = K >> 5;

    // prologue: stage chunks 0 and 1
    load_tileP(A, lda, bm, 0, sm, tid);
    load_tileP(B, ldb, bn, 0, sm + TILE_FLTS, tid);
    asm volatile("cp.async.commit_group;" ::: "memory");
    if (nk > 1) {
        load_tileP(A, lda, bm, 32, sm + STAGE_FLTS, tid);
        load_tileP(B, ldb, bn, 32, sm + STAGE_FLTS + TILE_FLTS, tid);
        asm volatile("cp.async.commit_group;" ::: "memory");
    }

    for (int kc = 0; kc < nk; kc++) {
        if (kc + 2 < nk) {
            int nb = (kc + 2) % NSTAGE;
            load_tileP(A, lda, bm, (kc + 2) * 32, sm + nb * STAGE_FLTS, tid);
            load_tileP(B, ldb, bn, (kc + 2) * 32, sm + nb * STAGE_FLTS + TILE_FLTS, tid);
            asm volatile("cp.async.commit_group;" ::: "memory");
            asm volatile("cp.async.wait_group 2;" ::: "memory");
        } else if (kc + 1 < nk) {
            asm volatile("cp.async.wait_group 1;" ::: "memory");
        } else {
            asm volatile("cp.async.wait_group 0;" ::: "memory");
        }
        __syncthreads();

        const float* sA = sm + (kc % NSTAGE) * STAGE_FLTS;
        const float* sB = sA + TILE_FLTS;

#pragma unroll
        for (int kk = 0; kk < 32; kk += 8) {
            uint32_t afr[4][4];
#pragma unroll
            for (int mt = 0; mt < 4; mt++) {
                int r0 = warp_m * 64 + mt * 16;
                afr[mt][0] = __float_as_uint(sA[(r0 + g) * APAD + kk + t]);
                afr[mt][1] = __float_as_uint(sA[(r0 + 8 + g) * APAD + kk + t]);
                afr[mt][2] = __float_as_uint(sA[(r0 + g) * APAD + kk + t + 4]);
                afr[mt][3] = __float_as_uint(sA[(r0 + 8 + g) * APAD + kk + t + 4]);
            }
            uint32_t bfr[4][2];
#pragma unroll
            for (int nt = 0; nt < 4; nt++) {
                int n0 = warp_n * 32 + nt * 8;
                bfr[nt][0] = __float_as_uint(sB[(n0 + g) * APAD + kk + t]);
                bfr[nt][1] = __float_as_uint(sB[(n0 + g) * APAD + kk + t + 4]);
            }
#pragma unroll
            for (int mt = 0; mt < 4; mt++)
#pragma unroll
                for (int nt = 0; nt < 4; nt++)
                    mma8(acc[mt][nt], afr[mt], bfr[nt]);
        }
        __syncthreads();
    }

#pragma unroll
    for (int mt = 0; mt < 4; mt++) {
        int row = bm + warp_m * 64 + mt * 16 + g;
#pragma unroll
        for (int nt = 0; nt < 4; nt++) {
            int col = bn + warp_n * 32 + nt * 8 + t * 2;
            float* c0 = C + (size_t)row * ldc + col;
            float* c1 = C + (size_t)(row + 8) * ldc + col;
            float2 v0 = make_float2(acc[mt][nt][0], acc[mt][nt][1]);
            float2 v1 = make_float2(acc[mt][nt][2], acc[mt][nt][3]);
            if (RES) {
                float2 o0 = *(const float2*)c0;
                float2 o1 = *(const float2*)c1;
                v0.x += o0.x; v0.y += o0.y;
                v1.x += o1.x; v1.y += o1.y;
            }
            *(float2*)c0 = v0;
            *(float2*)c1 = v1;
        }
    }
}

// ---------------- input channel scaling ----------------
__global__ void scale_x_kernel(const float* __restrict__ x, float* __restrict__ xs) {
    int idx = blockIdx.x * blockDim.x + threadIdx.x;
    int i = idx & 31;
    float v = x[idx];
    if (i < 4) {
        float c = (i == 0) ? 0.3f : (i == 1) ? 0.5f : (i == 2) ? 0.9f : 1.0f;
        v *= c;
    }
    xs[idx] = v;
}

// ---------------- generic tiled SGEMM (small GEMMs only) ----------------
#define BM 64
#define BN 64
#define BKK 16

template<int MODE>
__global__ void __launch_bounds__(256) gemm_tn_kernel(
    const float* __restrict__ A, int lda,
    const float* __restrict__ Bw, int ldb,
    const float* __restrict__ bias,
    float* __restrict__ C, int ldc,
    int M, int N, int K)
{
    __shared__ float As[BKK][BM + 4];
    __shared__ float Bs[BKK][BN + 4];

    int tid = threadIdx.x;
    int bm = blockIdx.y * BM;
    int bn = blockIdx.x * BN;

    int lrow = tid >> 2;
    int lk   = (tid & 3) * 4;
    int tr = (tid >> 4) * 4;
    int tc = (tid & 15) * 4;

    float acc[4][4];
#pragma unroll
    for (int i = 0; i < 4; i++)
#pragma unroll
        for (int j = 0; j < 4; j++) acc[i][j] = 0.f;

    const float* Aptr = A + (size_t)(bm + lrow) * lda + lk;
    const float* Bptr = Bw + (size_t)(bn + lrow) * ldb + lk;

    for (int k0 = 0; k0 < K; k0 += BKK) {
        float4 av = *(const float4*)Aptr;
        float4 bv = *(const float4*)Bptr;
        Aptr += BKK;
        Bptr += BKK;
        As[lk + 0][lrow] = av.x; As[lk + 1][lrow] = av.y;
        As[lk + 2][lrow] = av.z; As[lk + 3][lrow] = av.w;
        Bs[lk + 0][lrow] = bv.x; Bs[lk + 1][lrow] = bv.y;
        Bs[lk + 2][lrow] = bv.z; Bs[lk + 3][lrow] = bv.w;
        __syncthreads();
#pragma unroll
        for (int k = 0; k < BKK; ++k) {
            float4 a4 = *(const float4*)&As[k][tr];
            float4 b4 = *(const float4*)&Bs[k][tc];
            float ar[4] = {a4.x, a4.y, a4.z, a4.w};
            float br[4] = {b4.x, b4.y, b4.z, b4.w};
#pragma unroll
            for (int i = 0; i < 4; ++i)
#pragma unroll
                for (int j = 0; j < 4; ++j)
                    acc[i][j] = fmaf(ar[i], br[j], acc[i][j]);
        }
        __syncthreads();
    }

#pragma unroll
    for (int i = 0; i < 4; ++i) {
        float* Cp = C + (size_t)(bm + tr + i) * ldc + (bn + tc);
        float vals[4];
#pragma unroll
        for (int j = 0; j < 4; ++j) {
            float v = acc[i][j];
            if (MODE == 0 || MODE == 1) {
                if (bias) v += bias[bn + tc + j];
            }
            if (MODE == 1) {
                v = fmaxf(v, 0.f) + log1pf(expf(-fabsf(v)));
            }
            vals[j] = v;
        }
        float4 r; r.x = vals[0]; r.y = vals[1]; r.z = vals[2]; r.w = vals[3];
        *(float4*)Cp = r;
    }
}

// ---------------- rmsnorm (+ tf32 round for MMA consumption) ----------------
__global__ void __launch_bounds__(128) rmsnorm_kernel(
    const float* __restrict__ h, const float* __restrict__ w, float* __restrict__ out)
{
    int row = blockIdx.x;
    const float* hr = h + (size_t)row * HID;
    float v[4];
    float ss = 0.f;
#pragma unroll
    for (int i = 0; i < 4; i++) {
        v[i] = hr[threadIdx.x + i * 128];
        ss += v[i] * v[i];
    }
#pragma unroll
    for (int o = 16; o; o >>= 1) ss += __shfl_xor_sync(0xffffffffu, ss, o);
    __shared__ float red[4];
    if ((threadIdx.x & 31) == 0) red[threadIdx.x >> 5] = ss;
    __syncthreads();
    float tot = red[0] + red[1] + red[2] + red[3];
    float sc = rsqrtf(tot * (1.f / (float)HID) + 1e-5f);
#pragma unroll
    for (int i = 0; i < 4; i++) {
        int c = threadIdx.x + i * 128;
        out[(size_t)row * HID + c] = tf32r(v[i] * sc * w[c]);
    }
}

// ---------------- depthwise causal conv (K=4) + bias + silu ----------------
__global__ void conv_silu_kernel(const float* __restrict__ xz,
                                 const float* __restrict__ cw,
                                 const float* __restrict__ cb,
                                 float* __restrict__ xssm)
{
    int idx = blockIdx.x * blockDim.x + threadIdx.x;
    int d = idx & (DI - 1);
    int bt = idx >> 10;
    int t = bt & (Tlen - 1);
    float w0 = cw[d * 4 + 0], w1 = cw[d * 4 + 1], w2 = cw[d * 4 + 2], w3 = cw[d * 4 + 3];
    const float* col = xz + (size_t)bt * (2 * DI) + d;
    float acc = cb[d] + w3 * col[0];
    if (t >= 1) acc += w2 * col[-(2 * DI)];
    if (t >= 2) acc += w1 * col[-(4 * DI)];
    if (t >= 3) acc += w0 * col[-(6 * DI)];
    float sig = 1.f / (1.f + __expf(-acc));
    xssm[(size_t)bt * DI + d] = acc * sig;
}

// ================= chunked smem-staged selective scan =================
#define SCH 64
#define NCH (Tlen / SCH)   // 16

__global__ void __launch_bounds__(256) scan2_kernel(
    const float* __restrict__ delta,
    const float* __restrict__ xssm,
    const float* __restrict__ dbl,
    const float* __restrict__ xz,
    const float* __restrict__ A_log,
    const float* __restrict__ Dp,
    float* __restrict__ y)
{
    __shared__ float sd[2][SCH][16];
    __shared__ float sx[2][SCH][16];
    __shared__ float sz[2][SCH][16];
    __shared__ float sbc[2][SCH][32];
    __shared__ float sy[SCH][16];

    int tid = threadIdx.x;
    int b   = blockIdx.x >> 6;
    int dt0 = (blockIdx.x & 63) << 4;

    int s   = tid & 15;
    int grp = tid >> 4;
    int d   = dt0 + grp;

    float A  = -expf(A_log[d * DS + s]);
    float Dd = Dp[d];
    float hst = 0.f;

    int lrow = tid >> 2;
    int lq   = (tid & 3) * 4;
    size_t base_row = (size_t)b * Tlen;

    {
        size_t ro = (base_row + lrow);
        cpa16(smem_u32(&sd[0][lrow][lq]), delta + ro * DI + dt0 + lq);
        cpa16(smem_u32(&sx[0][lrow][lq]), xssm + ro * DI + dt0 + lq);
        cpa16(smem_u32(&sz[0][lrow][lq]), xz + ro * (2 * DI) + DI + dt0 + lq);
#pragma unroll
        for (int i = 0; i < 2; i++) {
            int idx = i * 256 + tid;
            int r = idx >> 3, qq = (idx & 7) * 4;
            cpa16(smem_u32(&sbc[0][r][qq]), dbl + (base_row + r) * 64 + 32 + qq);
        }
        asm volatile("cp.async.commit_group;" ::: "memory");
    }

    for (int c = 0; c < NCH; c++) {
        int buf = c & 1;
        if (c + 1 < NCH) {
            int nb = 1 - buf;
            size_t ro = (base_row + (c + 1) * SCH + lrow);
            cpa16(smem_u32(&sd[nb][lrow][lq]), delta + ro * DI + dt0 + lq);
            cpa16(smem_u32(&sx[nb][lrow][lq]), xssm + ro * DI + dt0 + lq);
            cpa16(smem_u32(&sz[nb][lrow][lq]), xz + ro * (2 * DI) + DI + dt0 + lq);
#pragma unroll
            for (int i = 0; i < 2; i++) {
                int idx = i * 256 + tid;
                int r = idx >> 3, qq = (idx & 7) * 4;
                cpa16(smem_u32(&sbc[nb][r][qq]),
                      dbl + (base_row + (c + 1) * SCH + r) * 64 + 32 + qq);
            }
            asm volatile("cp.async.commit_group;" ::: "memory");
            asm volatile("cp.async.wait_group 1;" ::: "memory");
        } else {
            asm volatile("cp.async.wait_group 0;" ::: "memory");
        }
        __syncthreads();

#pragma unroll 4
        for (int tt = 0; tt < SCH; tt++) {
            float dtv = sd[buf][tt][grp];
            float xv  = sx[buf][tt][grp];
            float Bv  = sbc[buf][tt][s];
            float Cv  = sbc[buf][tt][16 + s];
            float dA = __expf(dtv * A);
            hst = fmaf(hst, dA, dtv * xv * Bv);
            float yv = hst * Cv;
            yv += __shfl_xor_sync(0xffffffffu, yv, 8, 32);
            yv += __shfl_xor_sync(0xffffffffu, yv, 4, 32);
            yv += __shfl_xor_sync(0xffffffffu, yv, 2, 32);
            yv += __shfl_xor_sync(0xffffffffu, yv, 1, 32);
            if (s == 0) {
                float zv = sz[buf][tt][grp];
                float szl = zv / (1.f + __expf(-zv));
                sy[tt][grp] = tf32r((yv + xv * Dd) * szl);
            }
        }
        __syncthreads();

        {
            size_t ro = (base_row + c * SCH + lrow);
            float4 v = *(const float4*)&sy[lrow][lq];
            *(float4*)(y + ro * DI + dt0 + lq) = v;
        }
    }
}

// ---------------- final FC on last token ----------------
__global__ void fc_kernel(const float* __restrict__ h, const float* __restrict__ fc_w,
                          const float* __restrict__ fc_b, float* __restrict__ out)
{
    int idx = blockIdx.x * blockDim.x + threadIdx.x;
    if (idx >= Bsz * Fdim) return;
    int b = idx / Fdim, f = idx % Fdim;
    const float* hr = h + ((size_t)b * Tlen + (Tlen - 1)) * HID;
    const float* wr = fc_w + (size_t)f * HID;
    float acc = fc_b[f];
    for (int k = 0; k < HID; k += 4) {
        float4 hv = *(const float4*)(hr + k);
        float4 wv = *(const float4*)(wr + k);
        acc += hv.x * wv.x + hv.y * wv.y + hv.z * wv.z + hv.w * wv.w;
    }
    out[idx] = acc;
}

// ---------------- launcher ----------------
extern "C" void kernel_launch(void* const* d_in, const int* in_sizes, int n_in,
                              void* d_out, int out_size)
{
    const float* x        = (const float*)d_in[0];
    const float* ip_w     = (const float*)d_in[1];
    const float* ip_b     = (const float*)d_in[2];
    const float* norm_w   = (const float*)d_in[3];
    const float* inp_w    = (const float*)d_in[4];
    const float* conv_w   = (const float*)d_in[5];
    const float* conv_b   = (const float*)d_in[6];
    const float* xproj_w  = (const float*)d_in[7];
    const float* dtproj_w = (const float*)d_in[8];
    const float* dtproj_b = (const float*)d_in[9];
    const float* A_log    = (const float*)d_in[10];
    const float* Dvec     = (const float*)d_in[11];
    const float* outp_w   = (const float*)d_in[12];
    const float* fc_w     = (const float*)d_in[13];
    const float* fc_b     = (const float*)d_in[14];

    float *h, *hn, *xz, *xssm, *dbl, *delta, *y, *xs, *wi, *wo;
    cudaGetSymbolAddress((void**)&h, g_h);
    cudaGetSymbolAddress((void**)&hn, g_hn);
    cudaGetSymbolAddress((void**)&xz, g_xz);
    cudaGetSymbolAddress((void**)&xssm, g_xssm);
    cudaGetSymbolAddress((void**)&dbl, g_dbl);
    cudaGetSymbolAddress((void**)&delta, g_delta);
    cudaGetSymbolAddress((void**)&y, g_y);
    cudaGetSymbolAddress((void**)&xs, g_xs);
    cudaGetSymbolAddress((void**)&wi, g_wi);
    cudaGetSymbolAddress((void**)&wo, g_wo);

    static int attr_done = 0;
    if (!attr_done) {
        cudaFuncSetAttribute(gemm_mma_kernel<0>, cudaFuncAttributeMaxDynamicSharedMemorySize, SMEM_BYTES);
        cudaFuncSetAttribute(gemm_mma_kernel<1>, cudaFuncAttributeMaxDynamicSharedMemorySize, SMEM_BYTES);
        attr_done = 1;
    }

    // (1) x scaled
    scale_x_kernel<<<(MT * IN_DIM) / 256, 256>>>(x, xs);

    // (2) round ALL inp_w (both layers) to tf32 once, up front
    round_tf32_kernel<<<(2 * 2 * DI * HID) / 256, 256>>>(inp_w, wi, 2 * 2 * DI * HID);

    // (3) round ALL outp_w (both layers) to tf32
    round_tf32_kernel<<<(2 * HID * DI) / 256, 256>>>(outp_w, wo, 2 * HID * DI);

    // (4) h = xs @ ip_w^T + ip_b   (M=8192, N=512, K=32)
    gemm_tn_kernel<0><<<dim3(HID / BN, MT / BM), 256>>>(
        xs, IN_DIM, ip_w, IN_DIM, ip_b, h, HID, MT, HID, IN_DIM);

    for (int l = 0; l < 2; l++) {
        const float* nw  = norm_w + l * HID;
        const float* wil = wi + (size_t)l * 2 * DI * HID;
        const float* cw  = conv_w + (size_t)l * DI * 4;
        const float* cb  = conv_b + (size_t)l * DI;
        const float* xpw = xproj_w + (size_t)l * 64 * DI;
        const float* dpw = dtproj_w + (size_t)l * DI * DTR;
        const float* dpb = dtproj_b + (size_t)l * DI;
        const float* Al  = A_log + (size_t)l * DI * DS;
        const float* Dl  = Dvec + (size_t)l * DI;
        const float* wol = wo + (size_t)l * HID * DI;

        // (5) hn = rmsnorm(h) * nw  (tf32-rounded)
        rmsnorm_kernel<<<MT, 128>>>(h, nw, hn);

        // (6) xz = hn @ inp_w^T   (M=8192, N=2048, K=512) — mma.sync tf32  [ncu target]
        gemm_mma_kernel<0><<<dim3((2 * DI) / 128, MT / 128), 256, SMEM_BYTES>>>(
            hn, HID, wil, HID, xz, 2 * DI, HID);

        // depthwise conv + silu -> xssm
        conv_silu_kernel<<<(MT * DI) / 256, 256>>>(xz, cw, cb, xssm);

        // dbl = xssm @ xproj_w^T   (M=8192, N=64, K=1024)
        gemm_tn_kernel<0><<<dim3(64 / BN, MT / BM), 256>>>(
            xssm, DI, xpw, DI, nullptr, dbl, 64, MT, 64, DI);

        // delta = softplus(dt_raw @ dtproj_w^T + dtproj_b)
        gemm_tn_kernel<1><<<dim3(DI / BN, MT / BM), 256>>>(
            dbl, 64, dpw, DTR, dpb, delta, DI, MT, DI, DTR);

        // chunked selective scan (+ x*D, * silu(z)) -> y  (tf32-rounded)
        scan2_kernel<<<Bsz * (DI / 16), 256>>>(delta, xssm, dbl, xz, Al, Dl, y);

        // h += y @ outp_w^T   (M=8192, N=512, K=1024) — mma.sync tf32, residual add
        gemm_mma_kernel<1><<<dim3(HID / 128, MT / 128), 256, SMEM_BYTES>>>(
            y, DI, wol, DI, h, HID, DI);
    }

    // out = h[:, -1, :] @ fc_w^T + fc_b
    fc_kernel<<<3, 256>>>(h, fc_w, fc_b, (float*)d_out);
}

// round 10
// speedup vs baseline: 3.5450x; 1.2165x over previous
#include <cuda_runtime.h>
#include <cuda_bf16.h>
#include <cuda_fp16.h>
#include <math.h>
#include <stdint.h>

// Problem constants
#define Bsz 8
#define Tlen 1024
#define IN_DIM 32
#define HID 512
#define DI 1024
#define DS 16
#define DTR 32
#define Fdim 96
#define MT (Bsz * Tlen)   // 8192 rows

// ---------------- scratch (device globals; no runtime allocation) ----------------
__device__ float g_h[MT * HID];          // 16 MB
__device__ __half g_hn_h[MT * HID];      // 8 MB   (fp16 rmsnorm output for MMA)
__device__ float g_xz[MT * 2 * DI];      // 64 MB
__device__ float g_xssm[MT * DI];        // 32 MB
__device__ float g_dbl[MT * 64];         // 2 MB
__device__ float g_delta[MT * DI];       // 32 MB
__device__ __half g_y_h[MT * DI];        // 16 MB  (fp16 scan output for MMA)
__device__ __half g_wi_h[2 * 2 * DI * HID]; // 4 MB  (fp16 inp_w, both layers)
__device__ __half g_wo_h[2 * HID * DI];     // 2 MB  (fp16 outp_w, both layers)

__device__ __forceinline__ uint32_t smem_u32(const void* p) {
    uint32_t a;
    asm("{ .reg .u64 t; cvta.to.shared.u64 t, %1; cvt.u32.u64 %0, t; }" : "=r"(a) : "l"(p));
    return a;
}

__device__ __forceinline__ void cpa16(uint32_t saddr, const void* gaddr) {
    asm volatile("cp.async.cg.shared.global [%0], [%1], 16;" :: "r"(saddr), "l"(gaddr));
}

// ---------------- fp32 -> fp16 conversion ----------------
__global__ void f2h_kernel(const float* __restrict__ in, __half* __restrict__ out, int n) {
    int i = blockIdx.x * blockDim.x + threadIdx.x;
    if (i < n) out[i] = __float2half(in[i]);
}

// ================= mma.sync fp16 GEMM: C[m,n] = sum_k A[m,k]*B[n,k] =================
// A, B fp16 (K-contiguous rows), C fp32. CTA tile 128x128x32, 256 threads = 8 warps
// (2m x 4n), warp tile 64x32, m16n8k16. 3-stage cp.async pipeline.
// RES=0: C = acc ; RES=1: C += acc.

#define HPAD 40                       // halves per smem row (32 + 8) -> conflict-free
#define HTILE (128 * HPAD)            // halves per operand tile
#define HSTAGE (2 * HTILE)            // A + B
#define HNSTAGE 3
#define HSMEM_BYTES (HNSTAGE * HSTAGE * 2)   // 61440 B

// load 128-row x 32-half tile (8 KB) into padded smem rows
__device__ __forceinline__ void load_tileH(const __half* __restrict__ g, int ld,
                                           int row0, int k0, __half* s, int tid) {
#pragma unroll
    for (int i = 0; i < 2; i++) {
        int flat = i * 256 + tid;
        int r = flat >> 2;        // 0..127
        int c = flat & 3;         // 16B chunk (8 halves)
        const __half* gp = g + (size_t)(row0 + r) * ld + k0 + c * 8;
        cpa16(smem_u32(s + r * HPAD + c * 8), gp);
    }
}

__device__ __forceinline__ void mma16(float* d, const uint32_t* a, const uint32_t* b) {
    asm volatile(
        "mma.sync.aligned.m16n8k16.row.col.f32.f16.f16.f32 "
        "{%0,%1,%2,%3}, {%4,%5,%6,%7}, {%8,%9}, {%0,%1,%2,%3};"
        : "+f"(d[0]), "+f"(d[1]), "+f"(d[2]), "+f"(d[3])
        : "r"(a[0]), "r"(a[1]), "r"(a[2]), "r"(a[3]), "r"(b[0]), "r"(b[1]));
}

template<int RES>
__global__ void __launch_bounds__(256)
gemm_hmma_kernel(const __half* __restrict__ A, int lda,
                 const __half* __restrict__ B, int ldb,
                 float* __restrict__ C, int ldc, int K)
{
    extern __shared__ __half smh[];
    int tid = threadIdx.x;
    int wid = tid >> 5, lane = tid & 31;
    int g = lane >> 2, t = lane & 3;
    int warp_m = wid >> 2;            // 0..1 -> 64 rows
    int warp_n = wid & 3;             // 0..3 -> 32 cols
    int bm = blockIdx.y * 128;
    int bn = blockIdx.x * 128;

    float acc[4][4][4];
#pragma unroll
    for (int mt = 0; mt < 4; mt++)
#pragma unroll
        for (int nt = 0; nt < 4; nt++)
#pragma unroll
            for (int q = 0; q < 4; q++) acc[mt][nt][q] = 0.f;

    int nk = K >> 5;

    // prologue: stage chunks 0 and 1
    load_tileH(A, lda, bm, 0, smh, tid);
    load_tileH(B, ldb, bn, 0, smh + HTILE, tid);
    asm volatile("cp.async.commit_group;" ::: "memory");
    if (nk > 1) {
        load_tileH(A, lda, bm, 32, smh + HSTAGE, tid);
        load_tileH(B, ldb, bn, 32, smh + HSTAGE + HTILE, tid);
        asm volatile("cp.async.commit_group;" ::: "memory");
    }

    for (int kc = 0; kc < nk; kc++) {
        if (kc + 2 < nk) {
            int nb = (kc + 2) % HNSTAGE;
            load_tileH(A, lda, bm, (kc + 2) * 32, smh + nb * HSTAGE, tid);
            load_tileH(B, ldb, bn, (kc + 2) * 32, smh + nb * HSTAGE + HTILE, tid);
            asm volatile("cp.async.commit_group;" ::: "memory");
            asm volatile("cp.async.wait_group 2;" ::: "memory");
        } else if (kc + 1 < nk) {
            asm volatile("cp.async.wait_group 1;" ::: "memory");
        } else {
            asm volatile("cp.async.wait_group 0;" ::: "memory");
        }
        __syncthreads();

        const __half* sA = smh + (kc % HNSTAGE) * HSTAGE;
        const __half* sB = sA + HTILE;

#pragma unroll
        for (int kk = 0; kk < 32; kk += 16) {
            uint32_t afr[4][4];
#pragma unroll
            for (int mt = 0; mt < 4; mt++) {
                int r0 = warp_m * 64 + mt * 16;
                afr[mt][0] = *(const uint32_t*)&sA[(r0 + g) * HPAD + kk + 2 * t];
                afr[mt][1] = *(const uint32_t*)&sA[(r0 + 8 + g) * HPAD + kk + 2 * t];
                afr[mt][2] = *(const uint32_t*)&sA[(r0 + g) * HPAD + kk + 2 * t + 8];
                afr[mt][3] = *(const uint32_t*)&sA[(r0 + 8 + g) * HPAD + kk + 2 * t + 8];
            }
            uint32_t bfr[4][2];
#pragma unroll
            for (int nt = 0; nt < 4; nt++) {
                int n0 = warp_n * 32 + nt * 8;
                bfr[nt][0] = *(const uint32_t*)&sB[(n0 + g) * HPAD + kk + 2 * t];
                bfr[nt][1] = *(const uint32_t*)&sB[(n0 + g) * HPAD + kk + 2 * t + 8];
            }
#pragma unroll
            for (int mt = 0; mt < 4; mt++)
#pragma unroll
                for (int nt = 0; nt < 4; nt++)
                    mma16(acc[mt][nt], afr[mt], bfr[nt]);
        }
        __syncthreads();
    }

#pragma unroll
    for (int mt = 0; mt < 4; mt++) {
        int row = bm + warp_m * 64 + mt * 16 + g;
#pragma unroll
        for (int nt = 0; nt < 4; nt++) {
            int col = bn + warp_n * 32 + nt * 8 + t * 2;
            float* c0 = C + (size_t)row * ldc + col;
            float* c1 = C + (size_t)(row + 8) * ldc + col;
            float2 v0 = make_float2(acc[mt][nt][0], acc[mt][nt][1]);
            float2 v1 = make_float2(acc[mt][nt][2], acc[mt][nt][3]);
            if (RES) {
                float2 o0 = *(const float2*)c0;
                float2 o1 = *(const float2*)c1;
                v0.x += o0.x; v0.y += o0.y;
                v1.x += o1.x; v1.y += o1.y;
            }
            *(float2*)c0 = v0;
            *(float2*)c1 = v1;
        }
    }
}

// ---------------- generic tiled SGEMM (small GEMMs only) ----------------
// MODE 0: C = acc (+bias); MODE 1: C = softplus(acc + bias); MODE 3: MODE 0 + scale x[:, :4]
#define BM 64
#define BN 64
#define BKK 16

template<int MODE>
__global__ void __launch_bounds__(256) gemm_tn_kernel(
    const float* __restrict__ A, int lda,
    const float* __restrict__ Bw, int ldb,
    const float* __restrict__ bias,
    float* __restrict__ C, int ldc,
    int M, int N, int K)
{
    __shared__ float As[BKK][BM + 4];
    __shared__ float Bs[BKK][BN + 4];

    int tid = threadIdx.x;
    int bm = blockIdx.y * BM;
    int bn = blockIdx.x * BN;

    int lrow = tid >> 2;
    int lk   = (tid & 3) * 4;
    int tr = (tid >> 4) * 4;
    int tc = (tid & 15) * 4;

    float acc[4][4];
#pragma unroll
    for (int i = 0; i < 4; i++)
#pragma unroll
        for (int j = 0; j < 4; j++) acc[i][j] = 0.f;

    const float* Aptr = A + (size_t)(bm + lrow) * lda + lk;
    const float* Bptr = Bw + (size_t)(bn + lrow) * ldb + lk;

    for (int k0 = 0; k0 < K; k0 += BKK) {
        float4 av = *(const float4*)Aptr;
        float4 bv = *(const float4*)Bptr;
        if (MODE == 3 && k0 == 0 && lk == 0) {
            av.x *= 0.3f; av.y *= 0.5f; av.z *= 0.9f;   // coeff for x channels 0..3 (ch3 = 1.0)
        }
        Aptr += BKK;
        Bptr += BKK;
        As[lk + 0][lrow] = av.x; As[lk + 1][lrow] = av.y;
        As[lk + 2][lrow] = av.z; As[lk + 3][lrow] = av.w;
        Bs[lk + 0][lrow] = bv.x; Bs[lk + 1][lrow] = bv.y;
        Bs[lk + 2][lrow] = bv.z; Bs[lk + 3][lrow] = bv.w;
        __syncthreads();
#pragma unroll
        for (int k = 0; k < BKK; ++k) {
            float4 a4 = *(const float4*)&As[k][tr];
            float4 b4 = *(const float4*)&Bs[k][tc];
            float ar[4] = {a4.x, a4.y, a4.z, a4.w};
            float br[4] = {b4.x, b4.y, b4.z, b4.w};
#pragma unroll
            for (int i = 0; i < 4; ++i)
#pragma unroll
                for (int j = 0; j < 4; ++j)
                    acc[i][j] = fmaf(ar[i], br[j], acc[i][j]);
        }
        __syncthreads();
    }

#pragma unroll
    for (int i = 0; i < 4; ++i) {
        float* Cp = C + (size_t)(bm + tr + i) * ldc + (bn + tc);
        float vals[4];
#pragma unroll
        for (int j = 0; j < 4; ++j) {
            float v = acc[i][j];
            if (bias) v += bias[bn + tc + j];
            if (MODE == 1) {
                v = fmaxf(v, 0.f) + log1pf(expf(-fabsf(v)));
            }
            vals[j] = v;
        }
        float4 r; r.x = vals[0]; r.y = vals[1]; r.z = vals[2]; r.w = vals[3];
        *(float4*)Cp = r;
    }
}

// ---------------- rmsnorm -> fp16 output for MMA ----------------
__global__ void __launch_bounds__(128) rmsnorm_kernel(
    const float* __restrict__ h, const float* __restrict__ w, __half* __restrict__ out)
{
    int row = blockIdx.x;
    const float* hr = h + (size_t)row * HID;
    float v[4];
    float ss = 0.f;
#pragma unroll
    for (int i = 0; i < 4; i++) {
        v[i] = hr[threadIdx.x + i * 128];
        ss += v[i] * v[i];
    }
#pragma unroll
    for (int o = 16; o; o >>= 1) ss += __shfl_xor_sync(0xffffffffu, ss, o);
    __shared__ float red[4];
    if ((threadIdx.x & 31) == 0) red[threadIdx.x >> 5] = ss;
    __syncthreads();
    float tot = red[0] + red[1] + red[2] + red[3];
    float sc = rsqrtf(tot * (1.f / (float)HID) + 1e-5f);
#pragma unroll
    for (int i = 0; i < 4; i++) {
        int c = threadIdx.x + i * 128;
        out[(size_t)row * HID + c] = __float2half(v[i] * sc * w[c]);
    }
}

// ---------------- depthwise causal conv (K=4) + bias + silu ----------------
__global__ void conv_silu_kernel(const float* __restrict__ xz,
                                 const float* __restrict__ cw,
                                 const float* __restrict__ cb,
                                 float* __restrict__ xssm)
{
    int idx = blockIdx.x * blockDim.x + threadIdx.x;
    int d = idx & (DI - 1);
    int bt = idx >> 10;
    int t = bt & (Tlen - 1);
    float w0 = cw[d * 4 + 0], w1 = cw[d * 4 + 1], w2 = cw[d * 4 + 2], w3 = cw[d * 4 + 3];
    const float* col = xz + (size_t)bt * (2 * DI) + d;
    float acc = cb[d] + w3 * col[0];
    if (t >= 1) acc += w2 * col[-(2 * DI)];
    if (t >= 2) acc += w1 * col[-(4 * DI)];
    if (t >= 3) acc += w0 * col[-(6 * DI)];
    float sig = 1.f / (1.f + __expf(-acc));
    xssm[(size_t)bt * DI + d] = acc * sig;
}

// ================= chunked smem-staged selective scan (fp16 y output) =================
#define SCH 64
#define NCH (Tlen / SCH)   // 16

__global__ void __launch_bounds__(256) scan2_kernel(
    const float* __restrict__ delta,
    const float* __restrict__ xssm,
    const float* __restrict__ dbl,
    const float* __restrict__ xz,
    const float* __restrict__ A_log,
    const float* __restrict__ Dp,
    __half* __restrict__ y)
{
    __shared__ float sd[2][SCH][16];
    __shared__ float sx[2][SCH][16];
    __shared__ float sz[2][SCH][16];
    __shared__ float sbc[2][SCH][32];
    __shared__ float sy[SCH][16];

    int tid = threadIdx.x;
    int b   = blockIdx.x >> 6;
    int dt0 = (blockIdx.x & 63) << 4;

    int s   = tid & 15;
    int grp = tid >> 4;
    int d   = dt0 + grp;

    float A  = -expf(A_log[d * DS + s]);
    float Dd = Dp[d];
    float hst = 0.f;

    int lrow = tid >> 2;
    int lq   = (tid & 3) * 4;
    size_t base_row = (size_t)b * Tlen;

    {
        size_t ro = (base_row + lrow);
        cpa16(smem_u32(&sd[0][lrow][lq]), delta + ro * DI + dt0 + lq);
        cpa16(smem_u32(&sx[0][lrow][lq]), xssm + ro * DI + dt0 + lq);
        cpa16(smem_u32(&sz[0][lrow][lq]), xz + ro * (2 * DI) + DI + dt0 + lq);
#pragma unroll
        for (int i = 0; i < 2; i++) {
            int idx = i * 256 + tid;
            int r = idx >> 3, qq = (idx & 7) * 4;
            cpa16(smem_u32(&sbc[0][r][qq]), dbl + (base_row + r) * 64 + 32 + qq);
        }
        asm volatile("cp.async.commit_group;" ::: "memory");
    }

    for (int c = 0; c < NCH; c++) {
        int buf = c & 1;
        if (c + 1 < NCH) {
            int nb = 1 - buf;
            size_t ro = (base_row + (c + 1) * SCH + lrow);
            cpa16(smem_u32(&sd[nb][lrow][lq]), delta + ro * DI + dt0 + lq);
            cpa16(smem_u32(&sx[nb][lrow][lq]), xssm + ro * DI + dt0 + lq);
            cpa16(smem_u32(&sz[nb][lrow][lq]), xz + ro * (2 * DI) + DI + dt0 + lq);
#pragma unroll
            for (int i = 0; i < 2; i++) {
                int idx = i * 256 + tid;
                int r = idx >> 3, qq = (idx & 7) * 4;
                cpa16(smem_u32(&sbc[nb][r][qq]),
                      dbl + (base_row + (c + 1) * SCH + r) * 64 + 32 + qq);
            }
            asm volatile("cp.async.commit_group;" ::: "memory");
            asm volatile("cp.async.wait_group 1;" ::: "memory");
        } else {
            asm volatile("cp.async.wait_group 0;" ::: "memory");
        }
        __syncthreads();

#pragma unroll 4
        for (int tt = 0; tt < SCH; tt++) {
            float dtv = sd[buf][tt][grp];
            float xv  = sx[buf][tt][grp];
            float Bv  = sbc[buf][tt][s];
            float Cv  = sbc[buf][tt][16 + s];
            float dA = __expf(dtv * A);
            hst = fmaf(hst, dA, dtv * xv * Bv);
            float yv = hst * Cv;
            yv += __shfl_xor_sync(0xffffffffu, yv, 8, 32);
            yv += __shfl_xor_sync(0xffffffffu, yv, 4, 32);
            yv += __shfl_xor_sync(0xffffffffu, yv, 2, 32);
            yv += __shfl_xor_sync(0xffffffffu, yv, 1, 32);
            if (s == 0) {
                float zv = sz[buf][tt][grp];
                float szl = zv / (1.f + __expf(-zv));
                sy[tt][grp] = (yv + xv * Dd) * szl;
            }
        }
        __syncthreads();

        // coalesced fp16 store of y chunk (4 halves = 8 B per thread)
        {
            size_t ro = (base_row + c * SCH + lrow);
            float4 v = *(const float4*)&sy[lrow][lq];
            __half2 h0 = __floats2half2_rn(v.x, v.y);
            __half2 h1 = __floats2half2_rn(v.z, v.w);
            uint2 u;
            u.x = *(const uint32_t*)&h0;
            u.y = *(const uint32_t*)&h1;
            *(uint2*)(y + ro * DI + dt0 + lq) = u;
        }
    }
}

// ---------------- final FC on last token ----------------
__global__ void fc_kernel(const float* __restrict__ h, const float* __restrict__ fc_w,
                          const float* __restrict__ fc_b, float* __restrict__ out)
{
    int idx = blockIdx.x * blockDim.x + threadIdx.x;
    if (idx >= Bsz * Fdim) return;
    int b = idx / Fdim, f = idx % Fdim;
    const float* hr = h + ((size_t)b * Tlen + (Tlen - 1)) * HID;
    const float* wr = fc_w + (size_t)f * HID;
    float acc = fc_b[f];
    for (int k = 0; k < HID; k += 4) {
        float4 hv = *(const float4*)(hr + k);
        float4 wv = *(const float4*)(wr + k);
        acc += hv.x * wv.x + hv.y * wv.y + hv.z * wv.z + hv.w * wv.w;
    }
    out[idx] = acc;
}

// ---------------- launcher ----------------
extern "C" void kernel_launch(void* const* d_in, const int* in_sizes, int n_in,
                              void* d_out, int out_size)
{
    const float* x        = (const float*)d_in[0];
    const float* ip_w     = (const float*)d_in[1];
    const float* ip_b     = (const float*)d_in[2];
    const float* norm_w   = (const float*)d_in[3];
    const float* inp_w    = (const float*)d_in[4];
    const float* conv_w   = (const float*)d_in[5];
    const float* conv_b   = (const float*)d_in[6];
    const float* xproj_w  = (const float*)d_in[7];
    const float* dtproj_w = (const float*)d_in[8];
    const float* dtproj_b = (const float*)d_in[9];
    const float* A_log    = (const float*)d_in[10];
    const float* Dvec     = (const float*)d_in[11];
    const float* outp_w   = (const float*)d_in[12];
    const float* fc_w     = (const float*)d_in[13];
    const float* fc_b     = (const float*)d_in[14];

    float *h, *xz, *xssm, *dbl, *delta;
    __half *hn_h, *y_h, *wi_h, *wo_h;
    cudaGetSymbolAddress((void**)&h, g_h);
    cudaGetSymbolAddress((void**)&hn_h, g_hn_h);
    cudaGetSymbolAddress((void**)&xz, g_xz);
    cudaGetSymbolAddress((void**)&xssm, g_xssm);
    cudaGetSymbolAddress((void**)&dbl, g_dbl);
    cudaGetSymbolAddress((void**)&delta, g_delta);
    cudaGetSymbolAddress((void**)&y_h, g_y_h);
    cudaGetSymbolAddress((void**)&wi_h, g_wi_h);
    cudaGetSymbolAddress((void**)&wo_h, g_wo_h);

    static int attr_done = 0;
    if (!attr_done) {
        cudaFuncSetAttribute(gemm_hmma_kernel<0>, cudaFuncAttributeMaxDynamicSharedMemorySize, HSMEM_BYTES);
        cudaFuncSetAttribute(gemm_hmma_kernel<1>, cudaFuncAttributeMaxDynamicSharedMemorySize, HSMEM_BYTES);
        attr_done = 1;
    }

    // (1) convert inp_w (both layers) to fp16
    f2h_kernel<<<(2 * 2 * DI * HID) / 256, 256>>>(inp_w, wi_h, 2 * 2 * DI * HID);

    // (2) h = scaled_x @ ip_w^T + ip_b  (scaling fused into A-load; M=8192, N=512, K=32)
    gemm_tn_kernel<3><<<dim3(HID / BN, MT / BM), 256>>>(
        x, IN_DIM, ip_w, IN_DIM, ip_b, h, HID, MT, HID, IN_DIM);

    // (3) hn = rmsnorm(h) * nw  -> fp16   (layer 0)
    rmsnorm_kernel<<<MT, 128>>>(h, norm_w, hn_h);

    // (4) xz = hn @ inp_w^T  (M=8192, N=2048, K=512) — fp16 mma   [ncu target slot]
    gemm_hmma_kernel<0><<<dim3((2 * DI) / 128, MT / 128), 256, HSMEM_BYTES>>>(
        hn_h, HID, wi_h, HID, xz, 2 * DI, HID);

    // (5) convert outp_w (both layers) to fp16
    f2h_kernel<<<(2 * HID * DI) / 256, 256>>>(outp_w, wo_h, 2 * HID * DI);

    for (int l = 0; l < 2; l++) {
        const float* cw  = conv_w + (size_t)l * DI * 4;
        const float* cb  = conv_b + (size_t)l * DI;
        const float* xpw = xproj_w + (size_t)l * 64 * DI;
        const float* dpw = dtproj_w + (size_t)l * DI * DTR;
        const float* dpb = dtproj_b + (size_t)l * DI;
        const float* Al  = A_log + (size_t)l * DI * DS;
        const float* Dl  = Dvec + (size_t)l * DI;
        const __half* wol = wo_h + (size_t)l * HID * DI;

        if (l > 0) {
            // rmsnorm + inp GEMM for layer l (layer 0 already done above)
            rmsnorm_kernel<<<MT, 128>>>(h, norm_w + l * HID, hn_h);
            gemm_hmma_kernel<0><<<dim3((2 * DI) / 128, MT / 128), 256, HSMEM_BYTES>>>(
                hn_h, HID, wi_h + (size_t)l * 2 * DI * HID, HID, xz, 2 * DI, HID);
        }

        // depthwise conv + silu -> xssm
        conv_silu_kernel<<<(MT * DI) / 256, 256>>>(xz, cw, cb, xssm);

        // dbl = xssm @ xproj_w^T   (M=8192, N=64, K=1024)
        gemm_tn_kernel<0><<<dim3(64 / BN, MT / BM), 256>>>(
            xssm, DI, xpw, DI, nullptr, dbl, 64, MT, 64, DI);

        // delta = softplus(dt_raw @ dtproj_w^T + dtproj_b)
        gemm_tn_kernel<1><<<dim3(DI / BN, MT / BM), 256>>>(
            dbl, 64, dpw, DTR, dpb, delta, DI, MT, DI, DTR);

        // chunked selective scan (+ x*D, * silu(z)) -> y (fp16)
        scan2_kernel<<<Bsz * (DI / 16), 256>>>(delta, xssm, dbl, xz, Al, Dl, y_h);

        // h += y @ outp_w^T   (M=8192, N=512, K=1024) — fp16 mma, residual add
        gemm_hmma_kernel<1><<<dim3(HID / 128, MT / 128), 256, HSMEM_BYTES>>>(
            y_h, DI, wol, DI, h, HID, DI);
    }

    // out = h[:, -1, :] @ fc_w^T + fc_b
    fc_kernel<<<3, 256>>>(h, fc_w, fc_b, (float*)d_out);
}

// round 11
// speedup vs baseline: 4.2565x; 1.2007x over previous
#include <cuda_runtime.h>
#include <cuda_bf16.h>
#include <cuda_fp16.h>
#include <math.h>
#include <stdint.h>

// Problem constants
#define Bsz 8
#define Tlen 1024
#define IN_DIM 32
#define HID 512
#define DI 1024
#define DS 16
#define DTR 32
#define Fdim 96
#define MT (Bsz * Tlen)   // 8192 rows

// ---------------- scratch (device globals; no runtime allocation) ----------------
__device__ float g_h[MT * HID];          // 16 MB
__device__ __half g_hn_h[MT * HID];      // 8 MB
__device__ float g_xz[MT * 2 * DI];      // 64 MB
__device__ float g_xssm[MT * DI];        // 32 MB
__device__ __half g_xssm_h[MT * DI];     // 16 MB
__device__ float g_dbl[MT * 64];         // 2 MB
__device__ __half g_dbl_h[MT * 64];      // 1 MB
__device__ float g_delta[MT * DI];       // 32 MB
__device__ __half g_y_h[MT * DI];        // 16 MB
__device__ __half g_wi_h[2 * 2 * DI * HID]; // 4 MB
__device__ __half g_wo_h[2 * HID * DI];     // 2 MB
__device__ __half g_xpw_h[2 * 64 * DI];     // 256 KB
__device__ __half g_dpw_h[2 * DI * DTR];    // 128 KB

__device__ __forceinline__ uint32_t smem_u32(const void* p) {
    uint32_t a;
    asm("{ .reg .u64 t; cvta.to.shared.u64 t, %1; cvt.u32.u64 %0, t; }" : "=r"(a) : "l"(p));
    return a;
}

__device__ __forceinline__ void cpa16(uint32_t saddr, const void* gaddr) {
    asm volatile("cp.async.cg.shared.global [%0], [%1], 16;" :: "r"(saddr), "l"(gaddr));
}

// ---------------- fp32 -> fp16 conversion ----------------
__global__ void f2h_kernel(const float* __restrict__ in, __half* __restrict__ out, int n) {
    int i = blockIdx.x * blockDim.x + threadIdx.x;
    if (i < n) out[i] = __float2half(in[i]);
}

// ================= mma.sync fp16 GEMM: C[m,n] = sum_k A[m,k]*B[n,k] =================
// CTA tile 128x128x32, 256 threads = 8 warps (2m x 4n), warp tile 64x32, m16n8k16.
// 3-stage cp.async pipeline.
// RES=0: C = acc ; RES=1: C += acc.  EPI=0: none ; EPI=2: softplus(acc + bias).

#define HPAD 40
#define HTILE (128 * HPAD)
#define HSTAGE (2 * HTILE)
#define HNSTAGE 3
#define HSMEM_BYTES (HNSTAGE * HSTAGE * 2)   // 61440 B

__device__ __forceinline__ void load_tileH(const __half* __restrict__ g, int ld,
                                           int row0, int k0, __half* s, int tid) {
#pragma unroll
    for (int i = 0; i < 2; i++) {
        int flat = i * 256 + tid;
        int r = flat >> 2;
        int c = flat & 3;
        const __half* gp = g + (size_t)(row0 + r) * ld + k0 + c * 8;
        cpa16(smem_u32(s + r * HPAD + c * 8), gp);
    }
}

__device__ __forceinline__ void mma16(float* d, const uint32_t* a, const uint32_t* b) {
    asm volatile(
        "mma.sync.aligned.m16n8k16.row.col.f32.f16.f16.f32 "
        "{%0,%1,%2,%3}, {%4,%5,%6,%7}, {%8,%9}, {%0,%1,%2,%3};"
        : "+f"(d[0]), "+f"(d[1]), "+f"(d[2]), "+f"(d[3])
        : "r"(a[0]), "r"(a[1]), "r"(a[2]), "r"(a[3]), "r"(b[0]), "r"(b[1]));
}

template<int RES, int EPI>
__global__ void __launch_bounds__(256)
gemm_hmma_kernel(const __half* __restrict__ A, int lda,
                 const __half* __restrict__ B, int ldb,
                 const float* __restrict__ bias,
                 float* __restrict__ C, int ldc, int K)
{
    extern __shared__ __half smh[];
    int tid = threadIdx.x;
    int wid = tid >> 5, lane = tid & 31;
    int g = lane >> 2, t = lane & 3;
    int warp_m = wid >> 2;
    int warp_n = wid & 3;
    int bm = blockIdx.y * 128;
    int bn = blockIdx.x * 128;

    float acc[4][4][4];
#pragma unroll
    for (int mt = 0; mt < 4; mt++)
#pragma unroll
        for (int nt = 0; nt < 4; nt++)
#pragma unroll
            for (int q = 0; q < 4; q++) acc[mt][nt][q] = 0.f;

    int nk = K >> 5;

    load_tileH(A, lda, bm, 0, smh, tid);
    load_tileH(B, ldb, bn, 0, smh + HTILE, tid);
    asm volatile("cp.async.commit_group;" ::: "memory");
    if (nk > 1) {
        load_tileH(A, lda, bm, 32, smh + HSTAGE, tid);
        load_tileH(B, ldb, bn, 32, smh + HSTAGE + HTILE, tid);
        asm volatile("cp.async.commit_group;" ::: "memory");
    }

    for (int kc = 0; kc < nk; kc++) {
        if (kc + 2 < nk) {
            int nb = (kc + 2) % HNSTAGE;
            load_tileH(A, lda, bm, (kc + 2) * 32, smh + nb * HSTAGE, tid);
            load_tileH(B, ldb, bn, (kc + 2) * 32, smh + nb * HSTAGE + HTILE, tid);
            asm volatile("cp.async.commit_group;" ::: "memory");
            asm volatile("cp.async.wait_group 2;" ::: "memory");
        } else if (kc + 1 < nk) {
            asm volatile("cp.async.wait_group 1;" ::: "memory");
        } else {
            asm volatile("cp.async.wait_group 0;" ::: "memory");
        }
        __syncthreads();

        const __half* sA = smh + (kc % HNSTAGE) * HSTAGE;
        const __half* sB = sA + HTILE;

#pragma unroll
        for (int kk = 0; kk < 32; kk += 16) {
            uint32_t afr[4][4];
#pragma unroll
            for (int mt = 0; mt < 4; mt++) {
                int r0 = warp_m * 64 + mt * 16;
                afr[mt][0] = *(const uint32_t*)&sA[(r0 + g) * HPAD + kk + 2 * t];
                afr[mt][1] = *(const uint32_t*)&sA[(r0 + 8 + g) * HPAD + kk + 2 * t];
                afr[mt][2] = *(const uint32_t*)&sA[(r0 + g) * HPAD + kk + 2 * t + 8];
                afr[mt][3] = *(const uint32_t*)&sA[(r0 + 8 + g) * HPAD + kk + 2 * t + 8];
            }
            uint32_t bfr[4][2];
#pragma unroll
            for (int nt = 0; nt < 4; nt++) {
                int n0 = warp_n * 32 + nt * 8;
                bfr[nt][0] = *(const uint32_t*)&sB[(n0 + g) * HPAD + kk + 2 * t];
                bfr[nt][1] = *(const uint32_t*)&sB[(n0 + g) * HPAD + kk + 2 * t + 8];
            }
#pragma unroll
            for (int mt = 0; mt < 4; mt++)
#pragma unroll
                for (int nt = 0; nt < 4; nt++)
                    mma16(acc[mt][nt], afr[mt], bfr[nt]);
        }
        __syncthreads();
    }

#pragma unroll
    for (int mt = 0; mt < 4; mt++) {
        int row = bm + warp_m * 64 + mt * 16 + g;
#pragma unroll
        for (int nt = 0; nt < 4; nt++) {
            int col = bn + warp_n * 32 + nt * 8 + t * 2;
            float* c0 = C + (size_t)row * ldc + col;
            float* c1 = C + (size_t)(row + 8) * ldc + col;
            float2 v0 = make_float2(acc[mt][nt][0], acc[mt][nt][1]);
            float2 v1 = make_float2(acc[mt][nt][2], acc[mt][nt][3]);
            if (EPI == 2) {
                float b0 = bias[col], b1 = bias[col + 1];
                v0.x += b0; v0.y += b1; v1.x += b0; v1.y += b1;
                v0.x = fmaxf(v0.x, 0.f) + log1pf(expf(-fabsf(v0.x)));
                v0.y = fmaxf(v0.y, 0.f) + log1pf(expf(-fabsf(v0.y)));
                v1.x = fmaxf(v1.x, 0.f) + log1pf(expf(-fabsf(v1.x)));
                v1.y = fmaxf(v1.y, 0.f) + log1pf(expf(-fabsf(v1.y)));
            }
            if (RES) {
                float2 o0 = *(const float2*)c0;
                float2 o1 = *(const float2*)c1;
                v0.x += o0.x; v0.y += o0.y;
                v1.x += o1.x; v1.y += o1.y;
            }
            *(float2*)c0 = v0;
            *(float2*)c1 = v1;
        }
    }
}

// ================= xproj fp16 GEMM: 64x64 CTA tile, 4 warps, dual fp32+fp16 output ===
#define XTILE (64 * HPAD)
#define XSTAGE (2 * XTILE)
#define XNSTAGE 3
#define XSMEM_BYTES (XNSTAGE * XSTAGE * 2)   // 30720 B

__device__ __forceinline__ void load_tileH64(const __half* __restrict__ g, int ld,
                                             int row0, int k0, __half* s, int tid) {
#pragma unroll
    for (int i = 0; i < 2; i++) {
        int flat = i * 128 + tid;
        int r = flat >> 2;
        int c = flat & 3;
        const __half* gp = g + (size_t)(row0 + r) * ld + k0 + c * 8;
        cpa16(smem_u32(s + r * HPAD + c * 8), gp);
    }
}

__global__ void __launch_bounds__(128)
gemm_xproj_kernel(const __half* __restrict__ A, int lda,
                  const __half* __restrict__ B, int ldb,
                  float* __restrict__ C, __half* __restrict__ Ch, int ldc, int K)
{
    extern __shared__ __half smh[];
    int tid = threadIdx.x;
    int wid = tid >> 5, lane = tid & 31;
    int g = lane >> 2, t = lane & 3;
    int warp_m = wid >> 1;   // 0..1 -> 32 rows
    int warp_n = wid & 1;    // 0..1 -> 32 cols
    int bm = blockIdx.y * 64;
    int bn = 0;

    float acc[2][4][4];
#pragma unroll
    for (int mt = 0; mt < 2; mt++)
#pragma unroll
        for (int nt = 0; nt < 4; nt++)
#pragma unroll
            for (int q = 0; q < 4; q++) acc[mt][nt][q] = 0.f;

    int nk = K >> 5;

    load_tileH64(A, lda, bm, 0, smh, tid);
    load_tileH64(B, ldb, bn, 0, smh + XTILE, tid);
    asm volatile("cp.async.commit_group;" ::: "memory");
    load_tileH64(A, lda, bm, 32, smh + XSTAGE, tid);
    load_tileH64(B, ldb, bn, 32, smh + XSTAGE + XTILE, tid);
    asm volatile("cp.async.commit_group;" ::: "memory");

    for (int kc = 0; kc < nk; kc++) {
        if (kc + 2 < nk) {
            int nb = (kc + 2) % XNSTAGE;
            load_tileH64(A, lda, bm, (kc + 2) * 32, smh + nb * XSTAGE, tid);
            load_tileH64(B, ldb, bn, (kc + 2) * 32, smh + nb * XSTAGE + XTILE, tid);
            asm volatile("cp.async.commit_group;" ::: "memory");
            asm volatile("cp.async.wait_group 2;" ::: "memory");
        } else if (kc + 1 < nk) {
            asm volatile("cp.async.wait_group 1;" ::: "memory");
        } else {
            asm volatile("cp.async.wait_group 0;" ::: "memory");
        }
        __syncthreads();

        const __half* sA = smh + (kc % XNSTAGE) * XSTAGE;
        const __half* sB = sA + XTILE;

#pragma unroll
        for (int kk = 0; kk < 32; kk += 16) {
            uint32_t afr[2][4];
#pragma unroll
            for (int mt = 0; mt < 2; mt++) {
                int r0 = warp_m * 32 + mt * 16;
                afr[mt][0] = *(const uint32_t*)&sA[(r0 + g) * HPAD + kk + 2 * t];
                afr[mt][1] = *(const uint32_t*)&sA[(r0 + 8 + g) * HPAD + kk + 2 * t];
                afr[mt][2] = *(const uint32_t*)&sA[(r0 + g) * HPAD + kk + 2 * t + 8];
                afr[mt][3] = *(const uint32_t*)&sA[(r0 + 8 + g) * HPAD + kk + 2 * t + 8];
            }
            uint32_t bfr[4][2];
#pragma unroll
            for (int nt = 0; nt < 4; nt++) {
                int n0 = warp_n * 32 + nt * 8;
                bfr[nt][0] = *(const uint32_t*)&sB[(n0 + g) * HPAD + kk + 2 * t];
                bfr[nt][1] = *(const uint32_t*)&sB[(n0 + g) * HPAD + kk + 2 * t + 8];
            }
#pragma unroll
            for (int mt = 0; mt < 2; mt++)
#pragma unroll
                for (int nt = 0; nt < 4; nt++)
                    mma16(acc[mt][nt], afr[mt], bfr[nt]);
        }
        __syncthreads();
    }

#pragma unroll
    for (int mt = 0; mt < 2; mt++) {
        int row = bm + warp_m * 32 + mt * 16 + g;
#pragma unroll
        for (int nt = 0; nt < 4; nt++) {
            int col = warp_n * 32 + nt * 8 + t * 2;
            float* c0 = C + (size_t)row * ldc + col;
            float* c1 = C + (size_t)(row + 8) * ldc + col;
            *(float2*)c0 = make_float2(acc[mt][nt][0], acc[mt][nt][1]);
            *(float2*)c1 = make_float2(acc[mt][nt][2], acc[mt][nt][3]);
            __half2 h0 = __floats2half2_rn(acc[mt][nt][0], acc[mt][nt][1]);
            __half2 h1 = __floats2half2_rn(acc[mt][nt][2], acc[mt][nt][3]);
            *(__half2*)(Ch + (size_t)row * ldc + col) = h0;
            *(__half2*)(Ch + (size_t)(row + 8) * ldc + col) = h1;
        }
    }
}

// ---------------- generic tiled SGEMM (ip GEMM only) ----------------
#define BM 64
#define BN 64
#define BKK 16

template<int MODE>
__global__ void __launch_bounds__(256) gemm_tn_kernel(
    const float* __restrict__ A, int lda,
    const float* __restrict__ Bw, int ldb,
    const float* __restrict__ bias,
    float* __restrict__ C, int ldc,
    int M, int N, int K)
{
    __shared__ float As[BKK][BM + 4];
    __shared__ float Bs[BKK][BN + 4];

    int tid = threadIdx.x;
    int bm = blockIdx.y * BM;
    int bn = blockIdx.x * BN;

    int lrow = tid >> 2;
    int lk   = (tid & 3) * 4;
    int tr = (tid >> 4) * 4;
    int tc = (tid & 15) * 4;

    float acc[4][4];
#pragma unroll
    for (int i = 0; i < 4; i++)
#pragma unroll
        for (int j = 0; j < 4; j++) acc[i][j] = 0.f;

    const float* Aptr = A + (size_t)(bm + lrow) * lda + lk;
    const float* Bptr = Bw + (size_t)(bn + lrow) * ldb + lk;

    for (int k0 = 0; k0 < K; k0 += BKK) {
        float4 av = *(const float4*)Aptr;
        float4 bv = *(const float4*)Bptr;
        if (MODE == 3 && k0 == 0 && lk == 0) {
            av.x *= 0.3f; av.y *= 0.5f; av.z *= 0.9f;
        }
        Aptr += BKK;
        Bptr += BKK;
        As[lk + 0][lrow] = av.x; As[lk + 1][lrow] = av.y;
        As[lk + 2][lrow] = av.z; As[lk + 3][lrow] = av.w;
        Bs[lk + 0][lrow] = bv.x; Bs[lk + 1][lrow] = bv.y;
        Bs[lk + 2][lrow] = bv.z; Bs[lk + 3][lrow] = bv.w;
        __syncthreads();
#pragma unroll
        for (int k = 0; k < BKK; ++k) {
            float4 a4 = *(const float4*)&As[k][tr];
            float4 b4 = *(const float4*)&Bs[k][tc];
            float ar[4] = {a4.x, a4.y, a4.z, a4.w};
            float br[4] = {b4.x, b4.y, b4.z, b4.w};
#pragma unroll
            for (int i = 0; i < 4; ++i)
#pragma unroll
                for (int j = 0; j < 4; ++j)
                    acc[i][j] = fmaf(ar[i], br[j], acc[i][j]);
        }
        __syncthreads();
    }

#pragma unroll
    for (int i = 0; i < 4; ++i) {
        float* Cp = C + (size_t)(bm + tr + i) * ldc + (bn + tc);
        float vals[4];
#pragma unroll
        for (int j = 0; j < 4; ++j) {
            float v = acc[i][j];
            if (bias) v += bias[bn + tc + j];
            vals[j] = v;
        }
        float4 r; r.x = vals[0]; r.y = vals[1]; r.z = vals[2]; r.w = vals[3];
        *(float4*)Cp = r;
    }
}

// ---------------- rmsnorm -> fp16 output for MMA ----------------
__global__ void __launch_bounds__(128) rmsnorm_kernel(
    const float* __restrict__ h, const float* __restrict__ w, __half* __restrict__ out)
{
    int row = blockIdx.x;
    const float* hr = h + (size_t)row * HID;
    float v[4];
    float ss = 0.f;
#pragma unroll
    for (int i = 0; i < 4; i++) {
        v[i] = hr[threadIdx.x + i * 128];
        ss += v[i] * v[i];
    }
#pragma unroll
    for (int o = 16; o; o >>= 1) ss += __shfl_xor_sync(0xffffffffu, ss, o);
    __shared__ float red[4];
    if ((threadIdx.x & 31) == 0) red[threadIdx.x >> 5] = ss;
    __syncthreads();
    float tot = red[0] + red[1] + red[2] + red[3];
    float sc = rsqrtf(tot * (1.f / (float)HID) + 1e-5f);
#pragma unroll
    for (int i = 0; i < 4; i++) {
        int c = threadIdx.x + i * 128;
        out[(size_t)row * HID + c] = __float2half(v[i] * sc * w[c]);
    }
}

// ---------------- depthwise causal conv (K=4) + bias + silu, fp32 + fp16 out --------
__global__ void conv_silu_kernel(const float* __restrict__ xz,
                                 const float* __restrict__ cw,
                                 const float* __restrict__ cb,
                                 float* __restrict__ xssm,
                                 __half* __restrict__ xssm_h)
{
    int idx = blockIdx.x * blockDim.x + threadIdx.x;
    int d = idx & (DI - 1);
    int bt = idx >> 10;
    int t = bt & (Tlen - 1);
    float w0 = cw[d * 4 + 0], w1 = cw[d * 4 + 1], w2 = cw[d * 4 + 2], w3 = cw[d * 4 + 3];
    const float* col = xz + (size_t)bt * (2 * DI) + d;
    float acc = cb[d] + w3 * col[0];
    if (t >= 1) acc += w2 * col[-(2 * DI)];
    if (t >= 2) acc += w1 * col[-(4 * DI)];
    if (t >= 3) acc += w0 * col[-(6 * DI)];
    float sig = 1.f / (1.f + __expf(-acc));
    float v = acc * sig;
    xssm[(size_t)bt * DI + d] = v;
    xssm_h[(size_t)bt * DI + d] = __float2half(v);
}

// ================= chunked smem-staged selective scan (fp16 y output) =================
#define SCH 64
#define NCH (Tlen / SCH)   // 16

__global__ void __launch_bounds__(256) scan2_kernel(
    const float* __restrict__ delta,
    const float* __restrict__ xssm,
    const float* __restrict__ dbl,
    const float* __restrict__ xz,
    const float* __restrict__ A_log,
    const float* __restrict__ Dp,
    __half* __restrict__ y)
{
    __shared__ float sd[2][SCH][16];    // delta
    __shared__ float sx[2][SCH][16];    // x -> (precompute) dt*x
    __shared__ float sz[2][SCH][16];    // z -> (precompute) silu(z)
    __shared__ float sm2[2][SCH][16];   // (precompute) x*Dd*silu(z)
    __shared__ float sbc[2][SCH][32];
    __shared__ float sy[SCH][16];

    int tid = threadIdx.x;
    int b   = blockIdx.x >> 6;
    int dt0 = (blockIdx.x & 63) << 4;

    int s   = tid & 15;
    int grp = tid >> 4;
    int d   = dt0 + grp;

    float A  = -expf(A_log[d * DS + s]);
    float hst = 0.f;

    int lrow = tid >> 2;
    int lq   = (tid & 3) * 4;
    size_t base_row = (size_t)b * Tlen;

    // D for the 4 columns this thread precomputes
    float4 D4 = *(const float4*)(Dp + dt0 + lq);
    float Dc[4] = {D4.x, D4.y, D4.z, D4.w};

    {
        size_t ro = (base_row + lrow);
        cpa16(smem_u32(&sd[0][lrow][lq]), delta + ro * DI + dt0 + lq);
        cpa16(smem_u32(&sx[0][lrow][lq]), xssm + ro * DI + dt0 + lq);
        cpa16(smem_u32(&sz[0][lrow][lq]), xz + ro * (2 * DI) + DI + dt0 + lq);
#pragma unroll
        for (int i = 0; i < 2; i++) {
            int idx = i * 256 + tid;
            int r = idx >> 3, qq = (idx & 7) * 4;
            cpa16(smem_u32(&sbc[0][r][qq]), dbl + (base_row + r) * 64 + 32 + qq);
        }
        asm volatile("cp.async.commit_group;" ::: "memory");
    }

    for (int c = 0; c < NCH; c++) {
        int buf = c & 1;
        if (c + 1 < NCH) {
            int nb = 1 - buf;
            size_t ro = (base_row + (c + 1) * SCH + lrow);
            cpa16(smem_u32(&sd[nb][lrow][lq]), delta + ro * DI + dt0 + lq);
            cpa16(smem_u32(&sx[nb][lrow][lq]), xssm + ro * DI + dt0 + lq);
            cpa16(smem_u32(&sz[nb][lrow][lq]), xz + ro * (2 * DI) + DI + dt0 + lq);
#pragma unroll
            for (int i = 0; i < 2; i++) {
                int idx = i * 256 + tid;
                int r = idx >> 3, qq = (idx & 7) * 4;
                cpa16(smem_u32(&sbc[nb][r][qq]),
                      dbl + (base_row + (c + 1) * SCH + r) * 64 + 32 + qq);
            }
            asm volatile("cp.async.commit_group;" ::: "memory");
            asm volatile("cp.async.wait_group 1;" ::: "memory");
        } else {
            asm volatile("cp.async.wait_group 0;" ::: "memory");
        }
        __syncthreads();

        // precompute pass: sx <- dt*x ; sz <- silu(z) ; sm2 <- x*D*silu(z)
#pragma unroll
        for (int j = 0; j < 4; j++) {
            float dtv = sd[buf][lrow][lq + j];
            float xv  = sx[buf][lrow][lq + j];
            float zv  = sz[buf][lrow][lq + j];
            float szl = zv / (1.f + __expf(-zv));
            sx[buf][lrow][lq + j]  = dtv * xv;
            sz[buf][lrow][lq + j]  = szl;
            sm2[buf][lrow][lq + j] = xv * Dc[j] * szl;
        }
        __syncthreads();

#pragma unroll 4
        for (int tt = 0; tt < SCH; tt++) {
            float dtv = sd[buf][tt][grp];
            float dtx = sx[buf][tt][grp];
            float Bv  = sbc[buf][tt][s];
            float Cv  = sbc[buf][tt][16 + s];
            float dA = __expf(dtv * A);
            hst = fmaf(hst, dA, dtx * Bv);
            float yv = hst * Cv;
            yv += __shfl_xor_sync(0xffffffffu, yv, 8, 32);
            yv += __shfl_xor_sync(0xffffffffu, yv, 4, 32);
            yv += __shfl_xor_sync(0xffffffffu, yv, 2, 32);
            yv += __shfl_xor_sync(0xffffffffu, yv, 1, 32);
            if (s == 0) {
                sy[tt][grp] = fmaf(yv, sz[buf][tt][grp], sm2[buf][tt][grp]);
            }
        }
        __syncthreads();

        {
            size_t ro = (base_row + c * SCH + lrow);
            float4 v = *(const float4*)&sy[lrow][lq];
            __half2 h0 = __floats2half2_rn(v.x, v.y);
            __half2 h1 = __floats2half2_rn(v.z, v.w);
            uint2 u;
            u.x = *(const uint32_t*)&h0;
            u.y = *(const uint32_t*)&h1;
            *(uint2*)(y + ro * DI + dt0 + lq) = u;
        }
    }
}

// ---------------- final FC on last token ----------------
__global__ void fc_kernel(const float* __restrict__ h, const float* __restrict__ fc_w,
                          const float* __restrict__ fc_b, float* __restrict__ out)
{
    int idx = blockIdx.x * blockDim.x + threadIdx.x;
    if (idx >= Bsz * Fdim) return;
    int b = idx / Fdim, f = idx % Fdim;
    const float* hr = h + ((size_t)b * Tlen + (Tlen - 1)) * HID;
    const float* wr = fc_w + (size_t)f * HID;
    float acc = fc_b[f];
    for (int k = 0; k < HID; k += 4) {
        float4 hv = *(const float4*)(hr + k);
        float4 wv = *(const float4*)(wr + k);
        acc += hv.x * wv.x + hv.y * wv.y + hv.z * wv.z + hv.w * wv.w;
    }
    out[idx] = acc;
}

// ---------------- launcher ----------------
extern "C" void kernel_launch(void* const* d_in, const int* in_sizes, int n_in,
                              void* d_out, int out_size)
{
    const float* x        = (const float*)d_in[0];
    const float* ip_w     = (const float*)d_in[1];
    const float* ip_b     = (const float*)d_in[2];
    const float* norm_w   = (const float*)d_in[3];
    const float* inp_w    = (const float*)d_in[4];
    const float* conv_w   = (const float*)d_in[5];
    const float* conv_b   = (const float*)d_in[6];
    const float* xproj_w  = (const float*)d_in[7];
    const float* dtproj_w = (const float*)d_in[8];
    const float* dtproj_b = (const float*)d_in[9];
    const float* A_log    = (const float*)d_in[10];
    const float* Dvec     = (const float*)d_in[11];
    const float* outp_w   = (const float*)d_in[12];
    const float* fc_w     = (const float*)d_in[13];
    const float* fc_b     = (const float*)d_in[14];

    float *h, *xz, *xssm, *dbl, *delta;
    __half *hn_h, *y_h, *wi_h, *wo_h, *xssm_h, *dbl_h, *xpw_h, *dpw_h;
    cudaGetSymbolAddress((void**)&h, g_h);
    cudaGetSymbolAddress((void**)&hn_h, g_hn_h);
    cudaGetSymbolAddress((void**)&xz, g_xz);
    cudaGetSymbolAddress((void**)&xssm, g_xssm);
    cudaGetSymbolAddress((void**)&xssm_h, g_xssm_h);
    cudaGetSymbolAddress((void**)&dbl, g_dbl);
    cudaGetSymbolAddress((void**)&dbl_h, g_dbl_h);
    cudaGetSymbolAddress((void**)&delta, g_delta);
    cudaGetSymbolAddress((void**)&y_h, g_y_h);
    cudaGetSymbolAddress((void**)&wi_h, g_wi_h);
    cudaGetSymbolAddress((void**)&wo_h, g_wo_h);
    cudaGetSymbolAddress((void**)&xpw_h, g_xpw_h);
    cudaGetSymbolAddress((void**)&dpw_h, g_dpw_h);

    static int attr_done = 0;
    if (!attr_done) {
        cudaFuncSetAttribute(gemm_hmma_kernel<0, 0>, cudaFuncAttributeMaxDynamicSharedMemorySize, HSMEM_BYTES);
        cudaFuncSetAttribute(gemm_hmma_kernel<1, 0>, cudaFuncAttributeMaxDynamicSharedMemorySize, HSMEM_BYTES);
        cudaFuncSetAttribute(gemm_hmma_kernel<0, 2>, cudaFuncAttributeMaxDynamicSharedMemorySize, HSMEM_BYTES);
        attr_done = 1;
    }

    // (1) convert inp_w (both layers) to fp16
    f2h_kernel<<<(2 * 2 * DI * HID) / 256, 256>>>(inp_w, wi_h, 2 * 2 * DI * HID);

    // (2) h = scaled_x @ ip_w^T + ip_b
    gemm_tn_kernel<3><<<dim3(HID / BN, MT / BM), 256>>>(
        x, IN_DIM, ip_w, IN_DIM, ip_b, h, HID, MT, HID, IN_DIM);

    // (3) hn = rmsnorm(h) * nw  -> fp16   (layer 0)
    rmsnorm_kernel<<<MT, 128>>>(h, norm_w, hn_h);

    // (4) xz = hn @ inp_w^T  — fp16 mma   [ncu capture slot]
    gemm_hmma_kernel<0, 0><<<dim3((2 * DI) / 128, MT / 128), 256, HSMEM_BYTES>>>(
        hn_h, HID, wi_h, HID, nullptr, xz, 2 * DI, HID);

    // (5-7) remaining weight conversions (independent of step 4)
    f2h_kernel<<<(2 * HID * DI) / 256, 256>>>(outp_w, wo_h, 2 * HID * DI);
    f2h_kernel<<<(2 * 64 * DI) / 256, 256>>>(xproj_w, xpw_h, 2 * 64 * DI);
    f2h_kernel<<<(2 * DI * DTR) / 256, 256>>>(dtproj_w, dpw_h, 2 * DI * DTR);

    for (int l = 0; l < 2; l++) {
        const float* cw  = conv_w + (size_t)l * DI * 4;
        const float* cb  = conv_b + (size_t)l * DI;
        const float* dpb = dtproj_b + (size_t)l * DI;
        const float* Al  = A_log + (size_t)l * DI * DS;
        const float* Dl  = Dvec + (size_t)l * DI;
        const __half* wol  = wo_h + (size_t)l * HID * DI;
        const __half* xpwl = xpw_h + (size_t)l * 64 * DI;
        const __half* dpwl = dpw_h + (size_t)l * DI * DTR;

        if (l > 0) {
            rmsnorm_kernel<<<MT, 128>>>(h, norm_w + l * HID, hn_h);
            gemm_hmma_kernel<0, 0><<<dim3((2 * DI) / 128, MT / 128), 256, HSMEM_BYTES>>>(
                hn_h, HID, wi_h + (size_t)l * 2 * DI * HID, HID, nullptr, xz, 2 * DI, HID);
        }

        // depthwise conv + silu -> xssm (fp32 + fp16)
        conv_silu_kernel<<<(MT * DI) / 256, 256>>>(xz, cw, cb, xssm, xssm_h);

        // dbl = xssm @ xproj_w^T  (M=8192, N=64, K=1024) — fp16 mma, dual output
        gemm_xproj_kernel<<<dim3(1, MT / 64), 128, XSMEM_BYTES>>>(
            xssm_h, DI, xpwl, DI, dbl, dbl_h, 64, DI);

        // delta = softplus(dt_raw @ dtproj_w^T + dtproj_b)  (K=32) — fp16 mma
        gemm_hmma_kernel<0, 2><<<dim3(DI / 128, MT / 128), 256, HSMEM_BYTES>>>(
            dbl_h, 64, dpwl, DTR, dpb, delta, DI, DTR);

        // chunked selective scan -> y (fp16)
        scan2_kernel<<<Bsz * (DI / 16), 256>>>(delta, xssm, dbl, xz, Al, Dl, y_h);

        // h += y @ outp_w^T  — fp16 mma, residual add
        gemm_hmma_kernel<1, 0><<<dim3(HID / 128, MT / 128), 256, HSMEM_BYTES>>>(
            y_h, DI, wol, DI, nullptr, h, HID, DI);
    }

    // out = h[:, -1, :] @ fc_w^T + fc_b
    fc_kernel<<<3, 256>>>(h, fc_w, fc_b, (float*)d_out);
}

// round 12
// speedup vs baseline: 4.4022x; 1.0342x over previous
#include <cuda_runtime.h>
#include <cuda_bf16.h>
#include <cuda_fp16.h>
#include <math.h>
#include <stdint.h>

// Problem constants
#define Bsz 8
#define Tlen 1024
#define IN_DIM 32
#define HID 512
#define DI 1024
#define DS 16
#define DTR 32
#define Fdim 96
#define MT (Bsz * Tlen)   // 8192 rows

// ---------------- scratch (device globals; no runtime allocation) ----------------
__device__ float g_h[MT * HID];
__device__ __half g_hn_h[MT * HID];
__device__ float g_xz[MT * 2 * DI];
__device__ float g_xssm[MT * DI];
__device__ __half g_xssm_h[MT * DI];
__device__ float g_dbl[MT * 64];
__device__ __half g_dbl_h[MT * 64];
__device__ float g_delta[MT * DI];
__device__ __half g_y_h[MT * DI];
__device__ __half g_wi_h[2 * 2 * DI * HID];
__device__ __half g_wo_h[2 * HID * DI];
__device__ __half g_xpw_h[2 * 64 * DI];
__device__ __half g_dpw_h[2 * DI * DTR];

__device__ __forceinline__ uint32_t smem_u32(const void* p) {
    uint32_t a;
    asm("{ .reg .u64 t; cvta.to.shared.u64 t, %1; cvt.u32.u64 %0, t; }" : "=r"(a) : "l"(p));
    return a;
}

__device__ __forceinline__ void cpa16(uint32_t saddr, const void* gaddr) {
    asm volatile("cp.async.cg.shared.global [%0], [%1], 16;" :: "r"(saddr), "l"(gaddr));
}

// ---------------- fused fp32 -> fp16 conversion of all 4 weight groups ----------------
#define N_WI (2 * 2 * DI * HID)
#define N_WO (2 * HID * DI)
#define N_XPW (2 * 64 * DI)
#define N_DPW (2 * DI * DTR)
#define N_ALLW (N_WI + N_WO + N_XPW + N_DPW)

__global__ void f2h_all_kernel(const float* __restrict__ wi, const float* __restrict__ wo,
                               const float* __restrict__ xpw, const float* __restrict__ dpw,
                               __half* __restrict__ wi_h, __half* __restrict__ wo_h,
                               __half* __restrict__ xpw_h, __half* __restrict__ dpw_h) {
    int i = blockIdx.x * blockDim.x + threadIdx.x;
    if (i < N_WI) { wi_h[i] = __float2half(wi[i]); return; }
    i -= N_WI;
    if (i < N_WO) { wo_h[i] = __float2half(wo[i]); return; }
    i -= N_WO;
    if (i < N_XPW) { xpw_h[i] = __float2half(xpw[i]); return; }
    i -= N_XPW;
    if (i < N_DPW) { dpw_h[i] = __float2half(dpw[i]); }
}

__device__ __forceinline__ void mma16(float* d, const uint32_t* a, const uint32_t* b) {
    asm volatile(
        "mma.sync.aligned.m16n8k16.row.col.f32.f16.f16.f32 "
        "{%0,%1,%2,%3}, {%4,%5,%6,%7}, {%8,%9}, {%0,%1,%2,%3};"
        : "+f"(d[0]), "+f"(d[1]), "+f"(d[2]), "+f"(d[3])
        : "r"(a[0]), "r"(a[1]), "r"(a[2]), "r"(a[3]), "r"(b[0]), "r"(b[1]));
}

__device__ __forceinline__ void ldsm4(uint32_t& r0, uint32_t& r1, uint32_t& r2, uint32_t& r3,
                                      uint32_t addr) {
    asm volatile("ldmatrix.sync.aligned.m8n8.x4.shared.b16 {%0,%1,%2,%3}, [%4];"
                 : "=r"(r0), "=r"(r1), "=r"(r2), "=r"(r3) : "r"(addr));
}

// ================= main fp16 GEMM (ldmatrix + K-chunk 64) ==========================
// C[m,n] = sum_k A[m,k]*B[n,k].  CTA tile 128x128x64, 256 threads = 8 warps (2m x 4n),
// warp tile 64x32, m16n8k16, 3-stage cp.async. RES=0: C = acc ; RES=1: C += acc.

#define H2PAD 72                        // halves per smem row (64 + 8); 144B pitch
#define H2TILE (128 * H2PAD)
#define H2STAGE (2 * H2TILE)
#define H2NSTAGE 3
#define H2SMEM_BYTES (H2NSTAGE * H2STAGE * 2)   // 110592 B

__device__ __forceinline__ void load_tile64(const __half* __restrict__ g, int ld,
                                            int row0, int k0, __half* s, int tid) {
#pragma unroll
    for (int i = 0; i < 4; i++) {
        int flat = i * 256 + tid;
        int r = flat >> 3;       // 0..127
        int c = flat & 7;        // 8 chunks of 8 halves
        const __half* gp = g + (size_t)(row0 + r) * ld + k0 + c * 8;
        cpa16(smem_u32(s + r * H2PAD + c * 8), gp);
    }
}

template<int RES>
__global__ void __launch_bounds__(256)
gemm_hmma64_kernel(const __half* __restrict__ A, int lda,
                   const __half* __restrict__ B, int ldb,
                   float* __restrict__ C, int ldc, int K)
{
    extern __shared__ __half smh[];
    int tid = threadIdx.x;
    int wid = tid >> 5, lane = tid & 31;
    int g = lane >> 2, t = lane & 3;
    int warp_m = wid >> 2;
    int warp_n = wid & 3;
    int bm = blockIdx.y * 128;
    int bn = blockIdx.x * 128;

    // ldmatrix lane mapping: quad q, index i
    int q = lane >> 3, i = lane & 7;
    int lrow = ((q & 1) << 3) + i;     // +0/+8 row within 16-row tile
    int lcol = (q >> 1) << 3;          // +0/+8 col (halves)

    float acc[4][4][4];
#pragma unroll
    for (int mt = 0; mt < 4; mt++)
#pragma unroll
        for (int nt = 0; nt < 4; nt++)
#pragma unroll
            for (int qq = 0; qq < 4; qq++) acc[mt][nt][qq] = 0.f;

    int nk = K >> 6;

    load_tile64(A, lda, bm, 0, smh, tid);
    load_tile64(B, ldb, bn, 0, smh + H2TILE, tid);
    asm volatile("cp.async.commit_group;" ::: "memory");
    if (nk > 1) {
        load_tile64(A, lda, bm, 64, smh + H2STAGE, tid);
        load_tile64(B, ldb, bn, 64, smh + H2STAGE + H2TILE, tid);
        asm volatile("cp.async.commit_group;" ::: "memory");
    }

    for (int kc = 0; kc < nk; kc++) {
        if (kc + 2 < nk) {
            int nb = (kc + 2) % H2NSTAGE;
            load_tile64(A, lda, bm, (kc + 2) * 64, smh + nb * H2STAGE, tid);
            load_tile64(B, ldb, bn, (kc + 2) * 64, smh + nb * H2STAGE + H2TILE, tid);
            asm volatile("cp.async.commit_group;" ::: "memory");
            asm volatile("cp.async.wait_group 2;" ::: "memory");
        } else if (kc + 1 < nk) {
            asm volatile("cp.async.wait_group 1;" ::: "memory");
        } else {
            asm volatile("cp.async.wait_group 0;" ::: "memory");
        }
        __syncthreads();

        const __half* sA = smh + (kc % H2NSTAGE) * H2STAGE;
        const __half* sB = sA + H2TILE;

        // per-mt / per-ntp lane base addresses for ldmatrix
        uint32_t aAddr[4], bAddr[2];
#pragma unroll
        for (int mt = 0; mt < 4; mt++)
            aAddr[mt] = smem_u32(&sA[(warp_m * 64 + mt * 16 + lrow) * H2PAD + lcol]);
#pragma unroll
        for (int p = 0; p < 2; p++)
            bAddr[p] = smem_u32(&sB[(warp_n * 32 + p * 16 + lrow) * H2PAD + lcol]);

#pragma unroll
        for (int kk = 0; kk < 64; kk += 16) {
            uint32_t afr[4][4];
#pragma unroll
            for (int mt = 0; mt < 4; mt++)
                ldsm4(afr[mt][0], afr[mt][1], afr[mt][2], afr[mt][3], aAddr[mt] + kk * 2);
            uint32_t bfr[4][2];
#pragma unroll
            for (int p = 0; p < 2; p++) {
                uint32_t r0, r1, r2, r3;
                ldsm4(r0, r1, r2, r3, bAddr[p] + kk * 2);
                bfr[2 * p][0] = r0; bfr[2 * p + 1][0] = r1;
                bfr[2 * p][1] = r2; bfr[2 * p + 1][1] = r3;
            }
#pragma unroll
            for (int mt = 0; mt < 4; mt++)
#pragma unroll
                for (int nt = 0; nt < 4; nt++)
                    mma16(acc[mt][nt], afr[mt], bfr[nt]);
        }
        __syncthreads();
    }

#pragma unroll
    for (int mt = 0; mt < 4; mt++) {
        int row = bm + warp_m * 64 + mt * 16 + g;
#pragma unroll
        for (int nt = 0; nt < 4; nt++) {
            int col = bn + warp_n * 32 + nt * 8 + t * 2;
            float* c0 = C + (size_t)row * ldc + col;
            float* c1 = C + (size_t)(row + 8) * ldc + col;
            float2 v0 = make_float2(acc[mt][nt][0], acc[mt][nt][1]);
            float2 v1 = make_float2(acc[mt][nt][2], acc[mt][nt][3]);
            if (RES) {
                float2 o0 = *(const float2*)c0;
                float2 o1 = *(const float2*)c1;
                v0.x += o0.x; v0.y += o0.y;
                v1.x += o1.x; v1.y += o1.y;
            }
            *(float2*)c0 = v0;
            *(float2*)c1 = v1;
        }
    }
}

// ================= dtproj fp16 GEMM (K=32, softplus epilogue) =======================
#define HPAD 40
#define HTILE (128 * HPAD)
#define HSTAGE (2 * HTILE)
#define HSMEM_BYTES (2 * HSTAGE * 2)

__device__ __forceinline__ void load_tileH(const __half* __restrict__ g, int ld,
                                           int row0, int k0, __half* s, int tid) {
#pragma unroll
    for (int i = 0; i < 2; i++) {
        int flat = i * 256 + tid;
        int r = flat >> 2;
        int c = flat & 3;
        const __half* gp = g + (size_t)(row0 + r) * ld + k0 + c * 8;
        cpa16(smem_u32(s + r * HPAD + c * 8), gp);
    }
}

__global__ void __launch_bounds__(256)
gemm_dtproj_kernel(const __half* __restrict__ A, int lda,
                   const __half* __restrict__ B, int ldb,
                   const float* __restrict__ bias,
                   float* __restrict__ C, int ldc)
{
    extern __shared__ __half smh[];
    int tid = threadIdx.x;
    int wid = tid >> 5, lane = tid & 31;
    int g = lane >> 2, t = lane & 3;
    int warp_m = wid >> 2;
    int warp_n = wid & 3;
    int bm = blockIdx.y * 128;
    int bn = blockIdx.x * 128;

    float acc[4][4][4];
#pragma unroll
    for (int mt = 0; mt < 4; mt++)
#pragma unroll
        for (int nt = 0; nt < 4; nt++)
#pragma unroll
            for (int qq = 0; qq < 4; qq++) acc[mt][nt][qq] = 0.f;

    // single K-chunk (K=32)
    load_tileH(A, lda, bm, 0, smh, tid);
    load_tileH(B, ldb, bn, 0, smh + HTILE, tid);
    asm volatile("cp.async.commit_group;" ::: "memory");
    asm volatile("cp.async.wait_group 0;" ::: "memory");
    __syncthreads();

    const __half* sA = smh;
    const __half* sB = sA + HTILE;

#pragma unroll
    for (int kk = 0; kk < 32; kk += 16) {
        uint32_t afr[4][4];
#pragma unroll
        for (int mt = 0; mt < 4; mt++) {
            int r0 = warp_m * 64 + mt * 16;
            afr[mt][0] = *(const uint32_t*)&sA[(r0 + g) * HPAD + kk + 2 * t];
            afr[mt][1] = *(const uint32_t*)&sA[(r0 + 8 + g) * HPAD + kk + 2 * t];
            afr[mt][2] = *(const uint32_t*)&sA[(r0 + g) * HPAD + kk + 2 * t + 8];
            afr[mt][3] = *(const uint32_t*)&sA[(r0 + 8 + g) * HPAD + kk + 2 * t + 8];
        }
        uint32_t bfr[4][2];
#pragma unroll
        for (int nt = 0; nt < 4; nt++) {
            int n0 = warp_n * 32 + nt * 8;
            bfr[nt][0] = *(const uint32_t*)&sB[(n0 + g) * HPAD + kk + 2 * t];
            bfr[nt][1] = *(const uint32_t*)&sB[(n0 + g) * HPAD + kk + 2 * t + 8];
        }
#pragma unroll
        for (int mt = 0; mt < 4; mt++)
#pragma unroll
            for (int nt = 0; nt < 4; nt++)
                mma16(acc[mt][nt], afr[mt], bfr[nt]);
    }

#pragma unroll
    for (int mt = 0; mt < 4; mt++) {
        int row = bm + warp_m * 64 + mt * 16 + g;
#pragma unroll
        for (int nt = 0; nt < 4; nt++) {
            int col = bn + warp_n * 32 + nt * 8 + t * 2;
            float b0 = bias[col], b1 = bias[col + 1];
            float2 v0 = make_float2(acc[mt][nt][0] + b0, acc[mt][nt][1] + b1);
            float2 v1 = make_float2(acc[mt][nt][2] + b0, acc[mt][nt][3] + b1);
            v0.x = fmaxf(v0.x, 0.f) + log1pf(expf(-fabsf(v0.x)));
            v0.y = fmaxf(v0.y, 0.f) + log1pf(expf(-fabsf(v0.y)));
            v1.x = fmaxf(v1.x, 0.f) + log1pf(expf(-fabsf(v1.x)));
            v1.y = fmaxf(v1.y, 0.f) + log1pf(expf(-fabsf(v1.y)));
            *(float2*)(C + (size_t)row * ldc + col) = v0;
            *(float2*)(C + (size_t)(row + 8) * ldc + col) = v1;
        }
    }
}

// ================= xproj fp16 GEMM: 64x64 CTA tile, dual fp32+fp16 output ==========
#define XTILE (64 * HPAD)
#define XSTAGE (2 * XTILE)
#define XNSTAGE 3
#define XSMEM_BYTES (XNSTAGE * XSTAGE * 2)

__device__ __forceinline__ void load_tileH64(const __half* __restrict__ g, int ld,
                                             int row0, int k0, __half* s, int tid) {
#pragma unroll
    for (int i = 0; i < 2; i++) {
        int flat = i * 128 + tid;
        int r = flat >> 2;
        int c = flat & 3;
        const __half* gp = g + (size_t)(row0 + r) * ld + k0 + c * 8;
        cpa16(smem_u32(s + r * HPAD + c * 8), gp);
    }
}

__global__ void __launch_bounds__(128)
gemm_xproj_kernel(const __half* __restrict__ A, int lda,
                  const __half* __restrict__ B, int ldb,
                  float* __restrict__ C, __half* __restrict__ Ch, int ldc, int K)
{
    extern __shared__ __half smh[];
    int tid = threadIdx.x;
    int wid = tid >> 5, lane = tid & 31;
    int g = lane >> 2, t = lane & 3;
    int warp_m = wid >> 1;
    int warp_n = wid & 1;
    int bm = blockIdx.y * 64;
    int bn = 0;

    float acc[2][4][4];
#pragma unroll
    for (int mt = 0; mt < 2; mt++)
#pragma unroll
        for (int nt = 0; nt < 4; nt++)
#pragma unroll
            for (int qq = 0; qq < 4; qq++) acc[mt][nt][qq] = 0.f;

    int nk = K >> 5;

    load_tileH64(A, lda, bm, 0, smh, tid);
    load_tileH64(B, ldb, bn, 0, smh + XTILE, tid);
    asm volatile("cp.async.commit_group;" ::: "memory");
    load_tileH64(A, lda, bm, 32, smh + XSTAGE, tid);
    load_tileH64(B, ldb, bn, 32, smh + XSTAGE + XTILE, tid);
    asm volatile("cp.async.commit_group;" ::: "memory");

    for (int kc = 0; kc < nk; kc++) {
        if (kc + 2 < nk) {
            int nb = (kc + 2) % XNSTAGE;
            load_tileH64(A, lda, bm, (kc + 2) * 32, smh + nb * XSTAGE, tid);
            load_tileH64(B, ldb, bn, (kc + 2) * 32, smh + nb * XSTAGE + XTILE, tid);
            asm volatile("cp.async.commit_group;" ::: "memory");
            asm volatile("cp.async.wait_group 2;" ::: "memory");
        } else if (kc + 1 < nk) {
            asm volatile("cp.async.wait_group 1;" ::: "memory");
        } else {
            asm volatile("cp.async.wait_group 0;" ::: "memory");
        }
        __syncthreads();

        const __half* sA = smh + (kc % XNSTAGE) * XSTAGE;
        const __half* sB = sA + XTILE;

#pragma unroll
        for (int kk = 0; kk < 32; kk += 16) {
            uint32_t afr[2][4];
#pragma unroll
            for (int mt = 0; mt < 2; mt++) {
                int r0 = warp_m * 32 + mt * 16;
                afr[mt][0] = *(const uint32_t*)&sA[(r0 + g) * HPAD + kk + 2 * t];
                afr[mt][1] = *(const uint32_t*)&sA[(r0 + 8 + g) * HPAD + kk + 2 * t];
                afr[mt][2] = *(const uint32_t*)&sA[(r0 + g) * HPAD + kk + 2 * t + 8];
                afr[mt][3] = *(const uint32_t*)&sA[(r0 + 8 + g) * HPAD + kk + 2 * t + 8];
            }
            uint32_t bfr[4][2];
#pragma unroll
            for (int nt = 0; nt < 4; nt++) {
                int n0 = warp_n * 32 + nt * 8;
                bfr[nt][0] = *(const uint32_t*)&sB[(n0 + g) * HPAD + kk + 2 * t];
                bfr[nt][1] = *(const uint32_t*)&sB[(n0 + g) * HPAD + kk + 2 * t + 8];
            }
#pragma unroll
            for (int mt = 0; mt < 2; mt++)
#pragma unroll
                for (int nt = 0; nt < 4; nt++)
                    mma16(acc[mt][nt], afr[mt], bfr[nt]);
        }
        __syncthreads();
    }

#pragma unroll
    for (int mt = 0; mt < 2; mt++) {
        int row = bm + warp_m * 32 + mt * 16 + g;
#pragma unroll
        for (int nt = 0; nt < 4; nt++) {
            int col = warp_n * 32 + nt * 8 + t * 2;
            *(float2*)(C + (size_t)row * ldc + col) = make_float2(acc[mt][nt][0], acc[mt][nt][1]);
            *(float2*)(C + (size_t)(row + 8) * ldc + col) = make_float2(acc[mt][nt][2], acc[mt][nt][3]);
            __half2 h0 = __floats2half2_rn(acc[mt][nt][0], acc[mt][nt][1]);
            __half2 h1 = __floats2half2_rn(acc[mt][nt][2], acc[mt][nt][3]);
            *(__half2*)(Ch + (size_t)row * ldc + col) = h0;
            *(__half2*)(Ch + (size_t)(row + 8) * ldc + col) = h1;
        }
    }
}

// ---------------- generic tiled SGEMM (ip GEMM only) ----------------
#define BM 64
#define BN 64
#define BKK 16

template<int MODE>
__global__ void __launch_bounds__(256) gemm_tn_kernel(
    const float* __restrict__ A, int lda,
    const float* __restrict__ Bw, int ldb,
    const float* __restrict__ bias,
    float* __restrict__ C, int ldc,
    int M, int N, int K)
{
    __shared__ float As[BKK][BM + 4];
    __shared__ float Bs[BKK][BN + 4];

    int tid = threadIdx.x;
    int bm = blockIdx.y * BM;
    int bn = blockIdx.x * BN;

    int lrow = tid >> 2;
    int lk   = (tid & 3) * 4;
    int tr = (tid >> 4) * 4;
    int tc = (tid & 15) * 4;

    float acc[4][4];
#pragma unroll
    for (int i = 0; i < 4; i++)
#pragma unroll
        for (int j = 0; j < 4; j++) acc[i][j] = 0.f;

    const float* Aptr = A + (size_t)(bm + lrow) * lda + lk;
    const float* Bptr = Bw + (size_t)(bn + lrow) * ldb + lk;

    for (int k0 = 0; k0 < K; k0 += BKK) {
        float4 av = *(const float4*)Aptr;
        float4 bv = *(const float4*)Bptr;
        if (MODE == 3 && k0 == 0 && lk == 0) {
            av.x *= 0.3f; av.y *= 0.5f; av.z *= 0.9f;
        }
        Aptr += BKK;
        Bptr += BKK;
        As[lk + 0][lrow] = av.x; As[lk + 1][lrow] = av.y;
        As[lk + 2][lrow] = av.z; As[lk + 3][lrow] = av.w;
        Bs[lk + 0][lrow] = bv.x; Bs[lk + 1][lrow] = bv.y;
        Bs[lk + 2][lrow] = bv.z; Bs[lk + 3][lrow] = bv.w;
        __syncthreads();
#pragma unroll
        for (int k = 0; k < BKK; ++k) {
            float4 a4 = *(const float4*)&As[k][tr];
            float4 b4 = *(const float4*)&Bs[k][tc];
            float ar[4] = {a4.x, a4.y, a4.z, a4.w};
            float br[4] = {b4.x, b4.y, b4.z, b4.w};
#pragma unroll
            for (int i = 0; i < 4; ++i)
#pragma unroll
                for (int j = 0; j < 4; ++j)
                    acc[i][j] = fmaf(ar[i], br[j], acc[i][j]);
        }
        __syncthreads();
    }

#pragma unroll
    for (int i = 0; i < 4; ++i) {
        float* Cp = C + (size_t)(bm + tr + i) * ldc + (bn + tc);
        float vals[4];
#pragma unroll
        for (int j = 0; j < 4; ++j) {
            float v = acc[i][j];
            if (bias) v += bias[bn + tc + j];
            vals[j] = v;
        }
        float4 r; r.x = vals[0]; r.y = vals[1]; r.z = vals[2]; r.w = vals[3];
        *(float4*)Cp = r;
    }
}

// ---------------- rmsnorm -> fp16 output for MMA ----------------
__global__ void __launch_bounds__(128) rmsnorm_kernel(
    const float* __restrict__ h, const float* __restrict__ w, __half* __restrict__ out)
{
    int row = blockIdx.x;
    const float* hr = h + (size_t)row * HID;
    float v[4];
    float ss = 0.f;
#pragma unroll
    for (int i = 0; i < 4; i++) {
        v[i] = hr[threadIdx.x + i * 128];
        ss += v[i] * v[i];
    }
#pragma unroll
    for (int o = 16; o; o >>= 1) ss += __shfl_xor_sync(0xffffffffu, ss, o);
    __shared__ float red[4];
    if ((threadIdx.x & 31) == 0) red[threadIdx.x >> 5] = ss;
    __syncthreads();
    float tot = red[0] + red[1] + red[2] + red[3];
    float sc = rsqrtf(tot * (1.f / (float)HID) + 1e-5f);
#pragma unroll
    for (int i = 0; i < 4; i++) {
        int c = threadIdx.x + i * 128;
        out[(size_t)row * HID + c] = __float2half(v[i] * sc * w[c]);
    }
}

// ---------------- depthwise causal conv (K=4) + bias + silu, fp32 + fp16 out --------
__global__ void conv_silu_kernel(const float* __restrict__ xz,
                                 const float* __restrict__ cw,
                                 const float* __restrict__ cb,
                                 float* __restrict__ xssm,
                                 __half* __restrict__ xssm_h)
{
    int idx = blockIdx.x * blockDim.x + threadIdx.x;
    int d = idx & (DI - 1);
    int bt = idx >> 10;
    int t = bt & (Tlen - 1);
    float w0 = cw[d * 4 + 0], w1 = cw[d * 4 + 1], w2 = cw[d * 4 + 2], w3 = cw[d * 4 + 3];
    const float* col = xz + (size_t)bt * (2 * DI) + d;
    float acc = cb[d] + w3 * col[0];
    if (t >= 1) acc += w2 * col[-(2 * DI)];
    if (t >= 2) acc += w1 * col[-(4 * DI)];
    if (t >= 3) acc += w0 * col[-(6 * DI)];
    float sig = 1.f / (1.f + __expf(-acc));
    float v = acc * sig;
    xssm[(size_t)bt * DI + d] = v;
    xssm_h[(size_t)bt * DI + d] = __float2half(v);
}

// ================= chunked smem-staged selective scan (fp16 y output) =================
#define SCH 64
#define NCH (Tlen / SCH)   // 16

__global__ void __launch_bounds__(256) scan2_kernel(
    const float* __restrict__ delta,
    const float* __restrict__ xssm,
    const float* __restrict__ dbl,
    const float* __restrict__ xz,
    const float* __restrict__ A_log,
    const float* __restrict__ Dp,
    __half* __restrict__ y)
{
    __shared__ float sd[2][SCH][16];
    __shared__ float sx[2][SCH][16];
    __shared__ float sz[2][SCH][16];
    __shared__ float sm2[2][SCH][16];
    __shared__ float sbc[2][SCH][32];
    __shared__ float sy[SCH][16];

    int tid = threadIdx.x;
    int b   = blockIdx.x >> 6;
    int dt0 = (blockIdx.x & 63) << 4;

    int s   = tid & 15;
    int grp = tid >> 4;
    int d   = dt0 + grp;

    float A  = -expf(A_log[d * DS + s]);
    float hst = 0.f;

    int lrow = tid >> 2;
    int lq   = (tid & 3) * 4;
    size_t base_row = (size_t)b * Tlen;

    float4 D4 = *(const float4*)(Dp + dt0 + lq);
    float Dc[4] = {D4.x, D4.y, D4.z, D4.w};

    {
        size_t ro = (base_row + lrow);
        cpa16(smem_u32(&sd[0][lrow][lq]), delta + ro * DI + dt0 + lq);
        cpa16(smem_u32(&sx[0][lrow][lq]), xssm + ro * DI + dt0 + lq);
        cpa16(smem_u32(&sz[0][lrow][lq]), xz + ro * (2 * DI) + DI + dt0 + lq);
#pragma unroll
        for (int i = 0; i < 2; i++) {
            int idx = i * 256 + tid;
            int r = idx >> 3, qq = (idx & 7) * 4;
            cpa16(smem_u32(&sbc[0][r][qq]), dbl + (base_row + r) * 64 + 32 + qq);
        }
        asm volatile("cp.async.commit_group;" ::: "memory");
    }

    for (int c = 0; c < NCH; c++) {
        int buf = c & 1;
        if (c + 1 < NCH) {
            int nb = 1 - buf;
            size_t ro = (base_row + (c + 1) * SCH + lrow);
            cpa16(smem_u32(&sd[nb][lrow][lq]), delta + ro * DI + dt0 + lq);
            cpa16(smem_u32(&sx[nb][lrow][lq]), xssm + ro * DI + dt0 + lq);
            cpa16(smem_u32(&sz[nb][lrow][lq]), xz + ro * (2 * DI) + DI + dt0 + lq);
#pragma unroll
            for (int i = 0; i < 2; i++) {
                int idx = i * 256 + tid;
                int r = idx >> 3, qq = (idx & 7) * 4;
                cpa16(smem_u32(&sbc[nb][r][qq]),
                      dbl + (base_row + (c + 1) * SCH + r) * 64 + 32 + qq);
            }
            asm volatile("cp.async.commit_group;" ::: "memory");
            asm volatile("cp.async.wait_group 1;" ::: "memory");
        } else {
            asm volatile("cp.async.wait_group 0;" ::: "memory");
        }
        __syncthreads();

#pragma unroll
        for (int j = 0; j < 4; j++) {
            float dtv = sd[buf][lrow][lq + j];
            float xv  = sx[buf][lrow][lq + j];
            float zv  = sz[buf][lrow][lq + j];
            float szl = zv / (1.f + __expf(-zv));
            sx[buf][lrow][lq + j]  = dtv * xv;
            sz[buf][lrow][lq + j]  = szl;
            sm2[buf][lrow][lq + j] = xv * Dc[j] * szl;
        }
        __syncthreads();

#pragma unroll 4
        for (int tt = 0; tt < SCH; tt++) {
            float dtv = sd[buf][tt][grp];
            float dtx = sx[buf][tt][grp];
            float Bv  = sbc[buf][tt][s];
            float Cv  = sbc[buf][tt][16 + s];
            float dA = __expf(dtv * A);
            hst = fmaf(hst, dA, dtx * Bv);
            float yv = hst * Cv;
            yv += __shfl_xor_sync(0xffffffffu, yv, 8, 32);
            yv += __shfl_xor_sync(0xffffffffu, yv, 4, 32);
            yv += __shfl_xor_sync(0xffffffffu, yv, 2, 32);
            yv += __shfl_xor_sync(0xffffffffu, yv, 1, 32);
            if (s == 0) {
                sy[tt][grp] = fmaf(yv, sz[buf][tt][grp], sm2[buf][tt][grp]);
            }
        }
        __syncthreads();

        {
            size_t ro = (base_row + c * SCH + lrow);
            float4 v = *(const float4*)&sy[lrow][lq];
            __half2 h0 = __floats2half2_rn(v.x, v.y);
            __half2 h1 = __floats2half2_rn(v.z, v.w);
            uint2 u;
            u.x = *(const uint32_t*)&h0;
            u.y = *(const uint32_t*)&h1;
            *(uint2*)(y + ro * DI + dt0 + lq) = u;
        }
    }
}

// ---------------- final FC on last token ----------------
__global__ void fc_kernel(const float* __restrict__ h, const float* __restrict__ fc_w,
                          const float* __restrict__ fc_b, float* __restrict__ out)
{
    int idx = blockIdx.x * blockDim.x + threadIdx.x;
    if (idx >= Bsz * Fdim) return;
    int b = idx / Fdim, f = idx % Fdim;
    const float* hr = h + ((size_t)b * Tlen + (Tlen - 1)) * HID;
    const float* wr = fc_w + (size_t)f * HID;
    float acc = fc_b[f];
    for (int k = 0; k < HID; k += 4) {
        float4 hv = *(const float4*)(hr + k);
        float4 wv = *(const float4*)(wr + k);
        acc += hv.x * wv.x + hv.y * wv.y + hv.z * wv.z + hv.w * wv.w;
    }
    out[idx] = acc;
}

// ---------------- launcher ----------------
extern "C" void kernel_launch(void* const* d_in, const int* in_sizes, int n_in,
                              void* d_out, int out_size)
{
    const float* x        = (const float*)d_in[0];
    const float* ip_w     = (const float*)d_in[1];
    const float* ip_b     = (const float*)d_in[2];
    const float* norm_w   = (const float*)d_in[3];
    const float* inp_w    = (const float*)d_in[4];
    const float* conv_w   = (const float*)d_in[5];
    const float* conv_b   = (const float*)d_in[6];
    const float* xproj_w  = (const float*)d_in[7];
    const float* dtproj_w = (const float*)d_in[8];
    const float* dtproj_b = (const float*)d_in[9];
    const float* A_log    = (const float*)d_in[10];
    const float* Dvec     = (const float*)d_in[11];
    const float* outp_w   = (const float*)d_in[12];
    const float* fc_w     = (const float*)d_in[13];
    const float* fc_b     = (const float*)d_in[14];

    float *h, *xz, *xssm, *dbl, *delta;
    __half *hn_h, *y_h, *wi_h, *wo_h, *xssm_h, *dbl_h, *xpw_h, *dpw_h;
    cudaGetSymbolAddress((void**)&h, g_h);
    cudaGetSymbolAddress((void**)&hn_h, g_hn_h);
    cudaGetSymbolAddress((void**)&xz, g_xz);
    cudaGetSymbolAddress((void**)&xssm, g_xssm);
    cudaGetSymbolAddress((void**)&xssm_h, g_xssm_h);
    cudaGetSymbolAddress((void**)&dbl, g_dbl);
    cudaGetSymbolAddress((void**)&dbl_h, g_dbl_h);
    cudaGetSymbolAddress((void**)&delta, g_delta);
    cudaGetSymbolAddress((void**)&y_h, g_y_h);
    cudaGetSymbolAddress((void**)&wi_h, g_wi_h);
    cudaGetSymbolAddress((void**)&wo_h, g_wo_h);
    cudaGetSymbolAddress((void**)&xpw_h, g_xpw_h);
    cudaGetSymbolAddress((void**)&dpw_h, g_dpw_h);

    static int attr_done = 0;
    if (!attr_done) {
        cudaFuncSetAttribute(gemm_hmma64_kernel<0>, cudaFuncAttributeMaxDynamicSharedMemorySize, H2SMEM_BYTES);
        cudaFuncSetAttribute(gemm_hmma64_kernel<1>, cudaFuncAttributeMaxDynamicSharedMemorySize, H2SMEM_BYTES);
        cudaFuncSetAttribute(gemm_dtproj_kernel, cudaFuncAttributeMaxDynamicSharedMemorySize, HSMEM_BYTES);
        cudaFuncSetAttribute(gemm_xproj_kernel, cudaFuncAttributeMaxDynamicSharedMemorySize, XSMEM_BYTES);
        attr_done = 1;
    }

    // (1) convert ALL weights to fp16 (single launch)
    f2h_all_kernel<<<(N_ALLW + 255) / 256, 256>>>(
        inp_w, outp_w, xproj_w, dtproj_w, wi_h, wo_h, xpw_h, dpw_h);

    // (2) h = scaled_x @ ip_w^T + ip_b
    gemm_tn_kernel<3><<<dim3(HID / BN, MT / BM), 256>>>(
        x, IN_DIM, ip_w, IN_DIM, ip_b, h, HID, MT, HID, IN_DIM);

    // (3) hn = rmsnorm(h) * nw  -> fp16   (layer 0)
    rmsnorm_kernel<<<MT, 128>>>(h, norm_w, hn_h);

    // (4) xz = hn @ inp_w^T  — fp16 mma + ldmatrix   [ncu capture slot]
    gemm_hmma64_kernel<0><<<dim3((2 * DI) / 128, MT / 128), 256, H2SMEM_BYTES>>>(
        hn_h, HID, wi_h, HID, xz, 2 * DI, HID);

    for (int l = 0; l < 2; l++) {
        const float* cw  = conv_w + (size_t)l * DI * 4;
        const float* cb  = conv_b + (size_t)l * DI;
        const float* dpb = dtproj_b + (size_t)l * DI;
        const float* Al  = A_log + (size_t)l * DI * DS;
        const float* Dl  = Dvec + (size_t)l * DI;
        const __half* wol  = wo_h + (size_t)l * HID * DI;
        const __half* xpwl = xpw_h + (size_t)l * 64 * DI;
        const __half* dpwl = dpw_h + (size_t)l * DI * DTR;

        if (l > 0) {
            rmsnorm_kernel<<<MT, 128>>>(h, norm_w + l * HID, hn_h);
            gemm_hmma64_kernel<0><<<dim3((2 * DI) / 128, MT / 128), 256, H2SMEM_BYTES>>>(
                hn_h, HID, wi_h + (size_t)l * 2 * DI * HID, HID, xz, 2 * DI, HID);
        }

        // depthwise conv + silu -> xssm (fp32 + fp16)
        conv_silu_kernel<<<(MT * DI) / 256, 256>>>(xz, cw, cb, xssm, xssm_h);

        // dbl = xssm @ xproj_w^T  — fp16 mma, dual output
        gemm_xproj_kernel<<<dim3(1, MT / 64), 128, XSMEM_BYTES>>>(
            xssm_h, DI, xpwl, DI, dbl, dbl_h, 64, DI);

        // delta = softplus(dt_raw @ dtproj_w^T + dtproj_b)  (K=32) — fp16 mma
        gemm_dtproj_kernel<<<dim3(DI / 128, MT / 128), 256, HSMEM_BYTES>>>(
            dbl_h, 64, dpwl, DTR, dpb, delta, DI);

        // chunked selective scan -> y (fp16)
        scan2_kernel<<<Bsz * (DI / 16), 256>>>(delta, xssm, dbl, xz, Al, Dl, y_h);

        // h += y @ outp_w^T  — fp16 mma + ldmatrix, residual add
        gemm_hmma64_kernel<1><<<dim3(HID / 128, MT / 128), 256, H2SMEM_BYTES>>>(
            y_h, DI, wol, DI, h, HID, DI);
    }

    // out = h[:, -1, :] @ fc_w^T + fc_b
    fc_kernel<<<3, 256>>>(h, fc_w, fc_b, (float*)d_out);
}

// round 14
// speedup vs baseline: 4.5015x; 1.0226x over previous
#include <cuda_runtime.h>
#include <cuda_bf16.h>
#include <cuda_fp16.h>
#include <math.h>
#include <stdint.h>

// Problem constants
#define Bsz 8
#define Tlen 1024
#define IN_DIM 32
#define HID 512
#define DI 1024
#define DS 16
#define DTR 32
#define Fdim 96
#define MT (Bsz * Tlen)   // 8192 rows

// ---------------- scratch (device globals; no runtime allocation) ----------------
__device__ float g_h[MT * HID];
__device__ __half g_hn_h[MT * HID];
__device__ __half g_xz_h[MT * 2 * DI];     // fp16 xz (x | z)
__device__ __half g_xssm_h[MT * DI];
__device__ float g_dbl[MT * 64];
__device__ __half g_dbl_h[MT * 64];
__device__ float g_delta[MT * DI];
__device__ __half g_y_h[MT * DI];
__device__ __half g_wi_h[2 * 2 * DI * HID];
__device__ __half g_wo_h[2 * HID * DI];
__device__ __half g_xpw_h[2 * 64 * DI];
__device__ __half g_dpw_h[2 * DI * DTR];

__device__ __forceinline__ uint32_t smem_u32(const void* p) {
    uint32_t a;
    asm("{ .reg .u64 t; cvta.to.shared.u64 t, %1; cvt.u32.u64 %0, t; }" : "=r"(a) : "l"(p));
    return a;
}

__device__ __forceinline__ void cpa16(uint32_t saddr, const void* gaddr) {
    asm volatile("cp.async.cg.shared.global [%0], [%1], 16;" :: "r"(saddr), "l"(gaddr));
}

// ---------------- fused fp32 -> fp16 conversion of all 4 weight groups ----------------
#define N_WI (2 * 2 * DI * HID)
#define N_WO (2 * HID * DI)
#define N_XPW (2 * 64 * DI)
#define N_DPW (2 * DI * DTR)
#define N_ALLW (N_WI + N_WO + N_XPW + N_DPW)

__global__ void f2h_all_kernel(const float* __restrict__ wi, const float* __restrict__ wo,
                               const float* __restrict__ xpw, const float* __restrict__ dpw,
                               __half* __restrict__ wi_h, __half* __restrict__ wo_h,
                               __half* __restrict__ xpw_h, __half* __restrict__ dpw_h) {
    int i = blockIdx.x * blockDim.x + threadIdx.x;
    if (i < N_WI) { wi_h[i] = __float2half(wi[i]); return; }
    i -= N_WI;
    if (i < N_WO) { wo_h[i] = __float2half(wo[i]); return; }
    i -= N_WO;
    if (i < N_XPW) { xpw_h[i] = __float2half(xpw[i]); return; }
    i -= N_XPW;
    if (i < N_DPW) { dpw_h[i] = __float2half(dpw[i]); }
}

__device__ __forceinline__ void mma16(float* d, const uint32_t* a, const uint32_t* b) {
    asm volatile(
        "mma.sync.aligned.m16n8k16.row.col.f32.f16.f16.f32 "
        "{%0,%1,%2,%3}, {%4,%5,%6,%7}, {%8,%9}, {%0,%1,%2,%3};"
        : "+f"(d[0]), "+f"(d[1]), "+f"(d[2]), "+f"(d[3])
        : "r"(a[0]), "r"(a[1]), "r"(a[2]), "r"(a[3]), "r"(b[0]), "r"(b[1]));
}

__device__ __forceinline__ void ldsm4(uint32_t& r0, uint32_t& r1, uint32_t& r2, uint32_t& r3,
                                      uint32_t addr) {
    asm volatile("ldmatrix.sync.aligned.m8n8.x4.shared.b16 {%0,%1,%2,%3}, [%4];"
                 : "=r"(r0), "=r"(r1), "=r"(r2), "=r"(r3) : "r"(addr));
}

// ================= main fp16 GEMM (ldmatrix + K-chunk 64) ==========================
// C[m,n] = sum_k A[m,k]*B[n,k].  CTA tile 128x128x64, 256 threads = 8 warps (2m x 4n),
// warp tile 64x32, m16n8k16, 3-stage cp.async.
// MODE 0: fp16 output to Ch ; MODE 1: fp32 residual add into C.

#define H2PAD 72
#define H2TILE (128 * H2PAD)
#define H2STAGE (2 * H2TILE)
#define H2NSTAGE 3
#define H2SMEM_BYTES (H2NSTAGE * H2STAGE * 2)   // 110592 B

__device__ __forceinline__ void load_tile64(const __half* __restrict__ g, int ld,
                                            int row0, int k0, __half* s, int tid) {
#pragma unroll
    for (int i = 0; i < 4; i++) {
        int flat = i * 256 + tid;
        int r = flat >> 3;
        int c = flat & 7;
        const __half* gp = g + (size_t)(row0 + r) * ld + k0 + c * 8;
        cpa16(smem_u32(s + r * H2PAD + c * 8), gp);
    }
}

template<int MODE>
__global__ void __launch_bounds__(256)
gemm_hmma64_kernel(const __half* __restrict__ A, int lda,
                   const __half* __restrict__ B, int ldb,
                   float* __restrict__ C, __half* __restrict__ Ch, int ldc, int K)
{
    extern __shared__ __half smh[];
    int tid = threadIdx.x;
    int wid = tid >> 5, lane = tid & 31;
    int g = lane >> 2, t = lane & 3;
    int warp_m = wid >> 2;
    int warp_n = wid & 3;
    int bm = blockIdx.y * 128;
    int bn = blockIdx.x * 128;

    int q = lane >> 3, i = lane & 7;
    int lrow = ((q & 1) << 3) + i;
    int lcol = (q >> 1) << 3;

    float acc[4][4][4];
#pragma unroll
    for (int mt = 0; mt < 4; mt++)
#pragma unroll
        for (int nt = 0; nt < 4; nt++)
#pragma unroll
            for (int qq = 0; qq < 4; qq++) acc[mt][nt][qq] = 0.f;

    int nk = K >> 6;

    load_tile64(A, lda, bm, 0, smh, tid);
    load_tile64(B, ldb, bn, 0, smh + H2TILE, tid);
    asm volatile("cp.async.commit_group;" ::: "memory");
    if (nk > 1) {
        load_tile64(A, lda, bm, 64, smh + H2STAGE, tid);
        load_tile64(B, ldb, bn, 64, smh + H2STAGE + H2TILE, tid);
        asm volatile("cp.async.commit_group;" ::: "memory");
    }

    for (int kc = 0; kc < nk; kc++) {
        if (kc + 2 < nk) {
            int nb = (kc + 2) % H2NSTAGE;
            load_tile64(A, lda, bm, (kc + 2) * 64, smh + nb * H2STAGE, tid);
            load_tile64(B, ldb, bn, (kc + 2) * 64, smh + nb * H2STAGE + H2TILE, tid);
            asm volatile("cp.async.commit_group;" ::: "memory");
            asm volatile("cp.async.wait_group 2;" ::: "memory");
        } else if (kc + 1 < nk) {
            asm volatile("cp.async.wait_group 1;" ::: "memory");
        } else {
            asm volatile("cp.async.wait_group 0;" ::: "memory");
        }
        __syncthreads();

        const __half* sA = smh + (kc % H2NSTAGE) * H2STAGE;
        const __half* sB = sA + H2TILE;

        uint32_t aAddr[4], bAddr[2];
#pragma unroll
        for (int mt = 0; mt < 4; mt++)
            aAddr[mt] = smem_u32(&sA[(warp_m * 64 + mt * 16 + lrow) * H2PAD + lcol]);
#pragma unroll
        for (int p = 0; p < 2; p++)
            bAddr[p] = smem_u32(&sB[(warp_n * 32 + p * 16 + lrow) * H2PAD + lcol]);

#pragma unroll
        for (int kk = 0; kk < 64; kk += 16) {
            uint32_t afr[4][4];
#pragma unroll
            for (int mt = 0; mt < 4; mt++)
                ldsm4(afr[mt][0], afr[mt][1], afr[mt][2], afr[mt][3], aAddr[mt] + kk * 2);
            uint32_t bfr[4][2];
#pragma unroll
            for (int p = 0; p < 2; p++) {
                uint32_t r0, r1, r2, r3;
                ldsm4(r0, r1, r2, r3, bAddr[p] + kk * 2);
                bfr[2 * p][0] = r0; bfr[2 * p + 1][0] = r1;
                bfr[2 * p][1] = r2; bfr[2 * p + 1][1] = r3;
            }
#pragma unroll
            for (int mt = 0; mt < 4; mt++)
#pragma unroll
                for (int nt = 0; nt < 4; nt++)
                    mma16(acc[mt][nt], afr[mt], bfr[nt]);
        }
        __syncthreads();
    }

#pragma unroll
    for (int mt = 0; mt < 4; mt++) {
        int row = bm + warp_m * 64 + mt * 16 + g;
#pragma unroll
        for (int nt = 0; nt < 4; nt++) {
            int col = bn + warp_n * 32 + nt * 8 + t * 2;
            if (MODE == 0) {
                __half2 h0 = __floats2half2_rn(acc[mt][nt][0], acc[mt][nt][1]);
                __half2 h1 = __floats2half2_rn(acc[mt][nt][2], acc[mt][nt][3]);
                *(__half2*)(Ch + (size_t)row * ldc + col) = h0;
                *(__half2*)(Ch + (size_t)(row + 8) * ldc + col) = h1;
            } else {
                float* c0 = C + (size_t)row * ldc + col;
                float* c1 = C + (size_t)(row + 8) * ldc + col;
                float2 o0 = *(const float2*)c0;
                float2 o1 = *(const float2*)c1;
                *(float2*)c0 = make_float2(acc[mt][nt][0] + o0.x, acc[mt][nt][1] + o0.y);
                *(float2*)c1 = make_float2(acc[mt][nt][2] + o1.x, acc[mt][nt][3] + o1.y);
            }
        }
    }
}

// ================= dtproj fp16 GEMM (K=32, softplus epilogue) =======================
#define HPAD 40
#define HTILE (128 * HPAD)
#define HSTAGE (2 * HTILE)
#define HSMEM_BYTES (2 * HSTAGE * 2)

__device__ __forceinline__ void load_tileH(const __half* __restrict__ g, int ld,
                                           int row0, int k0, __half* s, int tid) {
#pragma unroll
    for (int i = 0; i < 2; i++) {
        int flat = i * 256 + tid;
        int r = flat >> 2;
        int c = flat & 3;
        const __half* gp = g + (size_t)(row0 + r) * ld + k0 + c * 8;
        cpa16(smem_u32(s + r * HPAD + c * 8), gp);
    }
}

__global__ void __launch_bounds__(256)
gemm_dtproj_kernel(const __half* __restrict__ A, int lda,
                   const __half* __restrict__ B, int ldb,
                   const float* __restrict__ bias,
                   float* __restrict__ C, int ldc)
{
    extern __shared__ __half smh[];
    int tid = threadIdx.x;
    int wid = tid >> 5, lane = tid & 31;
    int g = lane >> 2, t = lane & 3;
    int warp_m = wid >> 2;
    int warp_n = wid & 3;
    int bm = blockIdx.y * 128;
    int bn = blockIdx.x * 128;

    float acc[4][4][4];
#pragma unroll
    for (int mt = 0; mt < 4; mt++)
#pragma unroll
        for (int nt = 0; nt < 4; nt++)
#pragma unroll
            for (int qq = 0; qq < 4; qq++) acc[mt][nt][qq] = 0.f;

    load_tileH(A, lda, bm, 0, smh, tid);
    load_tileH(B, ldb, bn, 0, smh + HTILE, tid);
    asm volatile("cp.async.commit_group;" ::: "memory");
    asm volatile("cp.async.wait_group 0;" ::: "memory");
    __syncthreads();

    const __half* sA = smh;
    const __half* sB = sA + HTILE;

#pragma unroll
    for (int kk = 0; kk < 32; kk += 16) {
        uint32_t afr[4][4];
#pragma unroll
        for (int mt = 0; mt < 4; mt++) {
            int r0 = warp_m * 64 + mt * 16;
            afr[mt][0] = *(const uint32_t*)&sA[(r0 + g) * HPAD + kk + 2 * t];
            afr[mt][1] = *(const uint32_t*)&sA[(r0 + 8 + g) * HPAD + kk + 2 * t];
            afr[mt][2] = *(const uint32_t*)&sA[(r0 + g) * HPAD + kk + 2 * t + 8];
            afr[mt][3] = *(const uint32_t*)&sA[(r0 + 8 + g) * HPAD + kk + 2 * t + 8];
        }
        uint32_t bfr[4][2];
#pragma unroll
        for (int nt = 0; nt < 4; nt++) {
            int n0 = warp_n * 32 + nt * 8;
            bfr[nt][0] = *(const uint32_t*)&sB[(n0 + g) * HPAD + kk + 2 * t];
            bfr[nt][1] = *(const uint32_t*)&sB[(n0 + g) * HPAD + kk + 2 * t + 8];
        }
#pragma unroll
        for (int mt = 0; mt < 4; mt++)
#pragma unroll
            for (int nt = 0; nt < 4; nt++)
                mma16(acc[mt][nt], afr[mt], bfr[nt]);
    }

#pragma unroll
    for (int mt = 0; mt < 4; mt++) {
        int row = bm + warp_m * 64 + mt * 16 + g;
#pragma unroll
        for (int nt = 0; nt < 4; nt++) {
            int col = bn + warp_n * 32 + nt * 8 + t * 2;
            float b0 = bias[col], b1 = bias[col + 1];
            float2 v0 = make_float2(acc[mt][nt][0] + b0, acc[mt][nt][1] + b1);
            float2 v1 = make_float2(acc[mt][nt][2] + b0, acc[mt][nt][3] + b1);
            v0.x = fmaxf(v0.x, 0.f) + log1pf(expf(-fabsf(v0.x)));
            v0.y = fmaxf(v0.y, 0.f) + log1pf(expf(-fabsf(v0.y)));
            v1.x = fmaxf(v1.x, 0.f) + log1pf(expf(-fabsf(v1.x)));
            v1.y = fmaxf(v1.y, 0.f) + log1pf(expf(-fabsf(v1.y)));
            *(float2*)(C + (size_t)row * ldc + col) = v0;
            *(float2*)(C + (size_t)(row + 8) * ldc + col) = v1;
        }
    }
}

// ================= xproj fp16 GEMM: 64x64 CTA tile, dual fp32+fp16 output ==========
#define XTILE (64 * HPAD)
#define XSTAGE (2 * XTILE)
#define XNSTAGE 3
#define XSMEM_BYTES (XNSTAGE * XSTAGE * 2)

__device__ __forceinline__ void load_tileH64(const __half* __restrict__ g, int ld,
                                             int row0, int k0, __half* s, int tid) {
#pragma unroll
    for (int i = 0; i < 2; i++) {
        int flat = i * 128 + tid;
        int r = flat >> 2;
        int c = flat & 3;
        const __half* gp = g + (size_t)(row0 + r) * ld + k0 + c * 8;
        cpa16(smem_u32(s + r * HPAD + c * 8), gp);
    }
}

__global__ void __launch_bounds__(128)
gemm_xproj_kernel(const __half* __restrict__ A, int lda,
                  const __half* __restrict__ B, int ldb,
                  float* __restrict__ C, __half* __restrict__ Ch, int ldc, int K)
{
    extern __shared__ __half smh[];
    int tid = threadIdx.x;
    int wid = tid >> 5, lane = tid & 31;
    int g = lane >> 2, t = lane & 3;
    int warp_m = wid >> 1;
    int warp_n = wid & 1;
    int bm = blockIdx.y * 64;
    int bn = 0;

    float acc[2][4][4];
#pragma unroll
    for (int mt = 0; mt < 2; mt++)
#pragma unroll
        for (int nt = 0; nt < 4; nt++)
#pragma unroll
            for (int qq = 0; qq < 4; qq++) acc[mt][nt][qq] = 0.f;

    int nk = K >> 5;

    load_tileH64(A, lda, bm, 0, smh, tid);
    load_tileH64(B, ldb, bn, 0, smh + XTILE, tid);
    asm volatile("cp.async.commit_group;" ::: "memory");
    load_tileH64(A, lda, bm, 32, smh + XSTAGE, tid);
    load_tileH64(B, ldb, bn, 32, smh + XSTAGE + XTILE, tid);
    asm volatile("cp.async.commit_group;" ::: "memory");

    for (int kc = 0; kc < nk; kc++) {
        if (kc + 2 < nk) {
            int nb = (kc + 2) % XNSTAGE;
            load_tileH64(A, lda, bm, (kc + 2) * 32, smh + nb * XSTAGE, tid);
            load_tileH64(B, ldb, bn, (kc + 2) * 32, smh + nb * XSTAGE + XTILE, tid);
            asm volatile("cp.async.commit_group;" ::: "memory");
            asm volatile("cp.async.wait_group 2;" ::: "memory");
        } else if (kc + 1 < nk) {
            asm volatile("cp.async.wait_group 1;" ::: "memory");
        } else {
            asm volatile("cp.async.wait_group 0;" ::: "memory");
        }
        __syncthreads();

        const __half* sA = smh + (kc % XNSTAGE) * XSTAGE;
        const __half* sB = sA + XTILE;

#pragma unroll
        for (int kk = 0; kk < 32; kk += 16) {
            uint32_t afr[2][4];
#pragma unroll
            for (int mt = 0; mt < 2; mt++) {
                int r0 = warp_m * 32 + mt * 16;
                afr[mt][0] = *(const uint32_t*)&sA[(r0 + g) * HPAD + kk + 2 * t];
                afr[mt][1] = *(const uint32_t*)&sA[(r0 + 8 + g) * HPAD + kk + 2 * t];
                afr[mt][2] = *(const uint32_t*)&sA[(r0 + g) * HPAD + kk + 2 * t + 8];
                afr[mt][3] = *(const uint32_t*)&sA[(r0 + 8 + g) * HPAD + kk + 2 * t + 8];
            }
            uint32_t bfr[4][2];
#pragma unroll
            for (int nt = 0; nt < 4; nt++) {
                int n0 = warp_n * 32 + nt * 8;
                bfr[nt][0] = *(const uint32_t*)&sB[(n0 + g) * HPAD + kk + 2 * t];
                bfr[nt][1] = *(const uint32_t*)&sB[(n0 + g) * HPAD + kk + 2 * t + 8];
            }
#pragma unroll
            for (int mt = 0; mt < 2; mt++)
#pragma unroll
                for (int nt = 0; nt < 4; nt++)
                    mma16(acc[mt][nt], afr[mt], bfr[nt]);
        }
        __syncthreads();
    }

#pragma unroll
    for (int mt = 0; mt < 2; mt++) {
        int row = bm + warp_m * 32 + mt * 16 + g;
#pragma unroll
        for (int nt = 0; nt < 4; nt++) {
            int col = warp_n * 32 + nt * 8 + t * 2;
            *(float2*)(C + (size_t)row * ldc + col) = make_float2(acc[mt][nt][0], acc[mt][nt][1]);
            *(float2*)(C + (size_t)(row + 8) * ldc + col) = make_float2(acc[mt][nt][2], acc[mt][nt][3]);
            __half2 h0 = __floats2half2_rn(acc[mt][nt][0], acc[mt][nt][1]);
            __half2 h1 = __floats2half2_rn(acc[mt][nt][2], acc[mt][nt][3]);
            *(__half2*)(Ch + (size_t)row * ldc + col) = h0;
            *(__half2*)(Ch + (size_t)(row + 8) * ldc + col) = h1;
        }
    }
}

// ---------------- generic tiled SGEMM (ip GEMM only) ----------------
#define BM 64
#define BN 64
#define BKK 16

template<int MODE>
__global__ void __launch_bounds__(256) gemm_tn_kernel(
    const float* __restrict__ A, int lda,
    const float* __restrict__ Bw, int ldb,
    const float* __restrict__ bias,
    float* __restrict__ C, int ldc,
    int M, int N, int K)
{
    __shared__ float As[BKK][BM + 4];
    __shared__ float Bs[BKK][BN + 4];

    int tid = threadIdx.x;
    int bm = blockIdx.y * BM;
    int bn = blockIdx.x * BN;

    int lrow = tid >> 2;
    int lk   = (tid & 3) * 4;
    int tr = (tid >> 4) * 4;
    int tc = (tid & 15) * 4;

    float acc[4][4];
#pragma unroll
    for (int i = 0; i < 4; i++)
#pragma unroll
        for (int j = 0; j < 4; j++) acc[i][j] = 0.f;

    const float* Aptr = A + (size_t)(bm + lrow) * lda + lk;
    const float* Bptr = Bw + (size_t)(bn + lrow) * ldb + lk;

    for (int k0 = 0; k0 < K; k0 += BKK) {
        float4 av = *(const float4*)Aptr;
        float4 bv = *(const float4*)Bptr;
        if (MODE == 3 && k0 == 0 && lk == 0) {
            av.x *= 0.3f; av.y *= 0.5f; av.z *= 0.9f;
        }
        Aptr += BKK;
        Bptr += BKK;
        As[lk + 0][lrow] = av.x; As[lk + 1][lrow] = av.y;
        As[lk + 2][lrow] = av.z; As[lk + 3][lrow] = av.w;
        Bs[lk + 0][lrow] = bv.x; Bs[lk + 1][lrow] = bv.y;
        Bs[lk + 2][lrow] = bv.z; Bs[lk + 3][lrow] = bv.w;
        __syncthreads();
#pragma unroll
        for (int k = 0; k < BKK; ++k) {
            float4 a4 = *(const float4*)&As[k][tr];
            float4 b4 = *(const float4*)&Bs[k][tc];
            float ar[4] = {a4.x, a4.y, a4.z, a4.w};
            float br[4] = {b4.x, b4.y, b4.z, b4.w};
#pragma unroll
            for (int i = 0; i < 4; ++i)
#pragma unroll
                for (int j = 0; j < 4; ++j)
                    acc[i][j] = fmaf(ar[i], br[j], acc[i][j]);
        }
        __syncthreads();
    }

#pragma unroll
    for (int i = 0; i < 4; ++i) {
        float* Cp = C + (size_t)(bm + tr + i) * ldc + (bn + tc);
        float vals[4];
#pragma unroll
        for (int j = 0; j < 4; ++j) {
            float v = acc[i][j];
            if (bias) v += bias[bn + tc + j];
            vals[j] = v;
        }
        float4 r; r.x = vals[0]; r.y = vals[1]; r.z = vals[2]; r.w = vals[3];
        *(float4*)Cp = r;
    }
}

// ---------------- rmsnorm -> fp16 output for MMA ----------------
__global__ void __launch_bounds__(128) rmsnorm_kernel(
    const float* __restrict__ h, const float* __restrict__ w, __half* __restrict__ out)
{
    int row = blockIdx.x;
    const float* hr = h + (size_t)row * HID;
    float v[4];
    float ss = 0.f;
#pragma unroll
    for (int i = 0; i < 4; i++) {
        v[i] = hr[threadIdx.x + i * 128];
        ss += v[i] * v[i];
    }
#pragma unroll
    for (int o = 16; o; o >>= 1) ss += __shfl_xor_sync(0xffffffffu, ss, o);
    __shared__ float red[4];
    if ((threadIdx.x & 31) == 0) red[threadIdx.x >> 5] = ss;
    __syncthreads();
    float tot = red[0] + red[1] + red[2] + red[3];
    float sc = rsqrtf(tot * (1.f / (float)HID) + 1e-5f);
#pragma unroll
    for (int i = 0; i < 4; i++) {
        int c = threadIdx.x + i * 128;
        out[(size_t)row * HID + c] = __float2half(v[i] * sc * w[c]);
    }
}

// ---------------- depthwise causal conv (K=4) + bias + silu, fp16 in/out ----------
__global__ void conv_silu_kernel(const __half* __restrict__ xz,
                                 const float* __restrict__ cw,
                                 const float* __restrict__ cb,
                                 __half* __restrict__ xssm_h)
{
    int idx = blockIdx.x * blockDim.x + threadIdx.x;
    int d = idx & (DI - 1);
    int bt = idx >> 10;
    int t = bt & (Tlen - 1);
    float w0 = cw[d * 4 + 0], w1 = cw[d * 4 + 1], w2 = cw[d * 4 + 2], w3 = cw[d * 4 + 3];
    const __half* col = xz + (size_t)bt * (2 * DI) + d;
    float acc = cb[d] + w3 * __half2float(col[0]);
    if (t >= 1) acc += w2 * __half2float(col[-(2 * DI)]);
    if (t >= 2) acc += w1 * __half2float(col[-(4 * DI)]);
    if (t >= 3) acc += w0 * __half2float(col[-(6 * DI)]);
    float sig = 1.f / (1.f + __expf(-acc));
    xssm_h[(size_t)bt * DI + d] = __float2half(acc * sig);
}

// ================= chunked smem-staged selective scan (fp16 x/z in, fp16 y out) ======
#define SCH 64
#define NCH (Tlen / SCH)   // 16

__global__ void __launch_bounds__(256) scan2_kernel(
    const float* __restrict__ delta,
    const __half* __restrict__ xssm_h,
    const float* __restrict__ dbl,
    const __half* __restrict__ xz_h,
    const float* __restrict__ A_log,
    const float* __restrict__ Dp,
    __half* __restrict__ y)
{
    __shared__ float sd[2][SCH][16];     // delta (fp32)
    __shared__ __half sxh[2][SCH][16];   // x (fp16)
    __shared__ __half szh[2][SCH][16];   // z (fp16)
    __shared__ float sbc[2][SCH][32];    // B | C (fp32)
    __shared__ float sx32[SCH][16];      // dt*x
    __shared__ float sz32[SCH][16];      // silu(z)
    __shared__ float sm2[SCH][16];       // x*D*silu(z)
    __shared__ float sy[SCH][16];

    int tid = threadIdx.x;
    int b   = blockIdx.x >> 6;
    int dt0 = (blockIdx.x & 63) << 4;

    int s   = tid & 15;
    int grp = tid >> 4;
    int d   = dt0 + grp;

    float A  = -expf(A_log[d * DS + s]);
    float hst = 0.f;

    int lrow = tid >> 2;           // 0..63 (float tile loads)
    int lq   = (tid & 3) * 4;
    int hr2  = tid >> 1;           // 0..127 (half tile loads, threads < 128)
    int hc2  = (tid & 1) * 8;
    size_t base_row = (size_t)b * Tlen;

    float4 D4 = *(const float4*)(Dp + dt0 + lq);
    float Dc[4] = {D4.x, D4.y, D4.z, D4.w};

    {
        size_t ro = (base_row + lrow);
        cpa16(smem_u32(&sd[0][lrow][lq]), delta + ro * DI + dt0 + lq);
        if (tid < 128) {
            size_t rh = base_row + hr2;
            cpa16(smem_u32(&sxh[0][hr2][hc2]), xssm_h + rh * DI + dt0 + hc2);
            cpa16(smem_u32(&szh[0][hr2][hc2]), xz_h + rh * (2 * DI) + DI + dt0 + hc2);
        }
#pragma unroll
        for (int i = 0; i < 2; i++) {
            int idx = i * 256 + tid;
            int r = idx >> 3, qq = (idx & 7) * 4;
            cpa16(smem_u32(&sbc[0][r][qq]), dbl + (base_row + r) * 64 + 32 + qq);
        }
        asm volatile("cp.async.commit_group;" ::: "memory");
    }

    for (int c = 0; c < NCH; c++) {
        int buf = c & 1;
        if (c + 1 < NCH) {
            int nb = 1 - buf;
            size_t ro = (base_row + (c + 1) * SCH + lrow);
            cpa16(smem_u32(&sd[nb][lrow][lq]), delta + ro * DI + dt0 + lq);
            if (tid < 128) {
                size_t rh = base_row + (c + 1) * SCH + hr2;
                cpa16(smem_u32(&sxh[nb][hr2][hc2]), xssm_h + rh * DI + dt0 + hc2);
                cpa16(smem_u32(&szh[nb][hr2][hc2]), xz_h + rh * (2 * DI) + DI + dt0 + hc2);
            }
#pragma unroll
            for (int i = 0; i < 2; i++) {
                int idx = i * 256 + tid;
                int r = idx >> 3, qq = (idx & 7) * 4;
                cpa16(smem_u32(&sbc[nb][r][qq]),
                      dbl + (base_row + (c + 1) * SCH + r) * 64 + 32 + qq);
            }
            asm volatile("cp.async.commit_group;" ::: "memory");
            asm volatile("cp.async.wait_group 1;" ::: "memory");
        } else {
            asm volatile("cp.async.wait_group 0;" ::: "memory");
        }
        __syncthreads();

        // precompute: sx32 <- dt*x ; sz32 <- silu(z) ; sm2 <- x*D*silu(z)
#pragma unroll
        for (int j = 0; j < 4; j++) {
            float dtv = sd[buf][lrow][lq + j];
            float xv  = __half2float(sxh[buf][lrow][lq + j]);
            float zv  = __half2float(szh[buf][lrow][lq + j]);
            float szl = zv / (1.f + __expf(-zv));
            sx32[lrow][lq + j] = dtv * xv;
            sz32[lrow][lq + j] = szl;
            sm2[lrow][lq + j]  = xv * Dc[j] * szl;
        }
        __syncthreads();

#pragma unroll 4
        for (int tt = 0; tt < SCH; tt++) {
            float dtv = sd[buf][tt][grp];
            float dtx = sx32[tt][grp];
            float Bv  = sbc[buf][tt][s];
            float Cv  = sbc[buf][tt][16 + s];
            float dA = __expf(dtv * A);
            hst = fmaf(hst, dA, dtx * Bv);
            float yv = hst * Cv;
            yv += __shfl_xor_sync(0xffffffffu, yv, 8, 32);
            yv += __shfl_xor_sync(0xffffffffu, yv, 4, 32);
            yv += __shfl_xor_sync(0xffffffffu, yv, 2, 32);
            yv += __shfl_xor_sync(0xffffffffu, yv, 1, 32);
            if (s == 0) {
                sy[tt][grp] = fmaf(yv, sz32[tt][grp], sm2[tt][grp]);
            }
        }
        __syncthreads();

        {
            size_t ro = (base_row + c * SCH + lrow);
            float4 v = *(const float4*)&sy[lrow][lq];
            __half2 h0 = __floats2half2_rn(v.x, v.y);
            __half2 h1 = __floats2half2_rn(v.z, v.w);
            uint2 u;
            u.x = *(const uint32_t*)&h0;
            u.y = *(const uint32_t*)&h1;
            *(uint2*)(y + ro * DI + dt0 + lq) = u;
        }
        __syncthreads();   // protect sx32/sz32/sm2/sy before next chunk's precompute
    }
}

// ---------------- final FC on last token ----------------
__global__ void fc_kernel(const float* __restrict__ h, const float* __restrict__ fc_w,
                          const float* __restrict__ fc_b, float* __restrict__ out)
{
    int idx = blockIdx.x * blockDim.x + threadIdx.x;
    if (idx >= Bsz * Fdim) return;
    int b = idx / Fdim, f = idx % Fdim;
    const float* hr = h + ((size_t)b * Tlen + (Tlen - 1)) * HID;
    const float* wr = fc_w + (size_t)f * HID;
    float acc = fc_b[f];
    for (int k = 0; k < HID; k += 4) {
        float4 hv = *(const float4*)(hr + k);
        float4 wv = *(const float4*)(wr + k);
        acc += hv.x * wv.x + hv.y * wv.y + hv.z * wv.z + hv.w * wv.w;
    }
    out[idx] = acc;
}

// ---------------- launcher ----------------
extern "C" void kernel_launch(void* const* d_in, const int* in_sizes, int n_in,
                              void* d_out, int out_size)
{
    const float* x        = (const float*)d_in[0];
    const float* ip_w     = (const float*)d_in[1];
    const float* ip_b     = (const float*)d_in[2];
    const float* norm_w   = (const float*)d_in[3];
    const float* inp_w    = (const float*)d_in[4];
    const float* conv_w   = (const float*)d_in[5];
    const float* conv_b   = (const float*)d_in[6];
    const float* xproj_w  = (const float*)d_in[7];
    const float* dtproj_w = (const float*)d_in[8];
    const float* dtproj_b = (const float*)d_in[9];
    const float* A_log    = (const float*)d_in[10];
    const float* Dvec     = (const float*)d_in[11];
    const float* outp_w   = (const float*)d_in[12];
    const float* fc_w     = (const float*)d_in[13];
    const float* fc_b     = (const float*)d_in[14];

    float *h, *dbl, *delta;
    __half *hn_h, *y_h, *wi_h, *wo_h, *xz_h, *xssm_h, *dbl_h, *xpw_h, *dpw_h;
    cudaGetSymbolAddress((void**)&h, g_h);
    cudaGetSymbolAddress((void**)&hn_h, g_hn_h);
    cudaGetSymbolAddress((void**)&xz_h, g_xz_h);
    cudaGetSymbolAddress((void**)&xssm_h, g_xssm_h);
    cudaGetSymbolAddress((void**)&dbl, g_dbl);
    cudaGetSymbolAddress((void**)&dbl_h, g_dbl_h);
    cudaGetSymbolAddress((void**)&delta, g_delta);
    cudaGetSymbolAddress((void**)&y_h, g_y_h);
    cudaGetSymbolAddress((void**)&wi_h, g_wi_h);
    cudaGetSymbolAddress((void**)&wo_h, g_wo_h);
    cudaGetSymbolAddress((void**)&xpw_h, g_xpw_h);
    cudaGetSymbolAddress((void**)&dpw_h, g_dpw_h);

    static int attr_done = 0;
    if (!attr_done) {
        cudaFuncSetAttribute(gemm_hmma64_kernel<0>, cudaFuncAttributeMaxDynamicSharedMemorySize, H2SMEM_BYTES);
        cudaFuncSetAttribute(gemm_hmma64_kernel<1>, cudaFuncAttributeMaxDynamicSharedMemorySize, H2SMEM_BYTES);
        cudaFuncSetAttribute(gemm_dtproj_kernel, cudaFuncAttributeMaxDynamicSharedMemorySize, HSMEM_BYTES);
        cudaFuncSetAttribute(gemm_xproj_kernel, cudaFuncAttributeMaxDynamicSharedMemorySize, XSMEM_BYTES);
        attr_done = 1;
    }

    // (1) convert ALL weights to fp16 (single launch)
    f2h_all_kernel<<<(N_ALLW + 255) / 256, 256>>>(
        inp_w, outp_w, xproj_w, dtproj_w, wi_h, wo_h, xpw_h, dpw_h);

    // (2) h = scaled_x @ ip_w^T + ip_b
    gemm_tn_kernel<3><<<dim3(HID / BN, MT / BM), 256>>>(
        x, IN_DIM, ip_w, IN_DIM, ip_b, h, HID, MT, HID, IN_DIM);

    // (3) hn = rmsnorm(h) * nw  -> fp16   (layer 0)
    rmsnorm_kernel<<<MT, 128>>>(h, norm_w, hn_h);

    // (4) xz = hn @ inp_w^T  — fp16 mma, fp16 output   [ncu capture slot]
    gemm_hmma64_kernel<0><<<dim3((2 * DI) / 128, MT / 128), 256, H2SMEM_BYTES>>>(
        hn_h, HID, wi_h, HID, nullptr, xz_h, 2 * DI, HID);

    for (int l = 0; l < 2; l++) {
        const float* cw  = conv_w + (size_t)l * DI * 4;
        const float* cb  = conv_b + (size_t)l * DI;
        const float* dpb = dtproj_b + (size_t)l * DI;
        const float* Al  = A_log + (size_t)l * DI * DS;
        const float* Dl  = Dvec + (size_t)l * DI;
        const __half* wol  = wo_h + (size_t)l * HID * DI;
        const __half* xpwl = xpw_h + (size_t)l * 64 * DI;
        const __half* dpwl = dpw_h + (size_t)l * DI * DTR;

        if (l > 0) {
            rmsnorm_kernel<<<MT, 128>>>(h, norm_w + l * HID, hn_h);
            gemm_hmma64_kernel<0><<<dim3((2 * DI) / 128, MT / 128), 256, H2SMEM_BYTES>>>(
                hn_h, HID, wi_h + (size_t)l * 2 * DI * HID, HID, nullptr, xz_h, 2 * DI, HID);
        }

        // depthwise conv + silu -> xssm_h (fp16)
        conv_silu_kernel<<<(MT * DI) / 256, 256>>>(xz_h, cw, cb, xssm_h);

        // dbl = xssm @ xproj_w^T  — fp16 mma, dual fp32+fp16 output
        gemm_xproj_kernel<<<dim3(1, MT / 64), 128, XSMEM_BYTES>>>(
            xssm_h, DI, xpwl, DI, dbl, dbl_h, 64, DI);

        // delta = softplus(dt_raw @ dtproj_w^T + dtproj_b)  (K=32) — fp16 mma
        gemm_dtproj_kernel<<<dim3(DI / 128, MT / 128), 256, HSMEM_BYTES>>>(
            dbl_h, 64, dpwl, DTR, dpb, delta, DI);

        // chunked selective scan -> y (fp16)
        scan2_kernel<<<Bsz * (DI / 16), 256>>>(delta, xssm_h, dbl, xz_h, Al, Dl, y_h);

        // h += y @ outp_w^T  — fp16 mma, fp32 residual add
        gemm_hmma64_kernel<1><<<dim3(HID / 128, MT / 128), 256, H2SMEM_BYTES>>>(
            y_h, DI, wol, DI, h, nullptr, HID, DI);
    }

    // out = h[:, -1, :] @ fc_w^T + fc_b
    fc_kernel<<<3, 256>>>(h, fc_w, fc_b, (float*)d_out);
}

// round 15
// speedup vs baseline: 5.6532x; 1.2558x over previous
#include <cuda_runtime.h>
#include <cuda_bf16.h>
#include <cuda_fp16.h>
#include <math.h>
#include <stdint.h>

// Problem constants
#define Bsz 8
#define Tlen 1024
#define IN_DIM 32
#define HID 512
#define DI 1024
#define DS 16
#define DTR 32
#define Fdim 96
#define MT (Bsz * Tlen)   // 8192 rows

// ---------------- scratch (device globals; no runtime allocation) ----------------
__device__ float g_h[MT * HID];
__device__ __half g_hn_h[MT * HID];
__device__ __half g_xz_h[MT * 2 * DI];     // fp16 xz (x | z)
__device__ __half g_xssm_h[MT * DI];
__device__ float g_dbl[MT * 64];
__device__ __half g_dbl_h[MT * 64];
__device__ float g_delta[MT * DI];
__device__ __half g_y_h[MT * DI];
__device__ __half g_wi_h[2 * 2 * DI * HID];
__device__ __half g_wo_h[2 * HID * DI];
__device__ __half g_xpw_h[2 * 64 * DI];
__device__ __half g_dpw_h[2 * DI * DTR];

__device__ __forceinline__ uint32_t smem_u32(const void* p) {
    uint32_t a;
    asm("{ .reg .u64 t; cvta.to.shared.u64 t, %1; cvt.u32.u64 %0, t; }" : "=r"(a) : "l"(p));
    return a;
}

__device__ __forceinline__ void cpa16(uint32_t saddr, const void* gaddr) {
    asm volatile("cp.async.cg.shared.global [%0], [%1], 16;" :: "r"(saddr), "l"(gaddr));
}

// ---------------- fused fp32 -> fp16 conversion of all 4 weight groups ----------------
#define N_WI (2 * 2 * DI * HID)
#define N_WO (2 * HID * DI)
#define N_XPW (2 * 64 * DI)
#define N_DPW (2 * DI * DTR)
#define N_ALLW (N_WI + N_WO + N_XPW + N_DPW)

__global__ void f2h_all_kernel(const float* __restrict__ wi, const float* __restrict__ wo,
                               const float* __restrict__ xpw, const float* __restrict__ dpw,
                               __half* __restrict__ wi_h, __half* __restrict__ wo_h,
                               __half* __restrict__ xpw_h, __half* __restrict__ dpw_h) {
    int i = blockIdx.x * blockDim.x + threadIdx.x;
    if (i < N_WI) { wi_h[i] = __float2half(wi[i]); return; }
    i -= N_WI;
    if (i < N_WO) { wo_h[i] = __float2half(wo[i]); return; }
    i -= N_WO;
    if (i < N_XPW) { xpw_h[i] = __float2half(xpw[i]); return; }
    i -= N_XPW;
    if (i < N_DPW) { dpw_h[i] = __float2half(dpw[i]); }
}

__device__ __forceinline__ void mma16(float* d, const uint32_t* a, const uint32_t* b) {
    asm volatile(
        "mma.sync.aligned.m16n8k16.row.col.f32.f16.f16.f32 "
        "{%0,%1,%2,%3}, {%4,%5,%6,%7}, {%8,%9}, {%0,%1,%2,%3};"
        : "+f"(d[0]), "+f"(d[1]), "+f"(d[2]), "+f"(d[3])
        : "r"(a[0]), "r"(a[1]), "r"(a[2]), "r"(a[3]), "r"(b[0]), "r"(b[1]));
}

__device__ __forceinline__ void ldsm4(uint32_t& r0, uint32_t& r1, uint32_t& r2, uint32_t& r3,
                                      uint32_t addr) {
    asm volatile("ldmatrix.sync.aligned.m8n8.x4.shared.b16 {%0,%1,%2,%3}, [%4];"
                 : "=r"(r0), "=r"(r1), "=r"(r2), "=r"(r3) : "r"(addr));
}

// ================= main fp16 GEMM (ldmatrix + K-chunk 64) ==========================
#define H2PAD 72
#define H2TILE (128 * H2PAD)
#define H2STAGE (2 * H2TILE)
#define H2NSTAGE 3
#define H2SMEM_BYTES (H2NSTAGE * H2STAGE * 2)   // 110592 B

__device__ __forceinline__ void load_tile64(const __half* __restrict__ g, int ld,
                                            int row0, int k0, __half* s, int tid) {
#pragma unroll
    for (int i = 0; i < 4; i++) {
        int flat = i * 256 + tid;
        int r = flat >> 3;
        int c = flat & 7;
        const __half* gp = g + (size_t)(row0 + r) * ld + k0 + c * 8;
        cpa16(smem_u32(s + r * H2PAD + c * 8), gp);
    }
}

template<int MODE>
__global__ void __launch_bounds__(256)
gemm_hmma64_kernel(const __half* __restrict__ A, int lda,
                   const __half* __restrict__ B, int ldb,
                   float* __restrict__ C, __half* __restrict__ Ch, int ldc, int K)
{
    extern __shared__ __half smh[];
    int tid = threadIdx.x;
    int wid = tid >> 5, lane = tid & 31;
    int g = lane >> 2, t = lane & 3;
    int warp_m = wid >> 2;
    int warp_n = wid & 3;
    int bm = blockIdx.y * 128;
    int bn = blockIdx.x * 128;

    int q = lane >> 3, i = lane & 7;
    int lrow = ((q & 1) << 3) + i;
    int lcol = (q >> 1) << 3;

    float acc[4][4][4];
#pragma unroll
    for (int mt = 0; mt < 4; mt++)
#pragma unroll
        for (int nt = 0; nt < 4; nt++)
#pragma unroll
            for (int qq = 0; qq < 4; qq++) acc[mt][nt][qq] = 0.f;

    int nk = K >> 6;

    load_tile64(A, lda, bm, 0, smh, tid);
    load_tile64(B, ldb, bn, 0, smh + H2TILE, tid);
    asm volatile("cp.async.commit_group;" ::: "memory");
    if (nk > 1) {
        load_tile64(A, lda, bm, 64, smh + H2STAGE, tid);
        load_tile64(B, ldb, bn, 64, smh + H2STAGE + H2TILE, tid);
        asm volatile("cp.async.commit_group;" ::: "memory");
    }

    for (int kc = 0; kc < nk; kc++) {
        if (kc + 2 < nk) {
            int nb = (kc + 2) % H2NSTAGE;
            load_tile64(A, lda, bm, (kc + 2) * 64, smh + nb * H2STAGE, tid);
            load_tile64(B, ldb, bn, (kc + 2) * 64, smh + nb * H2STAGE + H2TILE, tid);
            asm volatile("cp.async.commit_group;" ::: "memory");
            asm volatile("cp.async.wait_group 2;" ::: "memory");
        } else if (kc + 1 < nk) {
            asm volatile("cp.async.wait_group 1;" ::: "memory");
        } else {
            asm volatile("cp.async.wait_group 0;" ::: "memory");
        }
        __syncthreads();

        const __half* sA = smh + (kc % H2NSTAGE) * H2STAGE;
        const __half* sB = sA + H2TILE;

        uint32_t aAddr[4], bAddr[2];
#pragma unroll
        for (int mt = 0; mt < 4; mt++)
            aAddr[mt] = smem_u32(&sA[(warp_m * 64 + mt * 16 + lrow) * H2PAD + lcol]);
#pragma unroll
        for (int p = 0; p < 2; p++)
            bAddr[p] = smem_u32(&sB[(warp_n * 32 + p * 16 + lrow) * H2PAD + lcol]);

#pragma unroll
        for (int kk = 0; kk < 64; kk += 16) {
            uint32_t afr[4][4];
#pragma unroll
            for (int mt = 0; mt < 4; mt++)
                ldsm4(afr[mt][0], afr[mt][1], afr[mt][2], afr[mt][3], aAddr[mt] + kk * 2);
            uint32_t bfr[4][2];
#pragma unroll
            for (int p = 0; p < 2; p++) {
                uint32_t r0, r1, r2, r3;
                ldsm4(r0, r1, r2, r3, bAddr[p] + kk * 2);
                bfr[2 * p][0] = r0; bfr[2 * p + 1][0] = r1;
                bfr[2 * p][1] = r2; bfr[2 * p + 1][1] = r3;
            }
#pragma unroll
            for (int mt = 0; mt < 4; mt++)
#pragma unroll
                for (int nt = 0; nt < 4; nt++)
                    mma16(acc[mt][nt], afr[mt], bfr[nt]);
        }
        __syncthreads();
    }

#pragma unroll
    for (int mt = 0; mt < 4; mt++) {
        int row = bm + warp_m * 64 + mt * 16 + g;
#pragma unroll
        for (int nt = 0; nt < 4; nt++) {
            int col = bn + warp_n * 32 + nt * 8 + t * 2;
            if (MODE == 0) {
                __half2 h0 = __floats2half2_rn(acc[mt][nt][0], acc[mt][nt][1]);
                __half2 h1 = __floats2half2_rn(acc[mt][nt][2], acc[mt][nt][3]);
                *(__half2*)(Ch + (size_t)row * ldc + col) = h0;
                *(__half2*)(Ch + (size_t)(row + 8) * ldc + col) = h1;
            } else {
                float* c0 = C + (size_t)row * ldc + col;
                float* c1 = C + (size_t)(row + 8) * ldc + col;
                float2 o0 = *(const float2*)c0;
                float2 o1 = *(const float2*)c1;
                *(float2*)c0 = make_float2(acc[mt][nt][0] + o0.x, acc[mt][nt][1] + o0.y);
                *(float2*)c1 = make_float2(acc[mt][nt][2] + o1.x, acc[mt][nt][3] + o1.y);
            }
        }
    }
}

// ================= dtproj fp16 GEMM (K=32, softplus epilogue) =======================
#define HPAD 40
#define HTILE (128 * HPAD)
#define HSTAGE (2 * HTILE)
#define HSMEM_BYTES (2 * HSTAGE * 2)

__device__ __forceinline__ void load_tileH(const __half* __restrict__ g, int ld,
                                           int row0, int k0, __half* s, int tid) {
#pragma unroll
    for (int i = 0; i < 2; i++) {
        int flat = i * 256 + tid;
        int r = flat >> 2;
        int c = flat & 3;
        const __half* gp = g + (size_t)(row0 + r) * ld + k0 + c * 8;
        cpa16(smem_u32(s + r * HPAD + c * 8), gp);
    }
}

__global__ void __launch_bounds__(256)
gemm_dtproj_kernel(const __half* __restrict__ A, int lda,
                   const __half* __restrict__ B, int ldb,
                   const float* __restrict__ bias,
                   float* __restrict__ C, int ldc)
{
    extern __shared__ __half smh[];
    int tid = threadIdx.x;
    int wid = tid >> 5, lane = tid & 31;
    int g = lane >> 2, t = lane & 3;
    int warp_m = wid >> 2;
    int warp_n = wid & 3;
    int bm = blockIdx.y * 128;
    int bn = blockIdx.x * 128;

    float acc[4][4][4];
#pragma unroll
    for (int mt = 0; mt < 4; mt++)
#pragma unroll
        for (int nt = 0; nt < 4; nt++)
#pragma unroll
            for (int qq = 0; qq < 4; qq++) acc[mt][nt][qq] = 0.f;

    load_tileH(A, lda, bm, 0, smh, tid);
    load_tileH(B, ldb, bn, 0, smh + HTILE, tid);
    asm volatile("cp.async.commit_group;" ::: "memory");
    asm volatile("cp.async.wait_group 0;" ::: "memory");
    __syncthreads();

    const __half* sA = smh;
    const __half* sB = sA + HTILE;

#pragma unroll
    for (int kk = 0; kk < 32; kk += 16) {
        uint32_t afr[4][4];
#pragma unroll
        for (int mt = 0; mt < 4; mt++) {
            int r0 = warp_m * 64 + mt * 16;
            afr[mt][0] = *(const uint32_t*)&sA[(r0 + g) * HPAD + kk + 2 * t];
            afr[mt][1] = *(const uint32_t*)&sA[(r0 + 8 + g) * HPAD + kk + 2 * t];
            afr[mt][2] = *(const uint32_t*)&sA[(r0 + g) * HPAD + kk + 2 * t + 8];
            afr[mt][3] = *(const uint32_t*)&sA[(r0 + 8 + g) * HPAD + kk + 2 * t + 8];
        }
        uint32_t bfr[4][2];
#pragma unroll
        for (int nt = 0; nt < 4; nt++) {
            int n0 = warp_n * 32 + nt * 8;
            bfr[nt][0] = *(const uint32_t*)&sB[(n0 + g) * HPAD + kk + 2 * t];
            bfr[nt][1] = *(const uint32_t*)&sB[(n0 + g) * HPAD + kk + 2 * t + 8];
        }
#pragma unroll
        for (int mt = 0; mt < 4; mt++)
#pragma unroll
            for (int nt = 0; nt < 4; nt++)
                mma16(acc[mt][nt], afr[mt], bfr[nt]);
    }

#pragma unroll
    for (int mt = 0; mt < 4; mt++) {
        int row = bm + warp_m * 64 + mt * 16 + g;
#pragma unroll
        for (int nt = 0; nt < 4; nt++) {
            int col = bn + warp_n * 32 + nt * 8 + t * 2;
            float b0 = bias[col], b1 = bias[col + 1];
            float2 v0 = make_float2(acc[mt][nt][0] + b0, acc[mt][nt][1] + b1);
            float2 v1 = make_float2(acc[mt][nt][2] + b0, acc[mt][nt][3] + b1);
            v0.x = fmaxf(v0.x, 0.f) + log1pf(expf(-fabsf(v0.x)));
            v0.y = fmaxf(v0.y, 0.f) + log1pf(expf(-fabsf(v0.y)));
            v1.x = fmaxf(v1.x, 0.f) + log1pf(expf(-fabsf(v1.x)));
            v1.y = fmaxf(v1.y, 0.f) + log1pf(expf(-fabsf(v1.y)));
            *(float2*)(C + (size_t)row * ldc + col) = v0;
            *(float2*)(C + (size_t)(row + 8) * ldc + col) = v1;
        }
    }
}

// ================= xproj fp16 GEMM: 64x64 CTA tile, dual fp32+fp16 output ==========
#define XTILE (64 * HPAD)
#define XSTAGE (2 * XTILE)
#define XNSTAGE 3
#define XSMEM_BYTES (XNSTAGE * XSTAGE * 2)

__device__ __forceinline__ void load_tileH64(const __half* __restrict__ g, int ld,
                                             int row0, int k0, __half* s, int tid) {
#pragma unroll
    for (int i = 0; i < 2; i++) {
        int flat = i * 128 + tid;
        int r = flat >> 2;
        int c = flat & 3;
        const __half* gp = g + (size_t)(row0 + r) * ld + k0 + c * 8;
        cpa16(smem_u32(s + r * HPAD + c * 8), gp);
    }
}

__global__ void __launch_bounds__(128)
gemm_xproj_kernel(const __half* __restrict__ A, int lda,
                  const __half* __restrict__ B, int ldb,
                  float* __restrict__ C, __half* __restrict__ Ch, int ldc, int K)
{
    extern __shared__ __half smh[];
    int tid = threadIdx.x;
    int wid = tid >> 5, lane = tid & 31;
    int g = lane >> 2, t = lane & 3;
    int warp_m = wid >> 1;
    int warp_n = wid & 1;
    int bm = blockIdx.y * 64;
    int bn = 0;

    float acc[2][4][4];
#pragma unroll
    for (int mt = 0; mt < 2; mt++)
#pragma unroll
        for (int nt = 0; nt < 4; nt++)
#pragma unroll
            for (int qq = 0; qq < 4; qq++) acc[mt][nt][qq] = 0.f;

    int nk = K >> 5;

    load_tileH64(A, lda, bm, 0, smh, tid);
    load_tileH64(B, ldb, bn, 0, smh + XTILE, tid);
    asm volatile("cp.async.commit_group;" ::: "memory");
    load_tileH64(A, lda, bm, 32, smh + XSTAGE, tid);
    load_tileH64(B, ldb, bn, 32, smh + XSTAGE + XTILE, tid);
    asm volatile("cp.async.commit_group;" ::: "memory");

    for (int kc = 0; kc < nk; kc++) {
        if (kc + 2 < nk) {
            int nb = (kc + 2) % XNSTAGE;
            load_tileH64(A, lda, bm, (kc + 2) * 32, smh + nb * XSTAGE, tid);
            load_tileH64(B, ldb, bn, (kc + 2) * 32, smh + nb * XSTAGE + XTILE, tid);
            asm volatile("cp.async.commit_group;" ::: "memory");
            asm volatile("cp.async.wait_group 2;" ::: "memory");
        } else if (kc + 1 < nk) {
            asm volatile("cp.async.wait_group 1;" ::: "memory");
        } else {
            asm volatile("cp.async.wait_group 0;" ::: "memory");
        }
        __syncthreads();

        const __half* sA = smh + (kc % XNSTAGE) * XSTAGE;
        const __half* sB = sA + XTILE;

#pragma unroll
        for (int kk = 0; kk < 32; kk += 16) {
            uint32_t afr[2][4];
#pragma unroll
            for (int mt = 0; mt < 2; mt++) {
                int r0 = warp_m * 32 + mt * 16;
                afr[mt][0] = *(const uint32_t*)&sA[(r0 + g) * HPAD + kk + 2 * t];
                afr[mt][1] = *(const uint32_t*)&sA[(r0 + 8 + g) * HPAD + kk + 2 * t];
                afr[mt][2] = *(const uint32_t*)&sA[(r0 + g) * HPAD + kk + 2 * t + 8];
                afr[mt][3] = *(const uint32_t*)&sA[(r0 + 8 + g) * HPAD + kk + 2 * t + 8];
            }
            uint32_t bfr[4][2];
#pragma unroll
            for (int nt = 0; nt < 4; nt++) {
                int n0 = warp_n * 32 + nt * 8;
                bfr[nt][0] = *(const uint32_t*)&sB[(n0 + g) * HPAD + kk + 2 * t];
                bfr[nt][1] = *(const uint32_t*)&sB[(n0 + g) * HPAD + kk + 2 * t + 8];
            }
#pragma unroll
            for (int mt = 0; mt < 2; mt++)
#pragma unroll
                for (int nt = 0; nt < 4; nt++)
                    mma16(acc[mt][nt], afr[mt], bfr[nt]);
        }
        __syncthreads();
    }

#pragma unroll
    for (int mt = 0; mt < 2; mt++) {
        int row = bm + warp_m * 32 + mt * 16 + g;
#pragma unroll
        for (int nt = 0; nt < 4; nt++) {
            int col = warp_n * 32 + nt * 8 + t * 2;
            *(float2*)(C + (size_t)row * ldc + col) = make_float2(acc[mt][nt][0], acc[mt][nt][1]);
            *(float2*)(C + (size_t)(row + 8) * ldc + col) = make_float2(acc[mt][nt][2], acc[mt][nt][3]);
            __half2 h0 = __floats2half2_rn(acc[mt][nt][0], acc[mt][nt][1]);
            __half2 h1 = __floats2half2_rn(acc[mt][nt][2], acc[mt][nt][3]);
            *(__half2*)(Ch + (size_t)row * ldc + col) = h0;
            *(__half2*)(Ch + (size_t)(row + 8) * ldc + col) = h1;
        }
    }
}

// ---------------- generic tiled SGEMM (ip GEMM only) ----------------
#define BM 64
#define BN 64
#define BKK 16

template<int MODE>
__global__ void __launch_bounds__(256) gemm_tn_kernel(
    const float* __restrict__ A, int lda,
    const float* __restrict__ Bw, int ldb,
    const float* __restrict__ bias,
    float* __restrict__ C, int ldc,
    int M, int N, int K)
{
    __shared__ float As[BKK][BM + 4];
    __shared__ float Bs[BKK][BN + 4];

    int tid = threadIdx.x;
    int bm = blockIdx.y * BM;
    int bn = blockIdx.x * BN;

    int lrow = tid >> 2;
    int lk   = (tid & 3) * 4;
    int tr = (tid >> 4) * 4;
    int tc = (tid & 15) * 4;

    float acc[4][4];
#pragma unroll
    for (int i = 0; i < 4; i++)
#pragma unroll
        for (int j = 0; j < 4; j++) acc[i][j] = 0.f;

    const float* Aptr = A + (size_t)(bm + lrow) * lda + lk;
    const float* Bptr = Bw + (size_t)(bn + lrow) * ldb + lk;

    for (int k0 = 0; k0 < K; k0 += BKK) {
        float4 av = *(const float4*)Aptr;
        float4 bv = *(const float4*)Bptr;
        if (MODE == 3 && k0 == 0 && lk == 0) {
            av.x *= 0.3f; av.y *= 0.5f; av.z *= 0.9f;
        }
        Aptr += BKK;
        Bptr += BKK;
        As[lk + 0][lrow] = av.x; As[lk + 1][lrow] = av.y;
        As[lk + 2][lrow] = av.z; As[lk + 3][lrow] = av.w;
        Bs[lk + 0][lrow] = bv.x; Bs[lk + 1][lrow] = bv.y;
        Bs[lk + 2][lrow] = bv.z; Bs[lk + 3][lrow] = bv.w;
        __syncthreads();
#pragma unroll
        for (int k = 0; k < BKK; ++k) {
            float4 a4 = *(const float4*)&As[k][tr];
            float4 b4 = *(const float4*)&Bs[k][tc];
            float ar[4] = {a4.x, a4.y, a4.z, a4.w};
            float br[4] = {b4.x, b4.y, b4.z, b4.w};
#pragma unroll
            for (int i = 0; i < 4; ++i)
#pragma unroll
                for (int j = 0; j < 4; ++j)
                    acc[i][j] = fmaf(ar[i], br[j], acc[i][j]);
        }
        __syncthreads();
    }

#pragma unroll
    for (int i = 0; i < 4; ++i) {
        float* Cp = C + (size_t)(bm + tr + i) * ldc + (bn + tc);
        float vals[4];
#pragma unroll
        for (int j = 0; j < 4; ++j) {
            float v = acc[i][j];
            if (bias) v += bias[bn + tc + j];
            vals[j] = v;
        }
        float4 r; r.x = vals[0]; r.y = vals[1]; r.z = vals[2]; r.w = vals[3];
        *(float4*)Cp = r;
    }
}

// ---------------- rmsnorm -> fp16 output for MMA ----------------
__global__ void __launch_bounds__(128) rmsnorm_kernel(
    const float* __restrict__ h, const float* __restrict__ w, __half* __restrict__ out)
{
    int row = blockIdx.x;
    const float* hr = h + (size_t)row * HID;
    float v[4];
    float ss = 0.f;
#pragma unroll
    for (int i = 0; i < 4; i++) {
        v[i] = hr[threadIdx.x + i * 128];
        ss += v[i] * v[i];
    }
#pragma unroll
    for (int o = 16; o; o >>= 1) ss += __shfl_xor_sync(0xffffffffu, ss, o);
    __shared__ float red[4];
    if ((threadIdx.x & 31) == 0) red[threadIdx.x >> 5] = ss;
    __syncthreads();
    float tot = red[0] + red[1] + red[2] + red[3];
    float sc = rsqrtf(tot * (1.f / (float)HID) + 1e-5f);
#pragma unroll
    for (int i = 0; i < 4; i++) {
        int c = threadIdx.x + i * 128;
        out[(size_t)row * HID + c] = __float2half(v[i] * sc * w[c]);
    }
}

// ---------------- depthwise causal conv (K=4) + bias + silu, fp16 in/out ----------
__global__ void conv_silu_kernel(const __half* __restrict__ xz,
                                 const float* __restrict__ cw,
                                 const float* __restrict__ cb,
                                 __half* __restrict__ xssm_h)
{
    int idx = blockIdx.x * blockDim.x + threadIdx.x;
    int d = idx & (DI - 1);
    int bt = idx >> 10;
    int t = bt & (Tlen - 1);
    float w0 = cw[d * 4 + 0], w1 = cw[d * 4 + 1], w2 = cw[d * 4 + 2], w3 = cw[d * 4 + 3];
    const __half* col = xz + (size_t)bt * (2 * DI) + d;
    float acc = cb[d] + w3 * __half2float(col[0]);
    if (t >= 1) acc += w2 * __half2float(col[-(2 * DI)]);
    if (t >= 2) acc += w1 * __half2float(col[-(4 * DI)]);
    if (t >= 3) acc += w0 * __half2float(col[-(6 * DI)]);
    float sig = 1.f / (1.f + __expf(-acc));
    xssm_h[(size_t)bt * DI + d] = __float2half(acc * sig);
}

// ================= scan v3: 2 states/lane, 8 lanes/d, 4 d/warp, 32 d/block ==========
// Block = 256 threads = 8 warps. Grid = Bsz * (DI/32) = 256 blocks.
// T in chunks of 64, double-buffered cp.async staging; precompute & store passes
// column-major; staging arrays padded to stride 36 for conflict-free access.
#define SCH3 64
#define NCH3 (Tlen / SCH3)   // 16
#define SD3 (SCH3 * 32)      // 2048 elements per f32/f16 tile
#define SP3 (SCH3 * 36)      // padded staging stride
#define SCAN3_SMEM ((2*SD3*4)*2 + (2*SD3*2)*2 + 4*SP3*4)   // 86016 B

__global__ void __launch_bounds__(256) scan3_kernel(
    const float* __restrict__ delta,
    const __half* __restrict__ xssm_h,
    const float* __restrict__ dbl,
    const __half* __restrict__ xz_h,
    const float* __restrict__ A_log,
    const float* __restrict__ Dp,
    __half* __restrict__ y)
{
    extern __shared__ char smraw[];
    float* sd   = (float*)smraw;              // [2][SCH3][32] delta
    float* sbc  = sd + 2 * SD3;               // [2][SCH3][32] B|C
    __half* sxh = (__half*)(sbc + 2 * SD3);   // [2][SCH3][32] x
    __half* szh = sxh + 2 * SD3;              // [2][SCH3][32] z
    float* sx32 = (float*)(szh + 2 * SD3);    // [SCH3][36] dt*x
    float* sz32 = sx32 + SP3;                 // [SCH3][36] silu(z)
    float* sm2  = sz32 + SP3;                 // [SCH3][36] x*D*silu(z)
    float* sy   = sm2 + SP3;                  // [SCH3][36] y

    int tid = threadIdx.x;
    int b   = blockIdx.x >> 5;
    int dt0 = (blockIdx.x & 31) << 5;   // 32 d per block

    int wid = tid >> 5, lane = tid & 31;
    int j   = lane & 7;                 // owns states 2j, 2j+1
    int sub = lane >> 3;                // 0..3
    int dloc = wid * 4 + sub;           // 0..31
    int d = dt0 + dloc;

    float A0 = -expf(A_log[d * DS + 2 * j]);
    float A1 = -expf(A_log[d * DS + 2 * j + 1]);
    float h0 = 0.f, h1 = 0.f;

    // precompute pass mapping (column-major: lane = column)
    int pc  = tid & 31;
    int pr0 = (tid >> 5) * 8;
    float Dcol = Dp[dt0 + pc];

    // store pass mapping
    int l4r = tid >> 2, l4c = (tid & 3) * 8;

    size_t base_row = (size_t)b * Tlen;

    // ---- prefetch chunk 0 -> buf 0 ----
    {
#pragma unroll
        for (int i = 0; i < 2; i++) {
            int idx = i * 256 + tid;
            int r = idx >> 3, qq = (idx & 7) * 4;
            cpa16(smem_u32(&sd[r * 32 + qq]), delta + (base_row + r) * DI + dt0 + qq);
            cpa16(smem_u32(&sbc[r * 32 + qq]), dbl + (base_row + r) * 64 + 32 + qq);
        }
        cpa16(smem_u32(&sxh[l4r * 32 + l4c]), xssm_h + (base_row + l4r) * DI + dt0 + l4c);
        cpa16(smem_u32(&szh[l4r * 32 + l4c]), xz_h + (base_row + l4r) * (2 * DI) + DI + dt0 + l4c);
        asm volatile("cp.async.commit_group;" ::: "memory");
    }

    for (int c = 0; c < NCH3; c++) {
        int buf = c & 1;
        int fo = buf * SD3;   // f32/f16 tile offset
        if (c + 1 < NCH3) {
            int nb = 1 - buf;
            int nfo = nb * SD3;
            size_t rbase = base_row + (c + 1) * SCH3;
#pragma unroll
            for (int i = 0; i < 2; i++) {
                int idx = i * 256 + tid;
                int r = idx >> 3, qq = (idx & 7) * 4;
                cpa16(smem_u32(&sd[nfo + r * 32 + qq]), delta + (rbase + r) * DI + dt0 + qq);
                cpa16(smem_u32(&sbc[nfo + r * 32 + qq]), dbl + (rbase + r) * 64 + 32 + qq);
            }
            cpa16(smem_u32(&sxh[nfo + l4r * 32 + l4c]), xssm_h + (rbase + l4r) * DI + dt0 + l4c);
            cpa16(smem_u32(&szh[nfo + l4r * 32 + l4c]), xz_h + (rbase + l4r) * (2 * DI) + DI + dt0 + l4c);
            asm volatile("cp.async.commit_group;" ::: "memory");
            asm volatile("cp.async.wait_group 1;" ::: "memory");
        } else {
            asm volatile("cp.async.wait_group 0;" ::: "memory");
        }
        __syncthreads();

        // precompute (column-major, conflict-free)
#pragma unroll
        for (int jj = 0; jj < 8; jj++) {
            int r = pr0 + jj;
            float dtv = sd[fo + r * 32 + pc];
            float xv  = __half2float(sxh[fo + r * 32 + pc]);
            float zv  = __half2float(szh[fo + r * 32 + pc]);
            float szl = zv / (1.f + __expf(-zv));
            sx32[r * 36 + pc] = dtv * xv;
            sz32[r * 36 + pc] = szl;
            sm2[r * 36 + pc]  = xv * Dcol * szl;
        }
        __syncthreads();

        // serial scan over the chunk
#pragma unroll 4
        for (int tt = 0; tt < SCH3; tt++) {
            float dtv = sd[fo + tt * 32 + dloc];
            float dtx = sx32[tt * 36 + dloc];
            float2 B2 = *(const float2*)&sbc[fo + tt * 32 + 2 * j];
            float2 C2 = *(const float2*)&sbc[fo + tt * 32 + 16 + 2 * j];
            h0 = fmaf(h0, __expf(dtv * A0), dtx * B2.x);
            h1 = fmaf(h1, __expf(dtv * A1), dtx * B2.y);
            float yp = fmaf(h1, C2.y, h0 * C2.x);
            yp += __shfl_xor_sync(0xffffffffu, yp, 4, 32);
            yp += __shfl_xor_sync(0xffffffffu, yp, 2, 32);
            yp += __shfl_xor_sync(0xffffffffu, yp, 1, 32);
            if (j == 0) {
                sy[tt * 36 + dloc] = fmaf(yp, sz32[tt * 36 + dloc], sm2[tt * 36 + dloc]);
            }
        }
        __syncthreads();

        // coalesced fp16 store of y chunk
        {
            size_t ro = base_row + c * SCH3 + l4r;
            float4 v0 = *(const float4*)&sy[l4r * 36 + l4c];
            float4 v1 = *(const float4*)&sy[l4r * 36 + l4c + 4];
            __half2 a0 = __floats2half2_rn(v0.x, v0.y);
            __half2 a1 = __floats2half2_rn(v0.z, v0.w);
            __half2 a2 = __floats2half2_rn(v1.x, v1.y);
            __half2 a3 = __floats2half2_rn(v1.z, v1.w);
            uint4 u;
            u.x = *(const uint32_t*)&a0;
            u.y = *(const uint32_t*)&a1;
            u.z = *(const uint32_t*)&a2;
            u.w = *(const uint32_t*)&a3;
            *(uint4*)(y + ro * DI + dt0 + l4c) = u;
        }
        __syncthreads();   // protect staging arrays before next chunk's precompute
    }
}

// ---------------- final FC on last token ----------------
__global__ void fc_kernel(const float* __restrict__ h, const float* __restrict__ fc_w,
                          const float* __restrict__ fc_b, float* __restrict__ out)
{
    int idx = blockIdx.x * blockDim.x + threadIdx.x;
    if (idx >= Bsz * Fdim) return;
    int b = idx / Fdim, f = idx % Fdim;
    const float* hr = h + ((size_t)b * Tlen + (Tlen - 1)) * HID;
    const float* wr = fc_w + (size_t)f * HID;
    float acc = fc_b[f];
    for (int k = 0; k < HID; k += 4) {
        float4 hv = *(const float4*)(hr + k);
        float4 wv = *(const float4*)(wr + k);
        acc += hv.x * wv.x + hv.y * wv.y + hv.z * wv.z + hv.w * wv.w;
    }
    out[idx] = acc;
}

// ---------------- launcher ----------------
extern "C" void kernel_launch(void* const* d_in, const int* in_sizes, int n_in,
                              void* d_out, int out_size)
{
    const float* x        = (const float*)d_in[0];
    const float* ip_w     = (const float*)d_in[1];
    const float* ip_b     = (const float*)d_in[2];
    const float* norm_w   = (const float*)d_in[3];
    const float* inp_w    = (const float*)d_in[4];
    const float* conv_w   = (const float*)d_in[5];
    const float* conv_b   = (const float*)d_in[6];
    const float* xproj_w  = (const float*)d_in[7];
    const float* dtproj_w = (const float*)d_in[8];
    const float* dtproj_b = (const float*)d_in[9];
    const float* A_log    = (const float*)d_in[10];
    const float* Dvec     = (const float*)d_in[11];
    const float* outp_w   = (const float*)d_in[12];
    const float* fc_w     = (const float*)d_in[13];
    const float* fc_b     = (const float*)d_in[14];

    float *h, *dbl, *delta;
    __half *hn_h, *y_h, *wi_h, *wo_h, *xz_h, *xssm_h, *dbl_h, *xpw_h, *dpw_h;
    cudaGetSymbolAddress((void**)&h, g_h);
    cudaGetSymbolAddress((void**)&hn_h, g_hn_h);
    cudaGetSymbolAddress((void**)&xz_h, g_xz_h);
    cudaGetSymbolAddress((void**)&xssm_h, g_xssm_h);
    cudaGetSymbolAddress((void**)&dbl, g_dbl);
    cudaGetSymbolAddress((void**)&dbl_h, g_dbl_h);
    cudaGetSymbolAddress((void**)&delta, g_delta);
    cudaGetSymbolAddress((void**)&y_h, g_y_h);
    cudaGetSymbolAddress((void**)&wi_h, g_wi_h);
    cudaGetSymbolAddress((void**)&wo_h, g_wo_h);
    cudaGetSymbolAddress((void**)&xpw_h, g_xpw_h);
    cudaGetSymbolAddress((void**)&dpw_h, g_dpw_h);

    static int attr_done = 0;
    if (!attr_done) {
        cudaFuncSetAttribute(gemm_hmma64_kernel<0>, cudaFuncAttributeMaxDynamicSharedMemorySize, H2SMEM_BYTES);
        cudaFuncSetAttribute(gemm_hmma64_kernel<1>, cudaFuncAttributeMaxDynamicSharedMemorySize, H2SMEM_BYTES);
        cudaFuncSetAttribute(gemm_dtproj_kernel, cudaFuncAttributeMaxDynamicSharedMemorySize, HSMEM_BYTES);
        cudaFuncSetAttribute(gemm_xproj_kernel, cudaFuncAttributeMaxDynamicSharedMemorySize, XSMEM_BYTES);
        cudaFuncSetAttribute(scan3_kernel, cudaFuncAttributeMaxDynamicSharedMemorySize, SCAN3_SMEM);
        attr_done = 1;
    }

    // (1) convert ALL weights to fp16 (single launch)
    f2h_all_kernel<<<(N_ALLW + 255) / 256, 256>>>(
        inp_w, outp_w, xproj_w, dtproj_w, wi_h, wo_h, xpw_h, dpw_h);

    // (2) h = scaled_x @ ip_w^T + ip_b
    gemm_tn_kernel<3><<<dim3(HID / BN, MT / BM), 256>>>(
        x, IN_DIM, ip_w, IN_DIM, ip_b, h, HID, MT, HID, IN_DIM);

    // (3) hn = rmsnorm(h) * nw  -> fp16   (layer 0)
    rmsnorm_kernel<<<MT, 128>>>(h, norm_w, hn_h);

    // (4) xz = hn @ inp_w^T  — fp16 mma, fp16 output   [ncu capture slot]
    gemm_hmma64_kernel<0><<<dim3((2 * DI) / 128, MT / 128), 256, H2SMEM_BYTES>>>(
        hn_h, HID, wi_h, HID, nullptr, xz_h, 2 * DI, HID);

    for (int l = 0; l < 2; l++) {
        const float* cw  = conv_w + (size_t)l * DI * 4;
        const float* cb  = conv_b + (size_t)l * DI;
        const float* dpb = dtproj_b + (size_t)l * DI;
        const float* Al  = A_log + (size_t)l * DI * DS;
        const float* Dl  = Dvec + (size_t)l * DI;
        const __half* wol  = wo_h + (size_t)l * HID * DI;
        const __half* xpwl = xpw_h + (size_t)l * 64 * DI;
        const __half* dpwl = dpw_h + (size_t)l * DI * DTR;

        if (l > 0) {
            rmsnorm_kernel<<<MT, 128>>>(h, norm_w + l * HID, hn_h);
            gemm_hmma64_kernel<0><<<dim3((2 * DI) / 128, MT / 128), 256, H2SMEM_BYTES>>>(
                hn_h, HID, wi_h + (size_t)l * 2 * DI * HID, HID, nullptr, xz_h, 2 * DI, HID);
        }

        // depthwise conv + silu -> xssm_h (fp16)
        conv_silu_kernel<<<(MT * DI) / 256, 256>>>(xz_h, cw, cb, xssm_h);

        // dbl = xssm @ xproj_w^T  — fp16 mma, dual fp32+fp16 output
        gemm_xproj_kernel<<<dim3(1, MT / 64), 128, XSMEM_BYTES>>>(
            xssm_h, DI, xpwl, DI, dbl, dbl_h, 64, DI);

        // delta = softplus(dt_raw @ dtproj_w^T + dtproj_b)  (K=32) — fp16 mma
        gemm_dtproj_kernel<<<dim3(DI / 128, MT / 128), 256, HSMEM_BYTES>>>(
            dbl_h, 64, dpwl, DTR, dpb, delta, DI);

        // selective scan v3 -> y (fp16)
        scan3_kernel<<<Bsz * (DI / 32), 256, SCAN3_SMEM>>>(
            delta, xssm_h, dbl, xz_h, Al, Dl, y_h);

        // h += y @ outp_w^T  — fp16 mma, fp32 residual add
        gemm_hmma64_kernel<1><<<dim3(HID / 128, MT / 128), 256, H2SMEM_BYTES>>>(
            y_h, DI, wol, DI, h, nullptr, HID, DI);
    }

    // out = h[:, -1, :] @ fc_w^T + fc_b
    fc_kernel<<<3, 256>>>(h, fc_w, fc_b, (float*)d_out);
}

// round 16
// speedup vs baseline: 5.7479x; 1.0168x over previous
#include <cuda_runtime.h>
#include <cuda_bf16.h>
#include <cuda_fp16.h>
#include <math.h>
#include <stdint.h>

// Problem constants
#define Bsz 8
#define Tlen 1024
#define IN_DIM 32
#define HID 512
#define DI 1024
#define DS 16
#define DTR 32
#define Fdim 96
#define MT (Bsz * Tlen)   // 8192 rows

// ---------------- scratch (device globals; no runtime allocation) ----------------
__device__ float g_h[MT * HID];
__device__ __half g_hn_h[MT * HID];
__device__ __half g_xz_h[MT * 2 * DI];     // fp16 xz (x | z)
__device__ __half g_xssm_h[MT * DI];
__device__ float g_dbl[MT * 64];
__device__ __half g_dbl_h[MT * 64];
__device__ float g_delta[MT * DI];
__device__ __half g_y_h[MT * DI];
__device__ __half g_wi_h[2 * 2 * DI * HID];
__device__ __half g_wo_h[2 * HID * DI];
__device__ __half g_xpw_h[2 * 64 * DI];
__device__ __half g_dpw_h[2 * DI * DTR];

__device__ __forceinline__ uint32_t smem_u32(const void* p) {
    uint32_t a;
    asm("{ .reg .u64 t; cvta.to.shared.u64 t, %1; cvt.u32.u64 %0, t; }" : "=r"(a) : "l"(p));
    return a;
}

__device__ __forceinline__ void cpa16(uint32_t saddr, const void* gaddr) {
    asm volatile("cp.async.cg.shared.global [%0], [%1], 16;" :: "r"(saddr), "l"(gaddr));
}

// ---------------- fused fp32 -> fp16 conversion of all 4 weight groups ----------------
#define N_WI (2 * 2 * DI * HID)
#define N_WO (2 * HID * DI)
#define N_XPW (2 * 64 * DI)
#define N_DPW (2 * DI * DTR)
#define N_ALLW (N_WI + N_WO + N_XPW + N_DPW)

__global__ void f2h_all_kernel(const float* __restrict__ wi, const float* __restrict__ wo,
                               const float* __restrict__ xpw, const float* __restrict__ dpw,
                               __half* __restrict__ wi_h, __half* __restrict__ wo_h,
                               __half* __restrict__ xpw_h, __half* __restrict__ dpw_h) {
    int i = blockIdx.x * blockDim.x + threadIdx.x;
    if (i < N_WI) { wi_h[i] = __float2half(wi[i]); return; }
    i -= N_WI;
    if (i < N_WO) { wo_h[i] = __float2half(wo[i]); return; }
    i -= N_WO;
    if (i < N_XPW) { xpw_h[i] = __float2half(xpw[i]); return; }
    i -= N_XPW;
    if (i < N_DPW) { dpw_h[i] = __float2half(dpw[i]); }
}

__device__ __forceinline__ void mma16(float* d, const uint32_t* a, const uint32_t* b) {
    asm volatile(
        "mma.sync.aligned.m16n8k16.row.col.f32.f16.f16.f32 "
        "{%0,%1,%2,%3}, {%4,%5,%6,%7}, {%8,%9}, {%0,%1,%2,%3};"
        : "+f"(d[0]), "+f"(d[1]), "+f"(d[2]), "+f"(d[3])
        : "r"(a[0]), "r"(a[1]), "r"(a[2]), "r"(a[3]), "r"(b[0]), "r"(b[1]));
}

__device__ __forceinline__ void ldsm4(uint32_t& r0, uint32_t& r1, uint32_t& r2, uint32_t& r3,
                                      uint32_t addr) {
    asm volatile("ldmatrix.sync.aligned.m8n8.x4.shared.b16 {%0,%1,%2,%3}, [%4];"
                 : "=r"(r0), "=r"(r1), "=r"(r2), "=r"(r3) : "r"(addr));
}

// ================= main fp16 GEMM (ldmatrix + K-chunk 64) ==========================
#define H2PAD 72
#define H2TILE (128 * H2PAD)
#define H2STAGE (2 * H2TILE)
#define H2NSTAGE 3
#define H2SMEM_BYTES (H2NSTAGE * H2STAGE * 2)   // 110592 B

__device__ __forceinline__ void load_tile64(const __half* __restrict__ g, int ld,
                                            int row0, int k0, __half* s, int tid) {
#pragma unroll
    for (int i = 0; i < 4; i++) {
        int flat = i * 256 + tid;
        int r = flat >> 3;
        int c = flat & 7;
        const __half* gp = g + (size_t)(row0 + r) * ld + k0 + c * 8;
        cpa16(smem_u32(s + r * H2PAD + c * 8), gp);
    }
}

template<int MODE>
__global__ void __launch_bounds__(256)
gemm_hmma64_kernel(const __half* __restrict__ A, int lda,
                   const __half* __restrict__ B, int ldb,
                   float* __restrict__ C, __half* __restrict__ Ch, int ldc, int K)
{
    extern __shared__ __half smh[];
    int tid = threadIdx.x;
    int wid = tid >> 5, lane = tid & 31;
    int g = lane >> 2, t = lane & 3;
    int warp_m = wid >> 2;
    int warp_n = wid & 3;
    int bm = blockIdx.y * 128;
    int bn = blockIdx.x * 128;

    int q = lane >> 3, i = lane & 7;
    int lrow = ((q & 1) << 3) + i;
    int lcol = (q >> 1) << 3;

    float acc[4][4][4];
#pragma unroll
    for (int mt = 0; mt < 4; mt++)
#pragma unroll
        for (int nt = 0; nt < 4; nt++)
#pragma unroll
            for (int qq = 0; qq < 4; qq++) acc[mt][nt][qq] = 0.f;

    int nk = K >> 6;

    load_tile64(A, lda, bm, 0, smh, tid);
    load_tile64(B, ldb, bn, 0, smh + H2TILE, tid);
    asm volatile("cp.async.commit_group;" ::: "memory");
    if (nk > 1) {
        load_tile64(A, lda, bm, 64, smh + H2STAGE, tid);
        load_tile64(B, ldb, bn, 64, smh + H2STAGE + H2TILE, tid);
        asm volatile("cp.async.commit_group;" ::: "memory");
    }

    for (int kc = 0; kc < nk; kc++) {
        if (kc + 2 < nk) {
            int nb = (kc + 2) % H2NSTAGE;
            load_tile64(A, lda, bm, (kc + 2) * 64, smh + nb * H2STAGE, tid);
            load_tile64(B, ldb, bn, (kc + 2) * 64, smh + nb * H2STAGE + H2TILE, tid);
            asm volatile("cp.async.commit_group;" ::: "memory");
            asm volatile("cp.async.wait_group 2;" ::: "memory");
        } else if (kc + 1 < nk) {
            asm volatile("cp.async.wait_group 1;" ::: "memory");
        } else {
            asm volatile("cp.async.wait_group 0;" ::: "memory");
        }
        __syncthreads();

        const __half* sA = smh + (kc % H2NSTAGE) * H2STAGE;
        const __half* sB = sA + H2TILE;

        uint32_t aAddr[4], bAddr[2];
#pragma unroll
        for (int mt = 0; mt < 4; mt++)
            aAddr[mt] = smem_u32(&sA[(warp_m * 64 + mt * 16 + lrow) * H2PAD + lcol]);
#pragma unroll
        for (int p = 0; p < 2; p++)
            bAddr[p] = smem_u32(&sB[(warp_n * 32 + p * 16 + lrow) * H2PAD + lcol]);

#pragma unroll
        for (int kk = 0; kk < 64; kk += 16) {
            uint32_t afr[4][4];
#pragma unroll
            for (int mt = 0; mt < 4; mt++)
                ldsm4(afr[mt][0], afr[mt][1], afr[mt][2], afr[mt][3], aAddr[mt] + kk * 2);
            uint32_t bfr[4][2];
#pragma unroll
            for (int p = 0; p < 2; p++) {
                uint32_t r0, r1, r2, r3;
                ldsm4(r0, r1, r2, r3, bAddr[p] + kk * 2);
                bfr[2 * p][0] = r0; bfr[2 * p + 1][0] = r1;
                bfr[2 * p][1] = r2; bfr[2 * p + 1][1] = r3;
            }
#pragma unroll
            for (int mt = 0; mt < 4; mt++)
#pragma unroll
                for (int nt = 0; nt < 4; nt++)
                    mma16(acc[mt][nt], afr[mt], bfr[nt]);
        }
        __syncthreads();
    }

#pragma unroll
    for (int mt = 0; mt < 4; mt++) {
        int row = bm + warp_m * 64 + mt * 16 + g;
#pragma unroll
        for (int nt = 0; nt < 4; nt++) {
            int col = bn + warp_n * 32 + nt * 8 + t * 2;
            if (MODE == 0) {
                __half2 h0 = __floats2half2_rn(acc[mt][nt][0], acc[mt][nt][1]);
                __half2 h1 = __floats2half2_rn(acc[mt][nt][2], acc[mt][nt][3]);
                *(__half2*)(Ch + (size_t)row * ldc + col) = h0;
                *(__half2*)(Ch + (size_t)(row + 8) * ldc + col) = h1;
            } else {
                float* c0 = C + (size_t)row * ldc + col;
                float* c1 = C + (size_t)(row + 8) * ldc + col;
                float2 o0 = *(const float2*)c0;
                float2 o1 = *(const float2*)c1;
                *(float2*)c0 = make_float2(acc[mt][nt][0] + o0.x, acc[mt][nt][1] + o0.y);
                *(float2*)c1 = make_float2(acc[mt][nt][2] + o1.x, acc[mt][nt][3] + o1.y);
            }
        }
    }
}

// ================= dtproj fp16 GEMM (K=32, softplus epilogue) =======================
#define HPAD 40
#define HTILE (128 * HPAD)
#define HSTAGE (2 * HTILE)
#define HSMEM_BYTES (2 * HSTAGE * 2)

__device__ __forceinline__ void load_tileH(const __half* __restrict__ g, int ld,
                                           int row0, int k0, __half* s, int tid) {
#pragma unroll
    for (int i = 0; i < 2; i++) {
        int flat = i * 256 + tid;
        int r = flat >> 2;
        int c = flat & 3;
        const __half* gp = g + (size_t)(row0 + r) * ld + k0 + c * 8;
        cpa16(smem_u32(s + r * HPAD + c * 8), gp);
    }
}

__global__ void __launch_bounds__(256)
gemm_dtproj_kernel(const __half* __restrict__ A, int lda,
                   const __half* __restrict__ B, int ldb,
                   const float* __restrict__ bias,
                   float* __restrict__ C, int ldc)
{
    extern __shared__ __half smh[];
    int tid = threadIdx.x;
    int wid = tid >> 5, lane = tid & 31;
    int g = lane >> 2, t = lane & 3;
    int warp_m = wid >> 2;
    int warp_n = wid & 3;
    int bm = blockIdx.y * 128;
    int bn = blockIdx.x * 128;

    float acc[4][4][4];
#pragma unroll
    for (int mt = 0; mt < 4; mt++)
#pragma unroll
        for (int nt = 0; nt < 4; nt++)
#pragma unroll
            for (int qq = 0; qq < 4; qq++) acc[mt][nt][qq] = 0.f;

    load_tileH(A, lda, bm, 0, smh, tid);
    load_tileH(B, ldb, bn, 0, smh + HTILE, tid);
    asm volatile("cp.async.commit_group;" ::: "memory");
    asm volatile("cp.async.wait_group 0;" ::: "memory");
    __syncthreads();

    const __half* sA = smh;
    const __half* sB = sA + HTILE;

#pragma unroll
    for (int kk = 0; kk < 32; kk += 16) {
        uint32_t afr[4][4];
#pragma unroll
        for (int mt = 0; mt < 4; mt++) {
            int r0 = warp_m * 64 + mt * 16;
            afr[mt][0] = *(const uint32_t*)&sA[(r0 + g) * HPAD + kk + 2 * t];
            afr[mt][1] = *(const uint32_t*)&sA[(r0 + 8 + g) * HPAD + kk + 2 * t];
            afr[mt][2] = *(const uint32_t*)&sA[(r0 + g) * HPAD + kk + 2 * t + 8];
            afr[mt][3] = *(const uint32_t*)&sA[(r0 + 8 + g) * HPAD + kk + 2 * t + 8];
        }
        uint32_t bfr[4][2];
#pragma unroll
        for (int nt = 0; nt < 4; nt++) {
            int n0 = warp_n * 32 + nt * 8;
            bfr[nt][0] = *(const uint32_t*)&sB[(n0 + g) * HPAD + kk + 2 * t];
            bfr[nt][1] = *(const uint32_t*)&sB[(n0 + g) * HPAD + kk + 2 * t + 8];
        }
#pragma unroll
        for (int mt = 0; mt < 4; mt++)
#pragma unroll
            for (int nt = 0; nt < 4; nt++)
                mma16(acc[mt][nt], afr[mt], bfr[nt]);
    }

#pragma unroll
    for (int mt = 0; mt < 4; mt++) {
        int row = bm + warp_m * 64 + mt * 16 + g;
#pragma unroll
        for (int nt = 0; nt < 4; nt++) {
            int col = bn + warp_n * 32 + nt * 8 + t * 2;
            float b0 = bias[col], b1 = bias[col + 1];
            float2 v0 = make_float2(acc[mt][nt][0] + b0, acc[mt][nt][1] + b1);
            float2 v1 = make_float2(acc[mt][nt][2] + b0, acc[mt][nt][3] + b1);
            v0.x = fmaxf(v0.x, 0.f) + log1pf(expf(-fabsf(v0.x)));
            v0.y = fmaxf(v0.y, 0.f) + log1pf(expf(-fabsf(v0.y)));
            v1.x = fmaxf(v1.x, 0.f) + log1pf(expf(-fabsf(v1.x)));
            v1.y = fmaxf(v1.y, 0.f) + log1pf(expf(-fabsf(v1.y)));
            *(float2*)(C + (size_t)row * ldc + col) = v0;
            *(float2*)(C + (size_t)(row + 8) * ldc + col) = v1;
        }
    }
}

// ================= xproj fp16 GEMM: 64x64 CTA tile, dual fp32+fp16 output ==========
#define XTILE (64 * HPAD)
#define XSTAGE (2 * XTILE)
#define XNSTAGE 3
#define XSMEM_BYTES (XNSTAGE * XSTAGE * 2)

__device__ __forceinline__ void load_tileH64(const __half* __restrict__ g, int ld,
                                             int row0, int k0, __half* s, int tid) {
#pragma unroll
    for (int i = 0; i < 2; i++) {
        int flat = i * 128 + tid;
        int r = flat >> 2;
        int c = flat & 3;
        const __half* gp = g + (size_t)(row0 + r) * ld + k0 + c * 8;
        cpa16(smem_u32(s + r * HPAD + c * 8), gp);
    }
}

__global__ void __launch_bounds__(128)
gemm_xproj_kernel(const __half* __restrict__ A, int lda,
                  const __half* __restrict__ B, int ldb,
                  float* __restrict__ C, __half* __restrict__ Ch, int ldc, int K)
{
    extern __shared__ __half smh[];
    int tid = threadIdx.x;
    int wid = tid >> 5, lane = tid & 31;
    int g = lane >> 2, t = lane & 3;
    int warp_m = wid >> 1;
    int warp_n = wid & 1;
    int bm = blockIdx.y * 64;
    int bn = 0;

    float acc[2][4][4];
#pragma unroll
    for (int mt = 0; mt < 2; mt++)
#pragma unroll
        for (int nt = 0; nt < 4; nt++)
#pragma unroll
            for (int qq = 0; qq < 4; qq++) acc[mt][nt][qq] = 0.f;

    int nk = K >> 5;

    load_tileH64(A, lda, bm, 0, smh, tid);
    load_tileH64(B, ldb, bn, 0, smh + XTILE, tid);
    asm volatile("cp.async.commit_group;" ::: "memory");
    load_tileH64(A, lda, bm, 32, smh + XSTAGE, tid);
    load_tileH64(B, ldb, bn, 32, smh + XSTAGE + XTILE, tid);
    asm volatile("cp.async.commit_group;" ::: "memory");

    for (int kc = 0; kc < nk; kc++) {
        if (kc + 2 < nk) {
            int nb = (kc + 2) % XNSTAGE;
            load_tileH64(A, lda, bm, (kc + 2) * 32, smh + nb * XSTAGE, tid);
            load_tileH64(B, ldb, bn, (kc + 2) * 32, smh + nb * XSTAGE + XTILE, tid);
            asm volatile("cp.async.commit_group;" ::: "memory");
            asm volatile("cp.async.wait_group 2;" ::: "memory");
        } else if (kc + 1 < nk) {
            asm volatile("cp.async.wait_group 1;" ::: "memory");
        } else {
            asm volatile("cp.async.wait_group 0;" ::: "memory");
        }
        __syncthreads();

        const __half* sA = smh + (kc % XNSTAGE) * XSTAGE;
        const __half* sB = sA + XTILE;

#pragma unroll
        for (int kk = 0; kk < 32; kk += 16) {
            uint32_t afr[2][4];
#pragma unroll
            for (int mt = 0; mt < 2; mt++) {
                int r0 = warp_m * 32 + mt * 16;
                afr[mt][0] = *(const uint32_t*)&sA[(r0 + g) * HPAD + kk + 2 * t];
                afr[mt][1] = *(const uint32_t*)&sA[(r0 + 8 + g) * HPAD + kk + 2 * t];
                afr[mt][2] = *(const uint32_t*)&sA[(r0 + g) * HPAD + kk + 2 * t + 8];
                afr[mt][3] = *(const uint32_t*)&sA[(r0 + 8 + g) * HPAD + kk + 2 * t + 8];
            }
            uint32_t bfr[4][2];
#pragma unroll
            for (int nt = 0; nt < 4; nt++) {
                int n0 = warp_n * 32 + nt * 8;
                bfr[nt][0] = *(const uint32_t*)&sB[(n0 + g) * HPAD + kk + 2 * t];
                bfr[nt][1] = *(const uint32_t*)&sB[(n0 + g) * HPAD + kk + 2 * t + 8];
            }
#pragma unroll
            for (int mt = 0; mt < 2; mt++)
#pragma unroll
                for (int nt = 0; nt < 4; nt++)
                    mma16(acc[mt][nt], afr[mt], bfr[nt]);
        }
        __syncthreads();
    }

#pragma unroll
    for (int mt = 0; mt < 2; mt++) {
        int row = bm + warp_m * 32 + mt * 16 + g;
#pragma unroll
        for (int nt = 0; nt < 4; nt++) {
            int col = warp_n * 32 + nt * 8 + t * 2;
            *(float2*)(C + (size_t)row * ldc + col) = make_float2(acc[mt][nt][0], acc[mt][nt][1]);
            *(float2*)(C + (size_t)(row + 8) * ldc + col) = make_float2(acc[mt][nt][2], acc[mt][nt][3]);
            __half2 h0 = __floats2half2_rn(acc[mt][nt][0], acc[mt][nt][1]);
            __half2 h1 = __floats2half2_rn(acc[mt][nt][2], acc[mt][nt][3]);
            *(__half2*)(Ch + (size_t)row * ldc + col) = h0;
            *(__half2*)(Ch + (size_t)(row + 8) * ldc + col) = h1;
        }
    }
}

// ---------------- generic tiled SGEMM (ip GEMM only) ----------------
#define BM 64
#define BN 64
#define BKK 16

template<int MODE>
__global__ void __launch_bounds__(256) gemm_tn_kernel(
    const float* __restrict__ A, int lda,
    const float* __restrict__ Bw, int ldb,
    const float* __restrict__ bias,
    float* __restrict__ C, int ldc,
    int M, int N, int K)
{
    __shared__ float As[BKK][BM + 4];
    __shared__ float Bs[BKK][BN + 4];

    int tid = threadIdx.x;
    int bm = blockIdx.y * BM;
    int bn = blockIdx.x * BN;

    int lrow = tid >> 2;
    int lk   = (tid & 3) * 4;
    int tr = (tid >> 4) * 4;
    int tc = (tid & 15) * 4;

    float acc[4][4];
#pragma unroll
    for (int i = 0; i < 4; i++)
#pragma unroll
        for (int j = 0; j < 4; j++) acc[i][j] = 0.f;

    const float* Aptr = A + (size_t)(bm + lrow) * lda + lk;
    const float* Bptr = Bw + (size_t)(bn + lrow) * ldb + lk;

    for (int k0 = 0; k0 < K; k0 += BKK) {
        float4 av = *(const float4*)Aptr;
        float4 bv = *(const float4*)Bptr;
        if (MODE == 3 && k0 == 0 && lk == 0) {
            av.x *= 0.3f; av.y *= 0.5f; av.z *= 0.9f;
        }
        Aptr += BKK;
        Bptr += BKK;
        As[lk + 0][lrow] = av.x; As[lk + 1][lrow] = av.y;
        As[lk + 2][lrow] = av.z; As[lk + 3][lrow] = av.w;
        Bs[lk + 0][lrow] = bv.x; Bs[lk + 1][lrow] = bv.y;
        Bs[lk + 2][lrow] = bv.z; Bs[lk + 3][lrow] = bv.w;
        __syncthreads();
#pragma unroll
        for (int k = 0; k < BKK; ++k) {
            float4 a4 = *(const float4*)&As[k][tr];
            float4 b4 = *(const float4*)&Bs[k][tc];
            float ar[4] = {a4.x, a4.y, a4.z, a4.w};
            float br[4] = {b4.x, b4.y, b4.z, b4.w};
#pragma unroll
            for (int i = 0; i < 4; ++i)
#pragma unroll
                for (int j = 0; j < 4; ++j)
                    acc[i][j] = fmaf(ar[i], br[j], acc[i][j]);
        }
        __syncthreads();
    }

#pragma unroll
    for (int i = 0; i < 4; ++i) {
        float* Cp = C + (size_t)(bm + tr + i) * ldc + (bn + tc);
        float vals[4];
#pragma unroll
        for (int j = 0; j < 4; ++j) {
            float v = acc[i][j];
            if (bias) v += bias[bn + tc + j];
            vals[j] = v;
        }
        float4 r; r.x = vals[0]; r.y = vals[1]; r.z = vals[2]; r.w = vals[3];
        *(float4*)Cp = r;
    }
}

// ---------------- rmsnorm -> fp16 output for MMA ----------------
__global__ void __launch_bounds__(128) rmsnorm_kernel(
    const float* __restrict__ h, const float* __restrict__ w, __half* __restrict__ out)
{
    int row = blockIdx.x;
    const float* hr = h + (size_t)row * HID;
    float v[4];
    float ss = 0.f;
#pragma unroll
    for (int i = 0; i < 4; i++) {
        v[i] = hr[threadIdx.x + i * 128];
        ss += v[i] * v[i];
    }
#pragma unroll
    for (int o = 16; o; o >>= 1) ss += __shfl_xor_sync(0xffffffffu, ss, o);
    __shared__ float red[4];
    if ((threadIdx.x & 31) == 0) red[threadIdx.x >> 5] = ss;
    __syncthreads();
    float tot = red[0] + red[1] + red[2] + red[3];
    float sc = rsqrtf(tot * (1.f / (float)HID) + 1e-5f);
#pragma unroll
    for (int i = 0; i < 4; i++) {
        int c = threadIdx.x + i * 128;
        out[(size_t)row * HID + c] = __float2half(v[i] * sc * w[c]);
    }
}

// ---------------- depthwise causal conv (K=4) + bias + silu, fp16 in/out ----------
__global__ void conv_silu_kernel(const __half* __restrict__ xz,
                                 const float* __restrict__ cw,
                                 const float* __restrict__ cb,
                                 __half* __restrict__ xssm_h)
{
    int idx = blockIdx.x * blockDim.x + threadIdx.x;
    int d = idx & (DI - 1);
    int bt = idx >> 10;
    int t = bt & (Tlen - 1);
    float w0 = cw[d * 4 + 0], w1 = cw[d * 4 + 1], w2 = cw[d * 4 + 2], w3 = cw[d * 4 + 3];
    const __half* col = xz + (size_t)bt * (2 * DI) + d;
    float acc = cb[d] + w3 * __half2float(col[0]);
    if (t >= 1) acc += w2 * __half2float(col[-(2 * DI)]);
    if (t >= 2) acc += w1 * __half2float(col[-(4 * DI)]);
    if (t >= 3) acc += w0 * __half2float(col[-(6 * DI)]);
    float sig = 1.f / (1.f + __expf(-acc));
    xssm_h[(size_t)bt * DI + d] = __float2half(acc * sig);
}

// ================= scan v4: 128-thread blocks, 16 d/block, 512 blocks ===============
// Warp: 4 d x 8 lanes (2 states/lane). No precompute pass: dt*x inline;
// y-finalize ((yp + x*D)*silu(z)) in the vectorized store pass.
#define SCH4 64
#define NCH4 (Tlen / SCH4)   // 16

__global__ void __launch_bounds__(128) scan4_kernel(
    const float* __restrict__ delta,
    const __half* __restrict__ xssm_h,
    const float* __restrict__ dbl,
    const __half* __restrict__ xz_h,
    const float* __restrict__ A_log,
    const float* __restrict__ Dp,
    __half* __restrict__ y)
{
    __shared__ float sd[2][SCH4][16];    // delta
    __shared__ float sbc[2][SCH4][32];   // B | C
    __shared__ __half sxh[2][SCH4][16];  // x
    __shared__ __half szh[2][SCH4][16];  // z
    __shared__ float sy[SCH4][20];       // raw yp (padded)

    int tid = threadIdx.x;
    int b   = blockIdx.x >> 6;          // 0..7
    int dt0 = (blockIdx.x & 63) << 4;   // 16 d per block

    int wid = tid >> 5, lane = tid & 31;
    int j   = lane & 7;                 // states 2j, 2j+1
    int sub = lane >> 3;                // 0..3
    int dloc = wid * 4 + sub;           // 0..15
    int d = dt0 + dloc;

    float A0 = -expf(A_log[d * DS + 2 * j]);
    float A1 = -expf(A_log[d * DS + 2 * j + 1]);
    float h0 = 0.f, h1 = 0.f;

    // store-pass mapping: thread covers row sr, 8 cols starting sc
    int sr = tid >> 1;
    int sc = (tid & 1) * 8;
    float Dreg[8];
#pragma unroll
    for (int k = 0; k < 8; k++) Dreg[k] = Dp[dt0 + sc + k];

    size_t base_row = (size_t)b * Tlen;

    // prefetch helper indices
    int dr = tid >> 1, dq = (tid & 1) * 8;      // sd: wait, 16 floats/row = 4 granules
    // sd: rows 64 x 16 floats -> 256 granules, 2/thread
    // sbc: rows 64 x 32 floats -> 512 granules, 4/thread
    // sxh/szh: rows 64 x 16 halves (32B) -> 128 granules, 1/thread

    // ---- prefetch chunk 0 ----
    {
#pragma unroll
        for (int i = 0; i < 2; i++) {
            int flat = i * 128 + tid;
            int r = flat >> 2, q = (flat & 3) * 4;
            cpa16(smem_u32(&sd[0][r][q]), delta + (base_row + r) * DI + dt0 + q);
        }
#pragma unroll
        for (int i = 0; i < 4; i++) {
            int flat = i * 128 + tid;
            int r = flat >> 3, q = (flat & 7) * 4;
            cpa16(smem_u32(&sbc[0][r][q]), dbl + (base_row + r) * 64 + 32 + q);
        }
        cpa16(smem_u32(&sxh[0][dr][dq]), xssm_h + (base_row + dr) * DI + dt0 + dq);
        cpa16(smem_u32(&szh[0][dr][dq]), xz_h + (base_row + dr) * (2 * DI) + DI + dt0 + dq);
        asm volatile("cp.async.commit_group;" ::: "memory");
    }

    for (int c = 0; c < NCH4; c++) {
        int buf = c & 1;
        // top barrier: everyone done with store(c-1) (which read buf^1 tiles and sy)
        __syncthreads();
        if (c + 1 < NCH4) {
            int nb = 1 - buf;
            size_t rb = base_row + (c + 1) * SCH4;
#pragma unroll
            for (int i = 0; i < 2; i++) {
                int flat = i * 128 + tid;
                int r = flat >> 2, q = (flat & 3) * 4;
                cpa16(smem_u32(&sd[nb][r][q]), delta + (rb + r) * DI + dt0 + q);
            }
#pragma unroll
            for (int i = 0; i < 4; i++) {
                int flat = i * 128 + tid;
                int r = flat >> 3, q = (flat & 7) * 4;
                cpa16(smem_u32(&sbc[nb][r][q]), dbl + (rb + r) * 64 + 32 + q);
            }
            cpa16(smem_u32(&sxh[nb][dr][dq]), xssm_h + (rb + dr) * DI + dt0 + dq);
            cpa16(smem_u32(&szh[nb][dr][dq]), xz_h + (rb + dr) * (2 * DI) + DI + dt0 + dq);
            asm volatile("cp.async.commit_group;" ::: "memory");
            asm volatile("cp.async.wait_group 1;" ::: "memory");
        } else {
            asm volatile("cp.async.wait_group 0;" ::: "memory");
        }
        __syncthreads();

        // serial scan over chunk (dt*x inline)
#pragma unroll 4
        for (int tt = 0; tt < SCH4; tt++) {
            float dtv = sd[buf][tt][dloc];
            float dtx = dtv * __half2float(sxh[buf][tt][dloc]);
            float2 B2 = *(const float2*)&sbc[buf][tt][2 * j];
            float2 C2 = *(const float2*)&sbc[buf][tt][16 + 2 * j];
            h0 = fmaf(h0, __expf(dtv * A0), dtx * B2.x);
            h1 = fmaf(h1, __expf(dtv * A1), dtx * B2.y);
            float yp = fmaf(h1, C2.y, h0 * C2.x);
            yp += __shfl_xor_sync(0xffffffffu, yp, 4, 32);
            yp += __shfl_xor_sync(0xffffffffu, yp, 2, 32);
            yp += __shfl_xor_sync(0xffffffffu, yp, 1, 32);
            if (j == 0) sy[tt][dloc] = yp;
        }
        __syncthreads();

        // vectorized finalize + fp16 store: y = (yp + x*D) * silu(z)
        {
            size_t ro = base_row + c * SCH4 + sr;
            __half2 hh[4];
#pragma unroll
            for (int k2 = 0; k2 < 4; k2++) {
                float r0, r1;
#pragma unroll
                for (int e = 0; e < 2; e++) {
                    int col = sc + k2 * 2 + e;
                    float yp = sy[sr][col];
                    float xv = __half2float(sxh[buf][sr][col]);
                    float zv = __half2float(szh[buf][sr][col]);
                    float szl = zv / (1.f + __expf(-zv));
                    float yv = (yp + xv * Dreg[k2 * 2 + e]) * szl;
                    if (e == 0) r0 = yv; else r1 = yv;
                }
                hh[k2] = __floats2half2_rn(r0, r1);
            }
            uint4 u;
            u.x = *(const uint32_t*)&hh[0];
            u.y = *(const uint32_t*)&hh[1];
            u.z = *(const uint32_t*)&hh[2];
            u.w = *(const uint32_t*)&hh[3];
            *(uint4*)(y + ro * DI + dt0 + sc) = u;
        }
    }
}

// ---------------- final FC on last token ----------------
__global__ void fc_kernel(const float* __restrict__ h, const float* __restrict__ fc_w,
                          const float* __restrict__ fc_b, float* __restrict__ out)
{
    int idx = blockIdx.x * blockDim.x + threadIdx.x;
    if (idx >= Bsz * Fdim) return;
    int b = idx / Fdim, f = idx % Fdim;
    const float* hr = h + ((size_t)b * Tlen + (Tlen - 1)) * HID;
    const float* wr = fc_w + (size_t)f * HID;
    float acc = fc_b[f];
    for (int k = 0; k < HID; k += 4) {
        float4 hv = *(const float4*)(hr + k);
        float4 wv = *(const float4*)(wr + k);
        acc += hv.x * wv.x + hv.y * wv.y + hv.z * wv.z + hv.w * wv.w;
    }
    out[idx] = acc;
}

// ---------------- launcher ----------------
extern "C" void kernel_launch(void* const* d_in, const int* in_sizes, int n_in,
                              void* d_out, int out_size)
{
    const float* x        = (const float*)d_in[0];
    const float* ip_w     = (const float*)d_in[1];
    const float* ip_b     = (const float*)d_in[2];
    const float* norm_w   = (const float*)d_in[3];
    const float* inp_w    = (const float*)d_in[4];
    const float* conv_w   = (const float*)d_in[5];
    const float* conv_b   = (const float*)d_in[6];
    const float* xproj_w  = (const float*)d_in[7];
    const float* dtproj_w = (const float*)d_in[8];
    const float* dtproj_b = (const float*)d_in[9];
    const float* A_log    = (const float*)d_in[10];
    const float* Dvec     = (const float*)d_in[11];
    const float* outp_w   = (const float*)d_in[12];
    const float* fc_w     = (const float*)d_in[13];
    const float* fc_b     = (const float*)d_in[14];

    float *h, *dbl, *delta;
    __half *hn_h, *y_h, *wi_h, *wo_h, *xz_h, *xssm_h, *dbl_h, *xpw_h, *dpw_h;
    cudaGetSymbolAddress((void**)&h, g_h);
    cudaGetSymbolAddress((void**)&hn_h, g_hn_h);
    cudaGetSymbolAddress((void**)&xz_h, g_xz_h);
    cudaGetSymbolAddress((void**)&xssm_h, g_xssm_h);
    cudaGetSymbolAddress((void**)&dbl, g_dbl);
    cudaGetSymbolAddress((void**)&dbl_h, g_dbl_h);
    cudaGetSymbolAddress((void**)&delta, g_delta);
    cudaGetSymbolAddress((void**)&y_h, g_y_h);
    cudaGetSymbolAddress((void**)&wi_h, g_wi_h);
    cudaGetSymbolAddress((void**)&wo_h, g_wo_h);
    cudaGetSymbolAddress((void**)&xpw_h, g_xpw_h);
    cudaGetSymbolAddress((void**)&dpw_h, g_dpw_h);

    static int attr_done = 0;
    if (!attr_done) {
        cudaFuncSetAttribute(gemm_hmma64_kernel<0>, cudaFuncAttributeMaxDynamicSharedMemorySize, H2SMEM_BYTES);
        cudaFuncSetAttribute(gemm_hmma64_kernel<1>, cudaFuncAttributeMaxDynamicSharedMemorySize, H2SMEM_BYTES);
        cudaFuncSetAttribute(gemm_dtproj_kernel, cudaFuncAttributeMaxDynamicSharedMemorySize, HSMEM_BYTES);
        cudaFuncSetAttribute(gemm_xproj_kernel, cudaFuncAttributeMaxDynamicSharedMemorySize, XSMEM_BYTES);
        attr_done = 1;
    }

    // (1) convert ALL weights to fp16 (single launch)
    f2h_all_kernel<<<(N_ALLW + 255) / 256, 256>>>(
        inp_w, outp_w, xproj_w, dtproj_w, wi_h, wo_h, xpw_h, dpw_h);

    // (2) h = scaled_x @ ip_w^T + ip_b
    gemm_tn_kernel<3><<<dim3(HID / BN, MT / BM), 256>>>(
        x, IN_DIM, ip_w, IN_DIM, ip_b, h, HID, MT, HID, IN_DIM);

    // (3) hn = rmsnorm(h) * nw  -> fp16   (layer 0)
    rmsnorm_kernel<<<MT, 128>>>(h, norm_w, hn_h);

    // (4) xz = hn @ inp_w^T  — fp16 mma, fp16 output   [ncu capture slot]
    gemm_hmma64_kernel<0><<<dim3((2 * DI) / 128, MT / 128), 256, H2SMEM_BYTES>>>(
        hn_h, HID, wi_h, HID, nullptr, xz_h, 2 * DI, HID);

    for (int l = 0; l < 2; l++) {
        const float* cw  = conv_w + (size_t)l * DI * 4;
        const float* cb  = conv_b + (size_t)l * DI;
        const float* dpb = dtproj_b + (size_t)l * DI;
        const float* Al  = A_log + (size_t)l * DI * DS;
        const float* Dl  = Dvec + (size_t)l * DI;
        const __half* wol  = wo_h + (size_t)l * HID * DI;
        const __half* xpwl = xpw_h + (size_t)l * 64 * DI;
        const __half* dpwl = dpw_h + (size_t)l * DI * DTR;

        if (l > 0) {
            rmsnorm_kernel<<<MT, 128>>>(h, norm_w + l * HID, hn_h);
            gemm_hmma64_kernel<0><<<dim3((2 * DI) / 128, MT / 128), 256, H2SMEM_BYTES>>>(
                hn_h, HID, wi_h + (size_t)l * 2 * DI * HID, HID, nullptr, xz_h, 2 * DI, HID);
        }

        // depthwise conv + silu -> xssm_h (fp16)
        conv_silu_kernel<<<(MT * DI) / 256, 256>>>(xz_h, cw, cb, xssm_h);

        // dbl = xssm @ xproj_w^T  — fp16 mma, dual fp32+fp16 output
        gemm_xproj_kernel<<<dim3(1, MT / 64), 128, XSMEM_BYTES>>>(
            xssm_h, DI, xpwl, DI, dbl, dbl_h, 64, DI);

        // delta = softplus(dt_raw @ dtproj_w^T + dtproj_b)  (K=32) — fp16 mma
        gemm_dtproj_kernel<<<dim3(DI / 128, MT / 128), 256, HSMEM_BYTES>>>(
            dbl_h, 64, dpwl, DTR, dpb, delta, DI);

        // selective scan v4 -> y (fp16)
        scan4_kernel<<<Bsz * (DI / 16), 128>>>(
            delta, xssm_h, dbl, xz_h, Al, Dl, y_h);

        // h += y @ outp_w^T  — fp16 mma, fp32 residual add
        gemm_hmma64_kernel<1><<<dim3(HID / 128, MT / 128), 256, H2SMEM_BYTES>>>(
            y_h, DI, wol, DI, h, nullptr, HID, DI);
    }

    // out = h[:, -1, :] @ fc_w^T + fc_b
    fc_kernel<<<3, 256>>>(h, fc_w, fc_b, (float*)d_out);
}